// round 1
// baseline (speedup 1.0000x reference)
#include <cuda_runtime.h>
#include <cstdint>
#include <cstddef>

#define SEQ    2048
#define BATCH  2
#define NH     16
#define DM     1024
#define HD     64
#define HIDDEN 2730
#define ROWS   (BATCH*SEQ)   // 4096

// ---------------- scratch (allocation-free: device globals) ----------------
__device__ float g_xn [ROWS*DM];
__device__ float g_q  [ROWS*DM];
__device__ float g_k  [ROWS*DM];
__device__ float g_v  [ROWS*DM];
__device__ float g_g  [ROWS*DM];
__device__ float g_at [ROWS*DM];
__device__ float g_x1 [ROWS*DM];
__device__ float g_xn2[ROWS*DM];
__device__ float g_ab [(size_t)ROWS*2*HIDDEN];
__device__ float g_h  [(size_t)ROWS*HIDDEN];

// ---------------- LayerNorm: one block per row of 1024 ----------------
__global__ void ln_kernel(const float* __restrict__ x, const float* __restrict__ w,
                          const float* __restrict__ b, float* __restrict__ o)
{
    __shared__ float red[2][8];
    int row = blockIdx.x, tid = threadIdx.x;
    const float* xr = x + (size_t)row * DM;
    float v[4], s = 0.f, q = 0.f;
#pragma unroll
    for (int i = 0; i < 4; i++) { v[i] = xr[tid + 256*i]; s += v[i]; q += v[i]*v[i]; }
#pragma unroll
    for (int off = 16; off; off >>= 1) {
        s += __shfl_xor_sync(~0u, s, off);
        q += __shfl_xor_sync(~0u, q, off);
    }
    if ((tid & 31) == 0) { red[0][tid>>5] = s; red[1][tid>>5] = q; }
    __syncthreads();
    if (tid < 32) {
        s = (tid < 8) ? red[0][tid] : 0.f;
        q = (tid < 8) ? red[1][tid] : 0.f;
#pragma unroll
        for (int off = 4; off; off >>= 1) {
            s += __shfl_xor_sync(~0u, s, off);
            q += __shfl_xor_sync(~0u, q, off);
        }
        if (tid == 0) { red[0][0] = s; red[1][0] = q; }
    }
    __syncthreads();
    s = red[0][0]; q = red[1][0];
    float mu = s * (1.f/DM);
    float rs = rsqrtf(q * (1.f/DM) - mu*mu + 1e-5f);
    float* orow = o + (size_t)row * DM;
#pragma unroll
    for (int i = 0; i < 4; i++) {
        int c = tid + 256*i;
        orow[c] = (v[i] - mu) * rs * w[c] + b[c];
    }
}

// ---------------- generic tiled SGEMM: C = A@B (+bias) (+add) ----------------
// BM=BN=64, BK=16, 256 threads, 4x4 per thread, strided thread mapping
__global__ void gemm_kernel(const float* __restrict__ A, const float* __restrict__ B,
                            float* __restrict__ C, int M, int N, int K,
                            const float* __restrict__ bias, const float* __restrict__ add)
{
    __shared__ float As[16][65];
    __shared__ float Bs[16][64];
    int tid = threadIdx.x;
    int tx = tid & 15, ty = tid >> 4;
    int m0 = blockIdx.y * 64, n0 = blockIdx.x * 64;
    float acc[4][4] = {};
    for (int k0 = 0; k0 < K; k0 += 16) {
#pragma unroll
        for (int l = tid; l < 64*16; l += 256) {
            int r = l >> 4, kk = l & 15;
            int gm = m0 + r, gk = k0 + kk;
            As[kk][r] = (gm < M && gk < K) ? A[(size_t)gm*K + gk] : 0.f;
        }
#pragma unroll
        for (int l = tid; l < 16*64; l += 256) {
            int kk = l >> 6, c = l & 63;
            int gk = k0 + kk, gn = n0 + c;
            Bs[kk][c] = (gk < K && gn < N) ? B[(size_t)gk*N + gn] : 0.f;
        }
        __syncthreads();
#pragma unroll
        for (int kk = 0; kk < 16; kk++) {
            float a[4], b[4];
#pragma unroll
            for (int i = 0; i < 4; i++) a[i] = As[kk][ty + 16*i];
#pragma unroll
            for (int j = 0; j < 4; j++) b[j] = Bs[kk][tx + 16*j];
#pragma unroll
            for (int i = 0; i < 4; i++)
#pragma unroll
                for (int j = 0; j < 4; j++) acc[i][j] += a[i] * b[j];
        }
        __syncthreads();
    }
#pragma unroll
    for (int i = 0; i < 4; i++) {
        int gm = m0 + ty + 16*i;
        if (gm >= M) continue;
#pragma unroll
        for (int j = 0; j < 4; j++) {
            int gn = n0 + tx + 16*j;
            if (gn >= N) continue;
            float v = acc[i][j];
            if (bias) v += bias[gn];
            if (add)  v += add[(size_t)gm*N + gn];
            C[(size_t)gm*N + gn] = v;
        }
    }
}

// ---------------- fused retention attention ----------------
// one block = 64 query rows of one (batch, head); loops over causal K/V tiles.
// decay gamma^(s-t) computed as separable exp2(s*lg) * exp2(-t*lg) (bounded, <2^94)
__global__ void attn_kernel(const float* __restrict__ qg, const float* __restrict__ kg,
                            const float* __restrict__ vg, float* __restrict__ og)
{
    extern __shared__ float sm[];
    float (*Qs)[HD+1] = (float(*)[HD+1])sm;                 // 64 x 65
    float (*KS)[HD+1] = (float(*)[HD+1])(sm + 64*(HD+1));   // 64 x 65 (K tile, then S tile)
    float (*Vs)[HD]   = (float(*)[HD])  (sm + 2*64*(HD+1)); // 64 x 64
    int tid = threadIdx.x;
    int tx = tid & 15, ty = tid >> 4;
    int bh = blockIdx.y;
    int b = bh >> 4, h = bh & 15;
    int s0 = blockIdx.x * 64;
    float lg = log2f(1.f - exp2f(-5.f - (float)h));
    float rowf[4], acc[4][4] = {};
#pragma unroll
    for (int i = 0; i < 4; i++) rowf[i] = exp2f((float)(s0 + ty + 16*i) * lg);

    for (int l = tid; l < 64*64; l += 256) {
        int r = l >> 6, d = l & 63;
        Qs[r][d] = qg[(((size_t)(b*SEQ + s0 + r))*NH + h)*HD + d] * 0.125f; // 1/sqrt(64)
    }

    for (int t0 = 0; t0 <= s0; t0 += 64) {
        __syncthreads();   // protect KS/Vs reuse (also covers initial Q load)
        for (int l = tid; l < 64*64; l += 256) {
            int r = l >> 6, d = l & 63;
            size_t gidx = (((size_t)(b*SEQ + t0 + r))*NH + h)*HD + d;
            KS[r][d] = kg[gidx];
            Vs[r][d] = vg[gidx];
        }
        __syncthreads();
        // S = Q @ K^T  (16 fma / 8 lds, conflict-free via strided mapping + pad)
        float s[4][4] = {};
        for (int d = 0; d < 64; d++) {
            float a[4], kk[4];
#pragma unroll
            for (int i = 0; i < 4; i++) a[i] = Qs[ty + 16*i][d];
#pragma unroll
            for (int j = 0; j < 4; j++) kk[j] = KS[tx + 16*j][d];
#pragma unroll
            for (int i = 0; i < 4; i++)
#pragma unroll
                for (int j = 0; j < 4; j++) s[i][j] += a[i] * kk[j];
        }
        __syncthreads();   // done reading K; overwrite with decayed S
#pragma unroll
        for (int j = 0; j < 4; j++) {
            int gj = t0 + tx + 16*j;
            float colf = exp2f(-(float)gj * lg);
#pragma unroll
            for (int i = 0; i < 4; i++) {
                int gi = s0 + ty + 16*i;
                float w = (gi >= gj) ? rowf[i] * colf : 0.f;
                KS[ty + 16*i][tx + 16*j] = s[i][j] * w;
            }
        }
        __syncthreads();
        // O += S @ V
        for (int j = 0; j < 64; j++) {
            float sv[4], vv[4];
#pragma unroll
            for (int i = 0; i < 4; i++) sv[i] = KS[ty + 16*i][j];
#pragma unroll
            for (int d4 = 0; d4 < 4; d4++) vv[d4] = Vs[j][tx + 16*d4];
#pragma unroll
            for (int i = 0; i < 4; i++)
#pragma unroll
                for (int d4 = 0; d4 < 4; d4++) acc[i][d4] += sv[i] * vv[d4];
        }
    }
#pragma unroll
    for (int i = 0; i < 4; i++)
#pragma unroll
        for (int d4 = 0; d4 < 4; d4++)
            og[(((size_t)(b*SEQ + s0 + ty + 16*i))*NH + h)*HD + tx + 16*d4] = acc[i][d4];
}

// ---------------- per-head groupnorm (eps 1e-6, no affine) * silu(gate) ------
// one warp per 64-element group; gate index == group base (h*64+d within row)
__global__ void gn_gate_kernel(float* __restrict__ at, const float* __restrict__ gate)
{
    int warp = threadIdx.x >> 5, lane = threadIdx.x & 31;
    int g = blockIdx.x * 8 + warp;     // ROWS*NH groups
    size_t base = (size_t)g * 64;
    float x0 = at[base + lane], x1 = at[base + 32 + lane];
    float s = x0 + x1, q = x0*x0 + x1*x1;
#pragma unroll
    for (int off = 16; off; off >>= 1) {
        s += __shfl_xor_sync(~0u, s, off);
        q += __shfl_xor_sync(~0u, q, off);
    }
    float mu = s * (1.f/64), var = q * (1.f/64) - mu*mu;
    float rs = rsqrtf(var + 1e-6f);
    float g0 = gate[base + lane], g1 = gate[base + 32 + lane];
    g0 = g0 / (1.f + __expf(-g0));
    g1 = g1 / (1.f + __expf(-g1));
    at[base + lane]      = (x0 - mu) * rs * g0;
    at[base + 32 + lane] = (x1 - mu) * rs * g1;
}

// ---------------- swiglu: h = a * silu(b) ----------------
__global__ void swiglu_kernel(const float* __restrict__ ab, float* __restrict__ hb)
{
    size_t i = (size_t)blockIdx.x * 256 + threadIdx.x;   // ROWS*HIDDEN elems
    int row = (int)(i / HIDDEN), col = (int)(i % HIDDEN);
    float a = ab[(size_t)row * (2*HIDDEN) + col];
    float b = ab[(size_t)row * (2*HIDDEN) + HIDDEN + col];
    hb[i] = a * b / (1.f + __expf(-b));
}

// ---------------- launch ----------------
extern "C" void kernel_launch(void* const* d_in, const int* in_sizes, int n_in,
                              void* d_out, int out_size)
{
    const float* x     = (const float*)d_in[0];
    const float* ln1w  = (const float*)d_in[1];
    const float* ln1b  = (const float*)d_in[2];
    const float* wq    = (const float*)d_in[3];
    const float* wk    = (const float*)d_in[4];
    const float* wv    = (const float*)d_in[5];
    const float* wg    = (const float*)d_in[6];
    const float* wo    = (const float*)d_in[7];
    const float* ln2w  = (const float*)d_in[8];
    const float* ln2b  = (const float*)d_in[9];
    const float* w_in  = (const float*)d_in[10];
    const float* b_in  = (const float*)d_in[11];
    const float* w_out = (const float*)d_in[12];
    const float* b_out = (const float*)d_in[13];
    float* out = (float*)d_out;

    float *xn, *qb, *kb, *vb, *gb, *at, *x1, *xn2, *ab, *hb;
    cudaGetSymbolAddress((void**)&xn,  g_xn);
    cudaGetSymbolAddress((void**)&qb,  g_q);
    cudaGetSymbolAddress((void**)&kb,  g_k);
    cudaGetSymbolAddress((void**)&vb,  g_v);
    cudaGetSymbolAddress((void**)&gb,  g_g);
    cudaGetSymbolAddress((void**)&at,  g_at);
    cudaGetSymbolAddress((void**)&x1,  g_x1);
    cudaGetSymbolAddress((void**)&xn2, g_xn2);
    cudaGetSymbolAddress((void**)&ab,  g_ab);
    cudaGetSymbolAddress((void**)&hb,  g_h);

    const int ATTN_SMEM = (2*64*(HD+1) + 64*HD) * (int)sizeof(float);   // 49664
    cudaFuncSetAttribute(attn_kernel, cudaFuncAttributeMaxDynamicSharedMemorySize, ATTN_SMEM);

    // 1. LN1
    ln_kernel<<<ROWS, 256>>>(x, ln1w, ln1b, xn);
    // 2. Q/K/V/G projections
    dim3 gSq(DM/64, ROWS/64);
    gemm_kernel<<<gSq, 256>>>(xn, wq, qb, ROWS, DM, DM, nullptr, nullptr);
    gemm_kernel<<<gSq, 256>>>(xn, wk, kb, ROWS, DM, DM, nullptr, nullptr);
    gemm_kernel<<<gSq, 256>>>(xn, wv, vb, ROWS, DM, DM, nullptr, nullptr);
    gemm_kernel<<<gSq, 256>>>(xn, wg, gb, ROWS, DM, DM, nullptr, nullptr);
    // 3. retention attention
    attn_kernel<<<dim3(SEQ/64, BATCH*NH), 256, ATTN_SMEM>>>(qb, kb, vb, at);
    // 4. groupnorm + silu gate (in place on at)
    gn_gate_kernel<<<ROWS*NH/8, 256>>>(at, gb);
    // 5. output projection + residual:  x1 = x + at @ wo
    gemm_kernel<<<gSq, 256>>>(at, wo, x1, ROWS, DM, DM, nullptr, x);
    // 6. LN2
    ln_kernel<<<ROWS, 256>>>(x1, ln2w, ln2b, xn2);
    // 7. FFN in:  ab = xn2 @ w_in + b_in   (N = 5460)
    gemm_kernel<<<dim3((2*HIDDEN + 63)/64, ROWS/64), 256>>>(xn2, w_in, ab, ROWS, 2*HIDDEN, DM, b_in, nullptr);
    // 8. swiglu
    swiglu_kernel<<<(ROWS*HIDDEN)/256, 256>>>(ab, hb);
    // 9. FFN out + bias + residual:  out = x1 + hb @ w_out + b_out  (K = 2730)
    gemm_kernel<<<gSq, 256>>>(hb, w_out, out, ROWS, DM, HIDDEN, b_out, x1);
}

// round 3
// speedup vs baseline: 3.4943x; 3.4943x over previous
#include <cuda_runtime.h>
#include <cuda_fp16.h>
#include <cstdint>
#include <cstddef>

#define SEQ    2048
#define BATCH  2
#define NH     16
#define DM     1024
#define HD     64
#define HID    2730
#define ROWS   (BATCH*SEQ)   // 4096
#define QKVG_N 4096

// ---------------- scratch (allocation-free device globals) ----------------
__device__ float g_xn  [ROWS*DM];
__device__ float g_qkvg[(size_t)ROWS*QKVG_N];
__device__ float g_at  [ROWS*DM];
__device__ float g_x1  [ROWS*DM];
__device__ float g_xn2 [ROWS*DM];
__device__ float g_ab  [(size_t)ROWS*2*HID];
__device__ float g_hb  [(size_t)ROWS*HID];

// ---------------- helpers ----------------
__device__ __forceinline__ void mma16(float* c, const uint32_t* a, const uint32_t* b) {
    asm volatile("mma.sync.aligned.m16n8k16.row.col.f32.f16.f16.f32 "
                 "{%0,%1,%2,%3},{%4,%5,%6,%7},{%8,%9},{%0,%1,%2,%3};\n"
                 : "+f"(c[0]), "+f"(c[1]), "+f"(c[2]), "+f"(c[3])
                 : "r"(a[0]), "r"(a[1]), "r"(a[2]), "r"(a[3]), "r"(b[0]), "r"(b[1]));
}
// split (x,y) into hi/lo half2 pairs
__device__ __forceinline__ void cvt2(float x, float y, __half2& hi, __half2& lo) {
    __half hx = __float2half_rn(x), hy = __float2half_rn(y);
    __half lx = __float2half_rn(x - __half2float(hx));
    __half ly = __float2half_rn(y - __half2float(hy));
    hi = __halves2half2(hx, hy);
    lo = __halves2half2(lx, ly);
}

// ---------------- LayerNorm ----------------
__global__ void ln_kernel(const float* __restrict__ x, const float* __restrict__ w,
                          const float* __restrict__ b, float* __restrict__ o)
{
    __shared__ float red[2][8];
    int row = blockIdx.x, tid = threadIdx.x;
    const float* xr = x + (size_t)row * DM;
    float v[4], s = 0.f, q = 0.f;
#pragma unroll
    for (int i = 0; i < 4; i++) { v[i] = xr[tid + 256*i]; s += v[i]; q += v[i]*v[i]; }
#pragma unroll
    for (int off = 16; off; off >>= 1) {
        s += __shfl_xor_sync(~0u, s, off);
        q += __shfl_xor_sync(~0u, q, off);
    }
    if ((tid & 31) == 0) { red[0][tid>>5] = s; red[1][tid>>5] = q; }
    __syncthreads();
    if (tid < 32) {
        s = (tid < 8) ? red[0][tid] : 0.f;
        q = (tid < 8) ? red[1][tid] : 0.f;
#pragma unroll
        for (int off = 4; off; off >>= 1) {
            s += __shfl_xor_sync(~0u, s, off);
            q += __shfl_xor_sync(~0u, q, off);
        }
        if (tid == 0) { red[0][0] = s; red[1][0] = q; }
    }
    __syncthreads();
    s = red[0][0]; q = red[1][0];
    float mu = s * (1.f/DM);
    float rs = rsqrtf(q * (1.f/DM) - mu*mu + 1e-5f);
    float* orow = o + (size_t)row * DM;
#pragma unroll
    for (int i = 0; i < 4; i++) {
        int c = tid + 256*i;
        orow[c] = (v[i] - mu) * rs * w[c] + b[c];
    }
}

// ---------------- fp16x2-compensated tensor-core GEMM ----------------
// C[M,N](ld=ldC) = A[M,K] @ B[K,N] (+bias) (+add[ldC]); 3-mma hi/lo compensation.
// BM=BN=128, BK=32, 256 thr (8 warps 2x4), warp tile 64x32.
#define BM 128
#define BN 128
#define BKK 32
#define HST 40                   // halves per smem row (conflict-free: 20 words)
#define THALF (128*HST)          // 5120 halves per matrix

__global__ __launch_bounds__(256)
void gemm3(const float* __restrict__ A, const float* __restrict__ B, float* __restrict__ C,
           int M, int N, int K, int ldC,
           const float* __restrict__ bias, const float* __restrict__ add)
{
    __shared__ __align__(16) __half sAhi[THALF], sAlo[THALF], sBhi[THALF], sBlo[THALF];
    const uint32_t* wAhi = (const uint32_t*)sAhi;
    const uint32_t* wAlo = (const uint32_t*)sAlo;
    const uint32_t* wBhi = (const uint32_t*)sBhi;
    const uint32_t* wBlo = (const uint32_t*)sBlo;

    int tid = threadIdx.x, lane = tid & 31, wid = tid >> 5;
    int wm = wid >> 2, wn = wid & 3;
    int m0 = blockIdx.y * BM, n0 = blockIdx.x * BN;
    int KT = (K + BKK - 1) / BKK;

    float2 rA[8];
    float  rB[16];
    float  acc[4][4][4] = {};

    // stage tile kt into registers
#define STAGE(kt) do {                                                          \
        int k0_ = (kt) * BKK;                                                   \
        _Pragma("unroll")                                                       \
        for (int i_ = 0; i_ < 8; i_++) {                                        \
            int p_ = tid + 256*i_;                                              \
            int m_ = p_ >> 4, kh_ = (p_ & 15) * 2;                              \
            int gk_ = k0_ + kh_;                                                \
            rA[i_] = (gk_ < K) ? *(const float2*)(A + (size_t)(m0 + m_)*K + gk_)\
                               : make_float2(0.f, 0.f);                         \
        }                                                                       \
        _Pragma("unroll")                                                       \
        for (int i_ = 0; i_ < 16; i_++) {                                       \
            int e_ = tid + 256*i_;                                              \
            int k_ = e_ >> 7, n_ = e_ & 127;                                    \
            int gk_ = k0_ + k_, gn_ = n0 + n_;                                  \
            rB[i_] = (gk_ < K && gn_ < N) ? B[(size_t)gk_*N + gn_] : 0.f;       \
        }                                                                       \
    } while (0)

    STAGE(0);

    for (int kt = 0; kt < KT; kt++) {
        __syncthreads();
        // commit staged registers to smem (convert to hi/lo halves)
#pragma unroll
        for (int i = 0; i < 8; i++) {
            int p = tid + 256*i;
            int m = p >> 4, kh = (p & 15) * 2;
            __half2 hi, lo;
            cvt2(rA[i].x, rA[i].y, hi, lo);
            *(__half2*)&sAhi[m*HST + kh] = hi;
            *(__half2*)&sAlo[m*HST + kh] = lo;
        }
#pragma unroll
        for (int i = 0; i < 16; i++) {
            int e = tid + 256*i;
            int k = e >> 7, n = e & 127;
            __half h = __float2half_rn(rB[i]);
            sBhi[n*HST + k] = h;
            sBlo[n*HST + k] = __float2half_rn(rB[i] - __half2float(h));
        }
        __syncthreads();
        if (kt + 1 < KT) STAGE(kt + 1);

#pragma unroll
        for (int ks = 0; ks < 2; ks++) {
            uint32_t ahi[4][4], alo[4][4], bhi[4][2], blo[4][2];
#pragma unroll
            for (int mi = 0; mi < 4; mi++) {
                int m = wm*64 + mi*16 + (lane >> 2);
                int base = m*20 + ks*8 + (lane & 3);
                ahi[mi][0] = wAhi[base];       ahi[mi][1] = wAhi[base + 160];
                ahi[mi][2] = wAhi[base + 4];   ahi[mi][3] = wAhi[base + 164];
                alo[mi][0] = wAlo[base];       alo[mi][1] = wAlo[base + 160];
                alo[mi][2] = wAlo[base + 4];   alo[mi][3] = wAlo[base + 164];
            }
#pragma unroll
            for (int ni = 0; ni < 4; ni++) {
                int n = wn*32 + ni*8 + (lane >> 2);
                int nb = n*20 + ks*8 + (lane & 3);
                bhi[ni][0] = wBhi[nb]; bhi[ni][1] = wBhi[nb + 4];
                blo[ni][0] = wBlo[nb]; blo[ni][1] = wBlo[nb + 4];
            }
#pragma unroll
            for (int mi = 0; mi < 4; mi++)
#pragma unroll
                for (int ni = 0; ni < 4; ni++) {
                    mma16(acc[mi][ni], ahi[mi], bhi[ni]);
                    mma16(acc[mi][ni], ahi[mi], blo[ni]);
                    mma16(acc[mi][ni], alo[mi], bhi[ni]);
                }
        }
    }
#undef STAGE

#pragma unroll
    for (int mi = 0; mi < 4; mi++) {
        int r = m0 + wm*64 + mi*16 + (lane >> 2);
#pragma unroll
        for (int ni = 0; ni < 4; ni++) {
            int cn = n0 + wn*32 + ni*8 + 2*(lane & 3);
            if (cn >= N) continue;
            float b0v = bias ? bias[cn]   : 0.f;
            float b1v = bias ? bias[cn+1] : 0.f;
            float v0 = acc[mi][ni][0] + b0v;
            float v1 = acc[mi][ni][1] + b1v;
            float v2 = acc[mi][ni][2] + b0v;
            float v3 = acc[mi][ni][3] + b1v;
            if (add) {
                v0 += add[(size_t)r*ldC + cn];     v1 += add[(size_t)r*ldC + cn + 1];
                v2 += add[(size_t)(r+8)*ldC + cn]; v3 += add[(size_t)(r+8)*ldC + cn + 1];
            }
            *(float2*)(C + (size_t)r*ldC + cn)     = make_float2(v0, v1);
            *(float2*)(C + (size_t)(r+8)*ldC + cn) = make_float2(v2, v3);
        }
    }
}

// ---------------- fused retention attention (fp16x2 tensor cores) ----------------
// block = 64 q-rows of one (b,h). 8 warps: wm=wid>>1 (m16), wn=wid&1 (n32).
// half buffers stride 72 (36 words, conflict-free). V stored transposed [d][t].
#define AHST 72
#define AWST 36
#define QHIW 0
#define QLOW 2304
#define KHIW 4608
#define KLOW 6912
#define VHIW 9216
#define VLOW 11520
#define SHIW 13824
#define SLOW 16128
#define RFW  18432      // float offsets (word == float)
#define CFW  18496
#define ATTN_SMEM ((CFW + 64)*4)   // 74240 B

__global__ __launch_bounds__(256)
void attn3(const float* __restrict__ qkvg, float* __restrict__ og)
{
    extern __shared__ uint32_t smw[];
    __half* smh = (__half*)smw;
    float*  smf = (float*)smw;
    int tid = threadIdx.x, lane = tid & 31, wid = tid >> 5;
    int wm = wid >> 1, wn = wid & 1;
    int bh = blockIdx.y, b = bh >> 4, h = bh & 15;
    int s0 = blockIdx.x * 64;
    float lg = log2f(1.f - exp2f(-5.f - (float)h));
    const float* q = qkvg + h*HD;
    const float* k = qkvg + DM + h*HD;
    const float* v = qkvg + 2*DM + h*HD;

    // Q tile (scaled 1/8), hi/lo
#pragma unroll
    for (int i = 0; i < 8; i++) {
        int p = tid + 256*i;
        int r = p >> 5, c2 = (p & 31) * 2;
        float2 t = *(const float2*)(q + (size_t)(b*SEQ + s0 + r)*QKVG_N + c2);
        __half2 hi, lo;
        cvt2(t.x*0.125f, t.y*0.125f, hi, lo);
        *(__half2*)&smh[QHIW*2 + r*AHST + c2] = hi;
        *(__half2*)&smh[QLOW*2 + r*AHST + c2] = lo;
    }
    if (tid < 64) smf[RFW + tid] = exp2f((float)(s0 + tid) * lg);

    float oacc[4][4] = {};
    for (int t0 = 0; t0 <= s0; t0 += 64) {
        __syncthreads();   // prev O-mma done with S/Vt; covers Q/RF on first iter too
        // K tile [t][d], V tile transposed [d][t]
#pragma unroll
        for (int i = 0; i < 8; i++) {
            int p = tid + 256*i;
            int r = p >> 5, c2 = (p & 31) * 2;
            size_t base = (size_t)(b*SEQ + t0 + r)*QKVG_N + c2;
            float2 tk = *(const float2*)(k + base);
            float2 tv = *(const float2*)(v + base);
            __half2 hi, lo;
            cvt2(tk.x, tk.y, hi, lo);
            *(__half2*)&smh[KHIW*2 + r*AHST + c2] = hi;
            *(__half2*)&smh[KLOW*2 + r*AHST + c2] = lo;
            __half vh0 = __float2half_rn(tv.x);
            __half vh1 = __float2half_rn(tv.y);
            smh[VHIW*2 + c2*AHST + r]       = vh0;
            smh[VHIW*2 + (c2+1)*AHST + r]   = vh1;
            smh[VLOW*2 + c2*AHST + r]       = __float2half_rn(tv.x - __half2float(vh0));
            smh[VLOW*2 + (c2+1)*AHST + r]   = __float2half_rn(tv.y - __half2float(vh1));
        }
        if (tid < 64) smf[CFW + tid] = exp2f(-(float)(t0 + tid) * lg);
        __syncthreads();

        // S = Q @ K^T (m64 n64 k64)
        float sacc[4][4] = {};
#pragma unroll
        for (int ks = 0; ks < 4; ks++) {
            uint32_t ahi[4], alo[4], bhi[4][2], blo[4][2];
            int m = wm*16 + (lane >> 2);
            int ab = m*AWST + ks*8 + (lane & 3);
            ahi[0] = smw[QHIW + ab];       ahi[1] = smw[QHIW + ab + 8*AWST];
            ahi[2] = smw[QHIW + ab + 4];   ahi[3] = smw[QHIW + ab + 8*AWST + 4];
            alo[0] = smw[QLOW + ab];       alo[1] = smw[QLOW + ab + 8*AWST];
            alo[2] = smw[QLOW + ab + 4];   alo[3] = smw[QLOW + ab + 8*AWST + 4];
#pragma unroll
            for (int ni = 0; ni < 4; ni++) {
                int n = wn*32 + ni*8 + (lane >> 2);
                int nb = n*AWST + ks*8 + (lane & 3);
                bhi[ni][0] = smw[KHIW + nb]; bhi[ni][1] = smw[KHIW + nb + 4];
                blo[ni][0] = smw[KLOW + nb]; blo[ni][1] = smw[KLOW + nb + 4];
            }
#pragma unroll
            for (int ni = 0; ni < 4; ni++) {
                mma16(sacc[ni], ahi, bhi[ni]);
                mma16(sacc[ni], ahi, blo[ni]);
                mma16(sacc[ni], alo, bhi[ni]);
            }
        }

        // decay * mask, split to hi/lo halves in Ss
        bool diag = (t0 == s0);
        int r0 = wm*16 + (lane >> 2);
        float rf0 = smf[RFW + r0], rf1 = smf[RFW + r0 + 8];
#pragma unroll
        for (int ni = 0; ni < 4; ni++) {
            int c0 = wn*32 + ni*8 + 2*(lane & 3);
            float cf0 = smf[CFW + c0], cf1 = smf[CFW + c0 + 1];
            float w00 = rf0*cf0, w01 = rf0*cf1, w10 = rf1*cf0, w11 = rf1*cf1;
            if (diag) {
                if (r0   < c0  ) w00 = 0.f;
                if (r0   < c0+1) w01 = 0.f;
                if (r0+8 < c0  ) w10 = 0.f;
                if (r0+8 < c0+1) w11 = 0.f;
            }
            float v0 = sacc[ni][0]*w00, v1 = sacc[ni][1]*w01;
            float v2 = sacc[ni][2]*w10, v3 = sacc[ni][3]*w11;
            __half2 hi, lo;
            cvt2(v0, v1, hi, lo);
            *(__half2*)&smh[SHIW*2 + r0*AHST + c0] = hi;
            *(__half2*)&smh[SLOW*2 + r0*AHST + c0] = lo;
            cvt2(v2, v3, hi, lo);
            *(__half2*)&smh[SHIW*2 + (r0+8)*AHST + c0] = hi;
            *(__half2*)&smh[SLOW*2 + (r0+8)*AHST + c0] = lo;
        }
        __syncthreads();

        // O += S @ V (m64 n64 k64), V^T layout [d][t]
#pragma unroll
        for (int ks = 0; ks < 4; ks++) {
            uint32_t ahi[4], alo[4], bhi[4][2], blo[4][2];
            int m = wm*16 + (lane >> 2);
            int ab = m*AWST + ks*8 + (lane & 3);
            ahi[0] = smw[SHIW + ab];       ahi[1] = smw[SHIW + ab + 8*AWST];
            ahi[2] = smw[SHIW + ab + 4];   ahi[3] = smw[SHIW + ab + 8*AWST + 4];
            alo[0] = smw[SLOW + ab];       alo[1] = smw[SLOW + ab + 8*AWST];
            alo[2] = smw[SLOW + ab + 4];   alo[3] = smw[SLOW + ab + 8*AWST + 4];
#pragma unroll
            for (int ni = 0; ni < 4; ni++) {
                int n = wn*32 + ni*8 + (lane >> 2);
                int nb = n*AWST + ks*8 + (lane & 3);
                bhi[ni][0] = smw[VHIW + nb]; bhi[ni][1] = smw[VHIW + nb + 4];
                blo[ni][0] = smw[VLOW + nb]; blo[ni][1] = smw[VLOW + nb + 4];
            }
#pragma unroll
            for (int ni = 0; ni < 4; ni++) {
                mma16(oacc[ni], ahi, bhi[ni]);
                mma16(oacc[ni], ahi, blo[ni]);
                mma16(oacc[ni], alo, bhi[ni]);
            }
        }
    }

    int r0 = wm*16 + (lane >> 2);
#pragma unroll
    for (int ni = 0; ni < 4; ni++) {
        int d0 = wn*32 + ni*8 + 2*(lane & 3);
        size_t i0 = ((size_t)(b*SEQ + s0 + r0)*NH + h)*HD + d0;
        size_t i1 = ((size_t)(b*SEQ + s0 + r0 + 8)*NH + h)*HD + d0;
        *(float2*)(og + i0) = make_float2(oacc[ni][0], oacc[ni][1]);
        *(float2*)(og + i1) = make_float2(oacc[ni][2], oacc[ni][3]);
    }
}

// ---------------- per-head groupnorm * silu(gate) ----------------
__global__ void gn_gate_kernel(float* __restrict__ at, const float* __restrict__ qkvg)
{
    int warp = threadIdx.x >> 5, lane = threadIdx.x & 31;
    int g = blockIdx.x * 8 + warp;          // row*16 + h
    int row = g >> 4, h = g & 15;
    size_t base = (size_t)g * 64;
    const float* gp = qkvg + (size_t)row*QKVG_N + 3*DM + h*64;
    float x0 = at[base + lane], x1 = at[base + 32 + lane];
    float s = x0 + x1, q = x0*x0 + x1*x1;
#pragma unroll
    for (int off = 16; off; off >>= 1) {
        s += __shfl_xor_sync(~0u, s, off);
        q += __shfl_xor_sync(~0u, q, off);
    }
    float mu = s * (1.f/64), var = q * (1.f/64) - mu*mu;
    float rs = rsqrtf(var + 1e-6f);
    float g0 = gp[lane], g1 = gp[32 + lane];
    g0 = g0 / (1.f + __expf(-g0));
    g1 = g1 / (1.f + __expf(-g1));
    at[base + lane]      = (x0 - mu) * rs * g0;
    at[base + 32 + lane] = (x1 - mu) * rs * g1;
}

// ---------------- swiglu: h = a * silu(b) ----------------
__global__ void swiglu_kernel(const float* __restrict__ ab, float* __restrict__ hb)
{
    size_t i = (size_t)blockIdx.x * 256 + threadIdx.x;   // ROWS*HID
    int row = (int)(i / HID), col = (int)(i % HID);
    float a = ab[(size_t)row * (2*HID) + col];
    float bb = ab[(size_t)row * (2*HID) + HID + col];
    hb[i] = a * bb / (1.f + __expf(-bb));
}

// ---------------- launch ----------------
extern "C" void kernel_launch(void* const* d_in, const int* in_sizes, int n_in,
                              void* d_out, int out_size)
{
    const float* x     = (const float*)d_in[0];
    const float* ln1w  = (const float*)d_in[1];
    const float* ln1b  = (const float*)d_in[2];
    const float* wq    = (const float*)d_in[3];
    const float* wk    = (const float*)d_in[4];
    const float* wv    = (const float*)d_in[5];
    const float* wg    = (const float*)d_in[6];
    const float* wo    = (const float*)d_in[7];
    const float* ln2w  = (const float*)d_in[8];
    const float* ln2b  = (const float*)d_in[9];
    const float* w_in  = (const float*)d_in[10];
    const float* b_in  = (const float*)d_in[11];
    const float* w_out = (const float*)d_in[12];
    const float* b_out = (const float*)d_in[13];
    float* out = (float*)d_out;

    float *xn, *qkvg, *at, *x1, *xn2, *ab, *hb;
    cudaGetSymbolAddress((void**)&xn,   g_xn);
    cudaGetSymbolAddress((void**)&qkvg, g_qkvg);
    cudaGetSymbolAddress((void**)&at,   g_at);
    cudaGetSymbolAddress((void**)&x1,   g_x1);
    cudaGetSymbolAddress((void**)&xn2,  g_xn2);
    cudaGetSymbolAddress((void**)&ab,   g_ab);
    cudaGetSymbolAddress((void**)&hb,   g_hb);

    cudaFuncSetAttribute(attn3, cudaFuncAttributeMaxDynamicSharedMemorySize, ATTN_SMEM);

    // 1. LN1
    ln_kernel<<<ROWS, 256>>>(x, ln1w, ln1b, xn);
    // 2. Q/K/V/G projections into fused buffer (C ld = 4096)
    dim3 gP(DM/BN, ROWS/BM);
    gemm3<<<gP, 256>>>(xn, wq, qkvg + 0*DM,  ROWS, DM, DM, QKVG_N, nullptr, nullptr);
    gemm3<<<gP, 256>>>(xn, wk, qkvg + 1*DM,  ROWS, DM, DM, QKVG_N, nullptr, nullptr);
    gemm3<<<gP, 256>>>(xn, wv, qkvg + 2*DM,  ROWS, DM, DM, QKVG_N, nullptr, nullptr);
    gemm3<<<gP, 256>>>(xn, wg, qkvg + 3*DM,  ROWS, DM, DM, QKVG_N, nullptr, nullptr);
    // 3. retention attention
    attn3<<<dim3(SEQ/64, BATCH*NH), 256, ATTN_SMEM>>>(qkvg, at);
    // 4. groupnorm + silu gate
    gn_gate_kernel<<<ROWS*NH/8, 256>>>(at, qkvg);
    // 5. output projection + residual: x1 = x + at @ wo
    gemm3<<<gP, 256>>>(at, wo, x1, ROWS, DM, DM, DM, nullptr, x);
    // 6. LN2
    ln_kernel<<<ROWS, 256>>>(x1, ln2w, ln2b, xn2);
    // 7. FFN in: ab = xn2 @ w_in + b_in (N=5460)
    gemm3<<<dim3((2*HID + BN - 1)/BN, ROWS/BM), 256>>>(xn2, w_in, ab,
        ROWS, 2*HID, DM, 2*HID, b_in, nullptr);
    // 8. swiglu
    swiglu_kernel<<<(int)(((size_t)ROWS*HID)/256), 256>>>(ab, hb);
    // 9. FFN out + bias + residual: out = x1 + hb @ w_out + b_out (K=2730 tail-guarded)
    gemm3<<<gP, 256>>>(hb, w_out, out, ROWS, DM, HID, DM, b_out, x1);
}

// round 4
// speedup vs baseline: 5.0635x; 1.4491x over previous
#include <cuda_runtime.h>
#include <cuda_fp16.h>
#include <cstdint>
#include <cstddef>

#define SEQ    2048
#define BATCH  2
#define NH     16
#define DM     1024
#define HD     64
#define HID    2730
#define HIDP   2752      // HID padded to 128... (multiple of 32; 2752 = 86*32)
#define NIN    5460      // 2*HID
#define NINP   5504      // padded to 43*128
#define ROWS   (BATCH*SEQ)   // 4096
#define QKVG_N 4096

// ---------------- scratch (allocation-free device globals) ----------------
__device__ float  g_qkvg [(size_t)ROWS*QKVG_N];
__device__ float  g_atraw[ROWS*DM];
__device__ float  g_x1   [ROWS*DM];
__device__ float  g_ab   [(size_t)ROWS*NINP];
// fp16 hi/lo planes (A operands)
__device__ __half g_xn_h [ROWS*DM],  g_xn_l [ROWS*DM];
__device__ __half g_xn2_h[ROWS*DM],  g_xn2_l[ROWS*DM];
__device__ __half g_at_h [ROWS*DM],  g_at_l [ROWS*DM];
__device__ __half g_hb_h [(size_t)ROWS*HIDP], g_hb_l[(size_t)ROWS*HIDP];
// transposed weight planes [n][k]
__device__ __half g_wqkvg_h[(size_t)QKVG_N*DM], g_wqkvg_l[(size_t)QKVG_N*DM];
__device__ __half g_wo_h   [DM*DM],             g_wo_l   [DM*DM];
__device__ __half g_win_h  [(size_t)NINP*DM],   g_win_l  [(size_t)NINP*DM];
__device__ __half g_wout_h [(size_t)DM*HIDP],   g_wout_l [(size_t)DM*HIDP];

// ---------------- helpers ----------------
__device__ __forceinline__ void mma16(float* c, const uint32_t* a, const uint32_t* b) {
    asm volatile("mma.sync.aligned.m16n8k16.row.col.f32.f16.f16.f32 "
                 "{%0,%1,%2,%3},{%4,%5,%6,%7},{%8,%9},{%0,%1,%2,%3};\n"
                 : "+f"(c[0]), "+f"(c[1]), "+f"(c[2]), "+f"(c[3])
                 : "r"(a[0]), "r"(a[1]), "r"(a[2]), "r"(a[3]), "r"(b[0]), "r"(b[1]));
}
__device__ __forceinline__ void cvt2(float x, float y, __half2& hi, __half2& lo) {
    __half hx = __float2half_rn(x), hy = __float2half_rn(y);
    __half lx = __float2half_rn(x - __half2float(hx));
    __half ly = __float2half_rn(y - __half2float(hy));
    hi = __halves2half2(hx, hy);
    lo = __halves2half2(lx, ly);
}
__device__ __forceinline__ uint32_t smem_u32(const void* p) {
    return (uint32_t)__cvta_generic_to_shared(p);
}
__device__ __forceinline__ void ldsm4(uint32_t& r0, uint32_t& r1, uint32_t& r2, uint32_t& r3,
                                      uint32_t addr) {
    asm volatile("ldmatrix.sync.aligned.m8n8.x4.shared.b16 {%0,%1,%2,%3},[%4];\n"
                 : "=r"(r0), "=r"(r1), "=r"(r2), "=r"(r3) : "r"(addr));
}
__device__ __forceinline__ void cpa16(uint32_t dst, const void* src) {
    asm volatile("cp.async.cg.shared.global [%0],[%1],16;\n" :: "r"(dst), "l"(src));
}

// ---------------- weight transpose + hi/lo split (+pad zeros) ----------------
// src [sK x sN] fp32 -> dst transposed [dN x dK] fp16 planes
__global__ void convw_t(const float* __restrict__ src, __half* __restrict__ hiT,
                        __half* __restrict__ loT, int sK, int sN, int dK)
{
    __shared__ float t[32][33];
    int tx = threadIdx.x & 31, ty = threadIdx.x >> 5;
    int n0 = blockIdx.x * 32, k0 = blockIdx.y * 32;
#pragma unroll
    for (int i = 0; i < 4; i++) {
        int k = k0 + ty + 8*i;
        float v = (k < sK && (n0 + tx) < sN) ? src[(size_t)k * sN + n0 + tx] : 0.f;
        t[ty + 8*i][tx] = v;
    }
    __syncthreads();
#pragma unroll
    for (int i = 0; i < 4; i++) {
        int nl = ty + 8*i;
        float v = t[tx][nl];
        __half h = __float2half_rn(v);
        size_t o = (size_t)(n0 + nl) * dK + k0 + tx;
        hiT[o] = h;
        loT[o] = __float2half_rn(v - __half2float(h));
    }
}

// ---------------- LayerNorm -> hi/lo planes ----------------
__global__ void ln_kernel(const float* __restrict__ x, const float* __restrict__ w,
                          const float* __restrict__ b,
                          __half* __restrict__ ohi, __half* __restrict__ olo)
{
    __shared__ float red[2][8];
    int row = blockIdx.x, tid = threadIdx.x;
    const float* xr = x + (size_t)row * DM;
    float v[4], s = 0.f, q = 0.f;
#pragma unroll
    for (int i = 0; i < 4; i++) { v[i] = xr[tid + 256*i]; s += v[i]; q += v[i]*v[i]; }
#pragma unroll
    for (int off = 16; off; off >>= 1) {
        s += __shfl_xor_sync(~0u, s, off);
        q += __shfl_xor_sync(~0u, q, off);
    }
    if ((tid & 31) == 0) { red[0][tid>>5] = s; red[1][tid>>5] = q; }
    __syncthreads();
    if (tid < 32) {
        s = (tid < 8) ? red[0][tid] : 0.f;
        q = (tid < 8) ? red[1][tid] : 0.f;
#pragma unroll
        for (int off = 4; off; off >>= 1) {
            s += __shfl_xor_sync(~0u, s, off);
            q += __shfl_xor_sync(~0u, q, off);
        }
        if (tid == 0) { red[0][0] = s; red[1][0] = q; }
    }
    __syncthreads();
    s = red[0][0]; q = red[1][0];
    float mu = s * (1.f/DM);
    float rs = rsqrtf(q * (1.f/DM) - mu*mu + 1e-5f);
#pragma unroll
    for (int i = 0; i < 4; i++) {
        int c = tid + 256*i;
        float o = (v[i] - mu) * rs * w[c] + b[c];
        __half h = __float2half_rn(o);
        ohi[(size_t)row*DM + c] = h;
        olo[(size_t)row*DM + c] = __float2half_rn(o - __half2float(h));
    }
}

// ---------------- plane GEMM: C = A@B^T(+bias)(+add) ----------------
// A planes [M x K] row-major; B planes transposed [N x K]; fp16 hi/lo, 3-mma comp.
// BM=BN=128, BK=32, 256 thr (8 warps 2x4), 2 CTAs/SM, cp.async + ldmatrix.
// smem/stage (bytes): Ahi 0, Alo 8192, Bhi 16384, Blo 24576; stage stride 32768.
#define GP_SMEM 65536

__global__ __launch_bounds__(256, 2)
void gemm_p(const __half* __restrict__ Ahi, const __half* __restrict__ Alo,
            const __half* __restrict__ Bhi, const __half* __restrict__ Blo,
            float* __restrict__ C, int N, int K, int ldC,
            const float* __restrict__ bias, const float* __restrict__ add)
{
    extern __shared__ __half sh[];
    uint32_t sbase = smem_u32(sh);
    int tid = threadIdx.x, lane = tid & 31, wid = tid >> 5;
    int wm = wid >> 2, wn = wid & 3;
    int m0 = blockIdx.y * 128, n0 = blockIdx.x * 128;
    int KT = K >> 5;

    // cp.async mapping: row cr (+64), chunk cc; swizzled chunk = cc ^ ((cr>>1)&3)
    int cr = tid >> 2, cc = tid & 3;
    uint32_t dsto = (uint32_t)(cr*64 + ((cc ^ ((cr>>1)&3)) * 16));
    const __half* aS0 = Ahi + (size_t)(m0 + cr)*K + cc*8;
    const __half* aS1 = Alo + (size_t)(m0 + cr)*K + cc*8;
    const __half* bS0 = Bhi + (size_t)(n0 + cr)*K + cc*8;
    const __half* bS1 = Blo + (size_t)(n0 + cr)*K + cc*8;

#define ISSUE(st, kt) do {                                                   \
        uint32_t d_ = sbase + (st)*32768 + dsto;                             \
        int ko_ = (kt)*32;                                                   \
        cpa16(d_,               aS0 + ko_);                                  \
        cpa16(d_ + 4096,        aS0 + ko_ + (size_t)64*K);                   \
        cpa16(d_ + 8192,        aS1 + ko_);                                  \
        cpa16(d_ + 8192 + 4096, aS1 + ko_ + (size_t)64*K);                   \
        cpa16(d_ + 16384,        bS0 + ko_);                                 \
        cpa16(d_ + 16384 + 4096, bS0 + ko_ + (size_t)64*K);                  \
        cpa16(d_ + 24576,        bS1 + ko_);                                 \
        cpa16(d_ + 24576 + 4096, bS1 + ko_ + (size_t)64*K);                  \
        asm volatile("cp.async.commit_group;\n");                            \
    } while (0)

    // ldmatrix lane mapping: group g = lane>>3, l8 = lane&7
    int l8 = lane & 7, g = lane >> 3;
    int f_rl = (g & 1)*8 + l8;          // row within 16
    int f_cs = g >> 1;                  // chunk select (0/1)
    int f_swz = (f_rl >> 1) & 3;
    uint32_t ck[2] = { (uint32_t)(((0 + f_cs) ^ f_swz) * 16),
                       (uint32_t)(((2 + f_cs) ^ f_swz) * 16) };
    uint32_t aRow = (uint32_t)((wm*64 + f_rl) * 64);   // + mi*16*64
    uint32_t bRow = (uint32_t)((wn*32 + f_rl) * 64);   // + nt*16*64

    float acc[4][4][4] = {};

    ISSUE(0, 0);
    for (int kt = 0; kt < KT; kt++) {
        if (kt + 1 < KT) {
            ISSUE((kt + 1) & 1, kt + 1);
            asm volatile("cp.async.wait_group 1;\n");
        } else {
            asm volatile("cp.async.wait_group 0;\n");
        }
        __syncthreads();
        uint32_t sb = sbase + (kt & 1)*32768;
#pragma unroll
        for (int ks = 0; ks < 2; ks++) {
            uint32_t bh[4][2], bl[4][2], af[4][4];
#pragma unroll
            for (int nt = 0; nt < 2; nt++) {
                uint32_t r0, r1, r2, r3;
                ldsm4(r0, r1, r2, r3, sb + 16384 + bRow + nt*1024 + ck[ks]);
                bh[2*nt][0] = r0; bh[2*nt+1][0] = r1; bh[2*nt][1] = r2; bh[2*nt+1][1] = r3;
                ldsm4(r0, r1, r2, r3, sb + 24576 + bRow + nt*1024 + ck[ks]);
                bl[2*nt][0] = r0; bl[2*nt+1][0] = r1; bl[2*nt][1] = r2; bl[2*nt+1][1] = r3;
            }
#pragma unroll
            for (int mi = 0; mi < 4; mi++)
                ldsm4(af[mi][0], af[mi][1], af[mi][2], af[mi][3],
                      sb + aRow + mi*1024 + ck[ks]);
#pragma unroll
            for (int mi = 0; mi < 4; mi++)
#pragma unroll
                for (int ni = 0; ni < 4; ni++) {
                    mma16(acc[mi][ni], af[mi], bh[ni]);
                    mma16(acc[mi][ni], af[mi], bl[ni]);
                }
#pragma unroll
            for (int mi = 0; mi < 4; mi++)
                ldsm4(af[mi][0], af[mi][1], af[mi][2], af[mi][3],
                      sb + 8192 + aRow + mi*1024 + ck[ks]);
#pragma unroll
            for (int mi = 0; mi < 4; mi++)
#pragma unroll
                for (int ni = 0; ni < 4; ni++)
                    mma16(acc[mi][ni], af[mi], bh[ni]);
        }
        __syncthreads();
    }
#undef ISSUE

#pragma unroll
    for (int mi = 0; mi < 4; mi++) {
        int r = m0 + wm*64 + mi*16 + (lane >> 2);
#pragma unroll
        for (int ni = 0; ni < 4; ni++) {
            int cn = n0 + wn*32 + ni*8 + 2*(lane & 3);
            if (cn >= N) continue;
            float b0v = bias ? bias[cn]   : 0.f;
            float b1v = bias ? bias[cn+1] : 0.f;
            float v0 = acc[mi][ni][0] + b0v;
            float v1 = acc[mi][ni][1] + b1v;
            float v2 = acc[mi][ni][2] + b0v;
            float v3 = acc[mi][ni][3] + b1v;
            if (add) {
                v0 += add[(size_t)r*ldC + cn];     v1 += add[(size_t)r*ldC + cn + 1];
                v2 += add[(size_t)(r+8)*ldC + cn]; v3 += add[(size_t)(r+8)*ldC + cn + 1];
            }
            *(float2*)(C + (size_t)r*ldC + cn)     = make_float2(v0, v1);
            *(float2*)(C + (size_t)(r+8)*ldC + cn) = make_float2(v2, v3);
        }
    }
}

// ---------------- fused retention attention (fp16x2 tensor cores) ----------------
#define AHST 72
#define AWST 36
#define QHIW 0
#define QLOW 2304
#define KHIW 4608
#define KLOW 6912
#define VHIW 9216
#define VLOW 11520
#define SHIW 13824
#define SLOW 16128
#define RFW  18432
#define CFW  18496
#define ATTN_SMEM ((CFW + 64)*4)

__global__ __launch_bounds__(256)
void attn3(const float* __restrict__ qkvg, float* __restrict__ og)
{
    extern __shared__ uint32_t smw[];
    __half* smh = (__half*)smw;
    float*  smf = (float*)smw;
    int tid = threadIdx.x, lane = tid & 31, wid = tid >> 5;
    int wm = wid >> 1, wn = wid & 1;
    int bh = blockIdx.y, b = bh >> 4, h = bh & 15;
    int s0 = blockIdx.x * 64;
    float lg = log2f(1.f - exp2f(-5.f - (float)h));
    const float* q = qkvg + h*HD;
    const float* k = qkvg + DM + h*HD;
    const float* v = qkvg + 2*DM + h*HD;

#pragma unroll
    for (int i = 0; i < 8; i++) {
        int p = tid + 256*i;
        int r = p >> 5, c2 = (p & 31) * 2;
        float2 t = *(const float2*)(q + (size_t)(b*SEQ + s0 + r)*QKVG_N + c2);
        __half2 hi, lo;
        cvt2(t.x*0.125f, t.y*0.125f, hi, lo);
        *(__half2*)&smh[QHIW*2 + r*AHST + c2] = hi;
        *(__half2*)&smh[QLOW*2 + r*AHST + c2] = lo;
    }
    if (tid < 64) smf[RFW + tid] = exp2f((float)(s0 + tid) * lg);

    float oacc[4][4] = {};
    for (int t0 = 0; t0 <= s0; t0 += 64) {
        __syncthreads();
#pragma unroll
        for (int i = 0; i < 8; i++) {
            int p = tid + 256*i;
            int r = p >> 5, c2 = (p & 31) * 2;
            size_t base = (size_t)(b*SEQ + t0 + r)*QKVG_N + c2;
            float2 tk = *(const float2*)(k + base);
            float2 tv = *(const float2*)(v + base);
            __half2 hi, lo;
            cvt2(tk.x, tk.y, hi, lo);
            *(__half2*)&smh[KHIW*2 + r*AHST + c2] = hi;
            *(__half2*)&smh[KLOW*2 + r*AHST + c2] = lo;
            __half vh0 = __float2half_rn(tv.x);
            __half vh1 = __float2half_rn(tv.y);
            smh[VHIW*2 + c2*AHST + r]     = vh0;
            smh[VHIW*2 + (c2+1)*AHST + r] = vh1;
            smh[VLOW*2 + c2*AHST + r]     = __float2half_rn(tv.x - __half2float(vh0));
            smh[VLOW*2 + (c2+1)*AHST + r] = __float2half_rn(tv.y - __half2float(vh1));
        }
        if (tid < 64) smf[CFW + tid] = exp2f(-(float)(t0 + tid) * lg);
        __syncthreads();

        float sacc[4][4] = {};
#pragma unroll
        for (int ks = 0; ks < 4; ks++) {
            uint32_t ahi[4], alo[4], bhi[4][2], blo[4][2];
            int m = wm*16 + (lane >> 2);
            int ab = m*AWST + ks*8 + (lane & 3);
            ahi[0] = smw[QHIW + ab];       ahi[1] = smw[QHIW + ab + 8*AWST];
            ahi[2] = smw[QHIW + ab + 4];   ahi[3] = smw[QHIW + ab + 8*AWST + 4];
            alo[0] = smw[QLOW + ab];       alo[1] = smw[QLOW + ab + 8*AWST];
            alo[2] = smw[QLOW + ab + 4];   alo[3] = smw[QLOW + ab + 8*AWST + 4];
#pragma unroll
            for (int ni = 0; ni < 4; ni++) {
                int n = wn*32 + ni*8 + (lane >> 2);
                int nb = n*AWST + ks*8 + (lane & 3);
                bhi[ni][0] = smw[KHIW + nb]; bhi[ni][1] = smw[KHIW + nb + 4];
                blo[ni][0] = smw[KLOW + nb]; blo[ni][1] = smw[KLOW + nb + 4];
            }
#pragma unroll
            for (int ni = 0; ni < 4; ni++) {
                mma16(sacc[ni], ahi, bhi[ni]);
                mma16(sacc[ni], ahi, blo[ni]);
                mma16(sacc[ni], alo, bhi[ni]);
            }
        }

        bool diag = (t0 == s0);
        int r0 = wm*16 + (lane >> 2);
        float rf0 = smf[RFW + r0], rf1 = smf[RFW + r0 + 8];
#pragma unroll
        for (int ni = 0; ni < 4; ni++) {
            int c0 = wn*32 + ni*8 + 2*(lane & 3);
            float cf0 = smf[CFW + c0], cf1 = smf[CFW + c0 + 1];
            float w00 = rf0*cf0, w01 = rf0*cf1, w10 = rf1*cf0, w11 = rf1*cf1;
            if (diag) {
                if (r0   < c0  ) w00 = 0.f;
                if (r0   < c0+1) w01 = 0.f;
                if (r0+8 < c0  ) w10 = 0.f;
                if (r0+8 < c0+1) w11 = 0.f;
            }
            float v0 = sacc[ni][0]*w00, v1 = sacc[ni][1]*w01;
            float v2 = sacc[ni][2]*w10, v3 = sacc[ni][3]*w11;
            __half2 hi, lo;
            cvt2(v0, v1, hi, lo);
            *(__half2*)&smh[SHIW*2 + r0*AHST + c0] = hi;
            *(__half2*)&smh[SLOW*2 + r0*AHST + c0] = lo;
            cvt2(v2, v3, hi, lo);
            *(__half2*)&smh[SHIW*2 + (r0+8)*AHST + c0] = hi;
            *(__half2*)&smh[SLOW*2 + (r0+8)*AHST + c0] = lo;
        }
        __syncthreads();

#pragma unroll
        for (int ks = 0; ks < 4; ks++) {
            uint32_t ahi[4], alo[4], bhi[4][2], blo[4][2];
            int m = wm*16 + (lane >> 2);
            int ab = m*AWST + ks*8 + (lane & 3);
            ahi[0] = smw[SHIW + ab];       ahi[1] = smw[SHIW + ab + 8*AWST];
            ahi[2] = smw[SHIW + ab + 4];   ahi[3] = smw[SHIW + ab + 8*AWST + 4];
            alo[0] = smw[SLOW + ab];       alo[1] = smw[SLOW + ab + 8*AWST];
            alo[2] = smw[SLOW + ab + 4];   alo[3] = smw[SLOW + ab + 8*AWST + 4];
#pragma unroll
            for (int ni = 0; ni < 4; ni++) {
                int n = wn*32 + ni*8 + (lane >> 2);
                int nb = n*AWST + ks*8 + (lane & 3);
                bhi[ni][0] = smw[VHIW + nb]; bhi[ni][1] = smw[VHIW + nb + 4];
                blo[ni][0] = smw[VLOW + nb]; blo[ni][1] = smw[VLOW + nb + 4];
            }
#pragma unroll
            for (int ni = 0; ni < 4; ni++) {
                mma16(oacc[ni], ahi, bhi[ni]);
                mma16(oacc[ni], ahi, blo[ni]);
                mma16(oacc[ni], alo, bhi[ni]);
            }
        }
    }

    int r0 = wm*16 + (lane >> 2);
#pragma unroll
    for (int ni = 0; ni < 4; ni++) {
        int d0 = wn*32 + ni*8 + 2*(lane & 3);
        size_t i0 = ((size_t)(b*SEQ + s0 + r0)*NH + h)*HD + d0;
        size_t i1 = ((size_t)(b*SEQ + s0 + r0 + 8)*NH + h)*HD + d0;
        *(float2*)(og + i0) = make_float2(oacc[ni][0], oacc[ni][1]);
        *(float2*)(og + i1) = make_float2(oacc[ni][2], oacc[ni][3]);
    }
}

// ---------------- per-head groupnorm * silu(gate) -> hi/lo planes ----------------
__global__ void gn_gate_kernel(const float* __restrict__ at, const float* __restrict__ qkvg,
                               __half* __restrict__ ohi, __half* __restrict__ olo)
{
    int warp = threadIdx.x >> 5, lane = threadIdx.x & 31;
    int g = blockIdx.x * 8 + warp;          // row*16 + h
    int row = g >> 4, h = g & 15;
    size_t base = (size_t)g * 64;
    const float* gp = qkvg + (size_t)row*QKVG_N + 3*DM + h*64;
    float x0 = at[base + lane], x1 = at[base + 32 + lane];
    float s = x0 + x1, q = x0*x0 + x1*x1;
#pragma unroll
    for (int off = 16; off; off >>= 1) {
        s += __shfl_xor_sync(~0u, s, off);
        q += __shfl_xor_sync(~0u, q, off);
    }
    float mu = s * (1.f/64), var = q * (1.f/64) - mu*mu;
    float rs = rsqrtf(var + 1e-6f);
    float g0 = gp[lane], g1 = gp[32 + lane];
    g0 = g0 / (1.f + __expf(-g0));
    g1 = g1 / (1.f + __expf(-g1));
    float o0 = (x0 - mu) * rs * g0;
    float o1 = (x1 - mu) * rs * g1;
    __half h0 = __float2half_rn(o0), h1 = __float2half_rn(o1);
    ohi[base + lane]      = h0;
    olo[base + lane]      = __float2half_rn(o0 - __half2float(h0));
    ohi[base + 32 + lane] = h1;
    olo[base + 32 + lane] = __float2half_rn(o1 - __half2float(h1));
}

// ---------------- swiglu -> hi/lo planes (K-padded, zero fill) ----------------
__global__ void swiglu_kernel(const float* __restrict__ ab,
                              __half* __restrict__ ohi, __half* __restrict__ olo)
{
    size_t i = (size_t)blockIdx.x * 256 + threadIdx.x;   // ROWS*HIDP
    int row = (int)(i / HIDP), col = (int)(i % HIDP);
    float r = 0.f;
    if (col < HID) {
        float a = ab[(size_t)row * NINP + col];
        float bb = ab[(size_t)row * NINP + HID + col];
        r = a * bb / (1.f + __expf(-bb));
    }
    __half h = __float2half_rn(r);
    ohi[i] = h;
    olo[i] = __float2half_rn(r - __half2float(h));
}

// ---------------- launch ----------------
extern "C" void kernel_launch(void* const* d_in, const int* in_sizes, int n_in,
                              void* d_out, int out_size)
{
    const float* x     = (const float*)d_in[0];
    const float* ln1w  = (const float*)d_in[1];
    const float* ln1b  = (const float*)d_in[2];
    const float* wq    = (const float*)d_in[3];
    const float* wk    = (const float*)d_in[4];
    const float* wv    = (const float*)d_in[5];
    const float* wg    = (const float*)d_in[6];
    const float* wo    = (const float*)d_in[7];
    const float* ln2w  = (const float*)d_in[8];
    const float* ln2b  = (const float*)d_in[9];
    const float* w_in  = (const float*)d_in[10];
    const float* b_in  = (const float*)d_in[11];
    const float* w_out = (const float*)d_in[12];
    const float* b_out = (const float*)d_in[13];
    float* out = (float*)d_out;

    float *qkvg, *atraw, *x1, *ab;
    __half *xn_h, *xn_l, *xn2_h, *xn2_l, *at_h, *at_l, *hb_h, *hb_l;
    __half *wqk_h, *wqk_l, *wo_h, *wo_l, *win_h, *win_l, *wout_h, *wout_l;
    cudaGetSymbolAddress((void**)&qkvg,  g_qkvg);
    cudaGetSymbolAddress((void**)&atraw, g_atraw);
    cudaGetSymbolAddress((void**)&x1,    g_x1);
    cudaGetSymbolAddress((void**)&ab,    g_ab);
    cudaGetSymbolAddress((void**)&xn_h,  g_xn_h);   cudaGetSymbolAddress((void**)&xn_l,  g_xn_l);
    cudaGetSymbolAddress((void**)&xn2_h, g_xn2_h);  cudaGetSymbolAddress((void**)&xn2_l, g_xn2_l);
    cudaGetSymbolAddress((void**)&at_h,  g_at_h);   cudaGetSymbolAddress((void**)&at_l,  g_at_l);
    cudaGetSymbolAddress((void**)&hb_h,  g_hb_h);   cudaGetSymbolAddress((void**)&hb_l,  g_hb_l);
    cudaGetSymbolAddress((void**)&wqk_h, g_wqkvg_h); cudaGetSymbolAddress((void**)&wqk_l, g_wqkvg_l);
    cudaGetSymbolAddress((void**)&wo_h,  g_wo_h);   cudaGetSymbolAddress((void**)&wo_l,  g_wo_l);
    cudaGetSymbolAddress((void**)&win_h, g_win_h);  cudaGetSymbolAddress((void**)&win_l, g_win_l);
    cudaGetSymbolAddress((void**)&wout_h, g_wout_h); cudaGetSymbolAddress((void**)&wout_l, g_wout_l);

    cudaFuncSetAttribute(gemm_p, cudaFuncAttributeMaxDynamicSharedMemorySize, GP_SMEM);
    cudaFuncSetAttribute(attn3, cudaFuncAttributeMaxDynamicSharedMemorySize, ATTN_SMEM);

    // weight transpose + split (wq/wk/wv/wg stacked along n in wqkvgT)
    convw_t<<<dim3(32, 32), 256>>>(wq, wqk_h + 0*DM*DM,      wqk_l + 0*DM*DM,      DM, DM, DM);
    convw_t<<<dim3(32, 32), 256>>>(wk, wqk_h + (size_t)1*DM*DM, wqk_l + (size_t)1*DM*DM, DM, DM, DM);
    convw_t<<<dim3(32, 32), 256>>>(wv, wqk_h + (size_t)2*DM*DM, wqk_l + (size_t)2*DM*DM, DM, DM, DM);
    convw_t<<<dim3(32, 32), 256>>>(wg, wqk_h + (size_t)3*DM*DM, wqk_l + (size_t)3*DM*DM, DM, DM, DM);
    convw_t<<<dim3(32, 32), 256>>>(wo, wo_h, wo_l, DM, DM, DM);
    convw_t<<<dim3(NINP/32, 32), 256>>>(w_in, win_h, win_l, DM, NIN, DM);
    convw_t<<<dim3(32, HIDP/32), 256>>>(w_out, wout_h, wout_l, HID, DM, HIDP);

    // 1. LN1 -> planes
    ln_kernel<<<ROWS, 256>>>(x, ln1w, ln1b, xn_h, xn_l);
    // 2. fused QKVG: [4096x1024] x [1024x4096]
    gemm_p<<<dim3(QKVG_N/128, ROWS/128), 256, GP_SMEM>>>(xn_h, xn_l, wqk_h, wqk_l,
        qkvg, QKVG_N, DM, QKVG_N, nullptr, nullptr);
    // 3. retention attention
    attn3<<<dim3(SEQ/64, BATCH*NH), 256, ATTN_SMEM>>>(qkvg, atraw);
    // 4. groupnorm + silu gate -> planes
    gn_gate_kernel<<<ROWS*NH/8, 256>>>(atraw, qkvg, at_h, at_l);
    // 5. output projection + residual: x1 = x + at @ wo
    gemm_p<<<dim3(DM/128, ROWS/128), 256, GP_SMEM>>>(at_h, at_l, wo_h, wo_l,
        x1, DM, DM, DM, nullptr, x);
    // 6. LN2 -> planes
    ln_kernel<<<ROWS, 256>>>(x1, ln2w, ln2b, xn2_h, xn2_l);
    // 7. FFN in: ab = xn2 @ w_in + b_in (N real 5460, padded 5504)
    gemm_p<<<dim3(NINP/128, ROWS/128), 256, GP_SMEM>>>(xn2_h, xn2_l, win_h, win_l,
        ab, NIN, DM, NINP, b_in, nullptr);
    // 8. swiglu -> planes (K padded 2752)
    swiglu_kernel<<<(int)(((size_t)ROWS*HIDP)/256), 256>>>(ab, hb_h, hb_l);
    // 9. FFN out + bias + residual (K = 2752)
    gemm_p<<<dim3(DM/128, ROWS/128), 256, GP_SMEM>>>(hb_h, hb_l, wout_h, wout_l,
        out, DM, HIDP, DM, b_out, x1);
}

// round 6
// speedup vs baseline: 5.1350x; 1.0141x over previous
#include <cuda_runtime.h>
#include <cuda_fp16.h>
#include <cstdint>
#include <cstddef>

#define SEQ    2048
#define BATCH  2
#define NH     16
#define DM     1024
#define HD     64
#define HID    2730
#define HIDP   2752
#define NIN    5460
#define NINP   5504
#define ROWS   (BATCH*SEQ)
#define QKVG_N 4096

// ---------------- scratch (allocation-free device globals) ----------------
__device__ float  g_qkvg [(size_t)ROWS*QKVG_N];
__device__ float  g_atraw[ROWS*DM];
__device__ float  g_x1   [ROWS*DM];
__device__ float  g_ab   [(size_t)ROWS*NINP];
__device__ __half g_xn_h [ROWS*DM],  g_xn_l [ROWS*DM];
__device__ __half g_xn2_h[ROWS*DM],  g_xn2_l[ROWS*DM];
__device__ __half g_at_h [ROWS*DM],  g_at_l [ROWS*DM];
__device__ __half g_hb_h [(size_t)ROWS*HIDP], g_hb_l[(size_t)ROWS*HIDP];
__device__ __half g_wqkvg_h[(size_t)QKVG_N*DM], g_wqkvg_l[(size_t)QKVG_N*DM];
__device__ __half g_wo_h   [DM*DM],             g_wo_l   [DM*DM];
__device__ __half g_win_h  [(size_t)NINP*DM],   g_win_l  [(size_t)NINP*DM];
__device__ __half g_wout_h [(size_t)DM*HIDP],   g_wout_l [(size_t)DM*HIDP];

// ---------------- helpers ----------------
__device__ __forceinline__ void mma16(float* c, const uint32_t* a, const uint32_t* b) {
    asm volatile("mma.sync.aligned.m16n8k16.row.col.f32.f16.f16.f32 "
                 "{%0,%1,%2,%3},{%4,%5,%6,%7},{%8,%9},{%0,%1,%2,%3};\n"
                 : "+f"(c[0]), "+f"(c[1]), "+f"(c[2]), "+f"(c[3])
                 : "r"(a[0]), "r"(a[1]), "r"(a[2]), "r"(a[3]), "r"(b[0]), "r"(b[1]));
}
__device__ __forceinline__ void cvt2(float x, float y, __half2& hi, __half2& lo) {
    __half hx = __float2half_rn(x), hy = __float2half_rn(y);
    __half lx = __float2half_rn(x - __half2float(hx));
    __half ly = __float2half_rn(y - __half2float(hy));
    hi = __halves2half2(hx, hy);
    lo = __halves2half2(lx, ly);
}
__device__ __forceinline__ uint32_t smem_u32(const void* p) {
    return (uint32_t)__cvta_generic_to_shared(p);
}
__device__ __forceinline__ void ldsm4(uint32_t& r0, uint32_t& r1, uint32_t& r2, uint32_t& r3,
                                      uint32_t addr) {
    asm volatile("ldmatrix.sync.aligned.m8n8.x4.shared.b16 {%0,%1,%2,%3},[%4];\n"
                 : "=r"(r0), "=r"(r1), "=r"(r2), "=r"(r3) : "r"(addr));
}
__device__ __forceinline__ void cpa16(uint32_t dst, const void* src) {
    asm volatile("cp.async.cg.shared.global [%0],[%1],16;\n" :: "r"(dst), "l"(src));
}

// ---------------- merged weight transpose + hi/lo split (ONE launch) ----------------
__global__ void convw_all(const float* __restrict__ wq, const float* __restrict__ wk,
                          const float* __restrict__ wv, const float* __restrict__ wg,
                          const float* __restrict__ wo, const float* __restrict__ w_in,
                          const float* __restrict__ w_out,
                          __half* __restrict__ wqk_h, __half* __restrict__ wqk_l,
                          __half* __restrict__ wo_h,  __half* __restrict__ wo_l,
                          __half* __restrict__ win_h, __half* __restrict__ win_l,
                          __half* __restrict__ wout_h,__half* __restrict__ wout_l)
{
    __shared__ float t[32][33];
    int bt = blockIdx.x;
    const float* src; __half *hiT, *loT; int sK, sN, dK, n0, k0;
    if (bt < 4096) {
        int sub = bt >> 10, tt = bt & 1023;
        src = sub == 0 ? wq : sub == 1 ? wk : sub == 2 ? wv : wg;
        hiT = wqk_h + (size_t)sub*DM*DM; loT = wqk_l + (size_t)sub*DM*DM;
        sK = DM; sN = DM; dK = DM; n0 = (tt & 31)*32; k0 = (tt >> 5)*32;
    } else if (bt < 5120) {
        int tt = bt - 4096;
        src = wo; hiT = wo_h; loT = wo_l;
        sK = DM; sN = DM; dK = DM; n0 = (tt & 31)*32; k0 = (tt >> 5)*32;
    } else if (bt < 10624) {
        int tt = bt - 5120;
        src = w_in; hiT = win_h; loT = win_l;
        sK = DM; sN = NIN; dK = DM; n0 = (tt % 172)*32; k0 = (tt / 172)*32;
    } else {
        int tt = bt - 10624;
        src = w_out; hiT = wout_h; loT = wout_l;
        sK = HID; sN = DM; dK = HIDP; n0 = (tt & 31)*32; k0 = (tt >> 5)*32;
    }
    int tx = threadIdx.x & 31, ty = threadIdx.x >> 5;
#pragma unroll
    for (int i = 0; i < 4; i++) {
        int k = k0 + ty + 8*i;
        float v = (k < sK && (n0 + tx) < sN) ? src[(size_t)k * sN + n0 + tx] : 0.f;
        t[ty + 8*i][tx] = v;
    }
    __syncthreads();
#pragma unroll
    for (int i = 0; i < 4; i++) {
        int nl = ty + 8*i;
        float v = t[tx][nl];
        __half h = __float2half_rn(v);
        size_t o = (size_t)(n0 + nl) * dK + k0 + tx;
        hiT[o] = h;
        loT[o] = __float2half_rn(v - __half2float(h));
    }
}

// ---------------- LayerNorm -> hi/lo planes ----------------
__global__ void ln_kernel(const float* __restrict__ x, const float* __restrict__ w,
                          const float* __restrict__ b,
                          __half* __restrict__ ohi, __half* __restrict__ olo)
{
    __shared__ float red[2][8];
    int row = blockIdx.x, tid = threadIdx.x;
    const float* xr = x + (size_t)row * DM;
    float v[4], s = 0.f, q = 0.f;
#pragma unroll
    for (int i = 0; i < 4; i++) { v[i] = xr[tid + 256*i]; s += v[i]; q += v[i]*v[i]; }
#pragma unroll
    for (int off = 16; off; off >>= 1) {
        s += __shfl_xor_sync(~0u, s, off);
        q += __shfl_xor_sync(~0u, q, off);
    }
    if ((tid & 31) == 0) { red[0][tid>>5] = s; red[1][tid>>5] = q; }
    __syncthreads();
    if (tid < 32) {
        s = (tid < 8) ? red[0][tid] : 0.f;
        q = (tid < 8) ? red[1][tid] : 0.f;
#pragma unroll
        for (int off = 4; off; off >>= 1) {
            s += __shfl_xor_sync(~0u, s, off);
            q += __shfl_xor_sync(~0u, q, off);
        }
        if (tid == 0) { red[0][0] = s; red[1][0] = q; }
    }
    __syncthreads();
    s = red[0][0]; q = red[1][0];
    float mu = s * (1.f/DM);
    float rs = rsqrtf(q * (1.f/DM) - mu*mu + 1e-5f);
#pragma unroll
    for (int i = 0; i < 4; i++) {
        int c = tid + 256*i;
        float o = (v[i] - mu) * rs * w[c] + b[c];
        __half h = __float2half_rn(o);
        ohi[(size_t)row*DM + c] = h;
        olo[(size_t)row*DM + c] = __float2half_rn(o - __half2float(h));
    }
}

// ---------------- plane GEMM: C = A@B^T(+bias)(+add), fp16 hi/lo 3-mma ----------------
#define GP_SMEM 65536

__global__ __launch_bounds__(256, 2)
void gemm_p(const __half* __restrict__ Ahi, const __half* __restrict__ Alo,
            const __half* __restrict__ Bhi, const __half* __restrict__ Blo,
            float* __restrict__ C, int N, int K, int ldC,
            const float* __restrict__ bias, const float* __restrict__ add)
{
    extern __shared__ __half sh[];
    uint32_t sbase = smem_u32(sh);
    int tid = threadIdx.x, lane = tid & 31, wid = tid >> 5;
    int wm = wid >> 2, wn = wid & 3;
    int m0 = blockIdx.y * 128, n0 = blockIdx.x * 128;
    int KT = K >> 5;

    int cr = tid >> 2, cc = tid & 3;
    uint32_t dsto = (uint32_t)(cr*64 + ((cc ^ ((cr>>1)&3)) * 16));
    const __half* aS0 = Ahi + (size_t)(m0 + cr)*K + cc*8;
    const __half* aS1 = Alo + (size_t)(m0 + cr)*K + cc*8;
    const __half* bS0 = Bhi + (size_t)(n0 + cr)*K + cc*8;
    const __half* bS1 = Blo + (size_t)(n0 + cr)*K + cc*8;

#define ISSUE(st, kt) do {                                                   \
        uint32_t d_ = sbase + (st)*32768 + dsto;                             \
        int ko_ = (kt)*32;                                                   \
        cpa16(d_,               aS0 + ko_);                                  \
        cpa16(d_ + 4096,        aS0 + ko_ + (size_t)64*K);                   \
        cpa16(d_ + 8192,        aS1 + ko_);                                  \
        cpa16(d_ + 8192 + 4096, aS1 + ko_ + (size_t)64*K);                   \
        cpa16(d_ + 16384,        bS0 + ko_);                                 \
        cpa16(d_ + 16384 + 4096, bS0 + ko_ + (size_t)64*K);                  \
        cpa16(d_ + 24576,        bS1 + ko_);                                 \
        cpa16(d_ + 24576 + 4096, bS1 + ko_ + (size_t)64*K);                  \
        asm volatile("cp.async.commit_group;\n");                            \
    } while (0)

    int l8 = lane & 7, g = lane >> 3;
    int f_rl = (g & 1)*8 + l8;
    int f_cs = g >> 1;
    int f_swz = (f_rl >> 1) & 3;
    uint32_t ck[2] = { (uint32_t)(((0 + f_cs) ^ f_swz) * 16),
                       (uint32_t)(((2 + f_cs) ^ f_swz) * 16) };
    uint32_t aRow = (uint32_t)((wm*64 + f_rl) * 64);
    uint32_t bRow = (uint32_t)((wn*32 + f_rl) * 64);

    float acc[4][4][4] = {};

    ISSUE(0, 0);
    for (int kt = 0; kt < KT; kt++) {
        if (kt + 1 < KT) {
            ISSUE((kt + 1) & 1, kt + 1);
            asm volatile("cp.async.wait_group 1;\n");
        } else {
            asm volatile("cp.async.wait_group 0;\n");
        }
        __syncthreads();
        uint32_t sb = sbase + (kt & 1)*32768;
#pragma unroll
        for (int ks = 0; ks < 2; ks++) {
            uint32_t bh[4][2], bl[4][2], af[4][4];
#pragma unroll
            for (int nt = 0; nt < 2; nt++) {
                uint32_t r0, r1, r2, r3;
                ldsm4(r0, r1, r2, r3, sb + 16384 + bRow + nt*1024 + ck[ks]);
                bh[2*nt][0] = r0; bh[2*nt+1][0] = r1; bh[2*nt][1] = r2; bh[2*nt+1][1] = r3;
                ldsm4(r0, r1, r2, r3, sb + 24576 + bRow + nt*1024 + ck[ks]);
                bl[2*nt][0] = r0; bl[2*nt+1][0] = r1; bl[2*nt][1] = r2; bl[2*nt+1][1] = r3;
            }
#pragma unroll
            for (int mi = 0; mi < 4; mi++)
                ldsm4(af[mi][0], af[mi][1], af[mi][2], af[mi][3],
                      sb + aRow + mi*1024 + ck[ks]);
#pragma unroll
            for (int mi = 0; mi < 4; mi++)
#pragma unroll
                for (int ni = 0; ni < 4; ni++) {
                    mma16(acc[mi][ni], af[mi], bh[ni]);
                    mma16(acc[mi][ni], af[mi], bl[ni]);
                }
#pragma unroll
            for (int mi = 0; mi < 4; mi++)
                ldsm4(af[mi][0], af[mi][1], af[mi][2], af[mi][3],
                      sb + 8192 + aRow + mi*1024 + ck[ks]);
#pragma unroll
            for (int mi = 0; mi < 4; mi++)
#pragma unroll
                for (int ni = 0; ni < 4; ni++)
                    mma16(acc[mi][ni], af[mi], bh[ni]);
        }
        __syncthreads();
    }
#undef ISSUE

#pragma unroll
    for (int mi = 0; mi < 4; mi++) {
        int r = m0 + wm*64 + mi*16 + (lane >> 2);
#pragma unroll
        for (int ni = 0; ni < 4; ni++) {
            int cn = n0 + wn*32 + ni*8 + 2*(lane & 3);
            if (cn >= N) continue;
            float b0v = bias ? bias[cn]   : 0.f;
            float b1v = bias ? bias[cn+1] : 0.f;
            float v0 = acc[mi][ni][0] + b0v;
            float v1 = acc[mi][ni][1] + b1v;
            float v2 = acc[mi][ni][2] + b0v;
            float v3 = acc[mi][ni][3] + b1v;
            if (add) {
                v0 += add[(size_t)r*ldC + cn];     v1 += add[(size_t)r*ldC + cn + 1];
                v2 += add[(size_t)(r+8)*ldC + cn]; v3 += add[(size_t)(r+8)*ldC + cn + 1];
            }
            *(float2*)(C + (size_t)r*ldC + cn)     = make_float2(v0, v1);
            *(float2*)(C + (size_t)(r+8)*ldC + cn) = make_float2(v2, v3);
        }
    }
}

// ---------------- fused retention attention (fp16x2 mma, reg-prefetched K/V) ----------------
#define AHST 72
#define AWST 36
#define QHIW 0
#define QLOW 2304
#define KHIW 4608
#define KLOW 6912
#define VHIW 9216
#define VLOW 11520
#define SHIW 13824
#define SLOW 16128
#define RFW  18432
#define CFW  18496
#define ATTN_SMEM ((CFW + 64)*4)

__global__ __launch_bounds__(256)
void attn3(const float* __restrict__ qkvg, float* __restrict__ og)
{
    extern __shared__ uint32_t smw[];
    __half* smh = (__half*)smw;
    float*  smf = (float*)smw;
    int tid = threadIdx.x, lane = tid & 31, wid = tid >> 5;
    int wm = wid >> 1, wn = wid & 1;
    int bh = blockIdx.y, b = bh >> 4, h = bh & 15;
    int s0 = blockIdx.x * 64;
    float lg = log2f(1.f - exp2f(-5.f - (float)h));
    const float* q = qkvg + h*HD;
    const float* k = qkvg + DM + h*HD;
    const float* v = qkvg + 2*DM + h*HD;

    // decay truncation: skip tiles whose max weight gamma^(s0-t0-63) < 2^-40
    int dist_max = (int)(40.0f / (-lg));
    int cc = s0 - 63 - dist_max;
    int t_start = (cc <= 0) ? 0 : ((cc + 63) & ~63);

#pragma unroll
    for (int i = 0; i < 8; i++) {
        int p = tid + 256*i;
        int r = p >> 5, c2 = (p & 31) * 2;
        float2 t = *(const float2*)(q + (size_t)(b*SEQ + s0 + r)*QKVG_N + c2);
        __half2 hi, lo;
        cvt2(t.x*0.125f, t.y*0.125f, hi, lo);
        *(__half2*)&smh[QHIW*2 + r*AHST + c2] = hi;
        *(__half2*)&smh[QLOW*2 + r*AHST + c2] = lo;
    }
    if (tid < 64) smf[RFW + tid] = exp2f((float)(s0 + tid) * lg);

    // register prefetch of K/V tiles
    float2 rK[8], rV[8];
#define LOADKV(t0_) do {                                                      \
        _Pragma("unroll")                                                     \
        for (int i_ = 0; i_ < 8; i_++) {                                      \
            int p_ = tid + 256*i_;                                            \
            int r_ = p_ >> 5, c2_ = (p_ & 31) * 2;                            \
            size_t base_ = (size_t)(b*SEQ + (t0_) + r_)*QKVG_N + c2_;         \
            rK[i_] = *(const float2*)(k + base_);                             \
            rV[i_] = *(const float2*)(v + base_);                             \
        }                                                                     \
    } while (0)

    LOADKV(t_start);

    float oacc[4][4] = {};
    for (int t0 = t_start; t0 <= s0; t0 += 64) {
        __syncthreads();   // prev iter done with K/V/S smem
        // commit staged K/V registers to smem (cvt to hi/lo; V transposed)
#pragma unroll
        for (int i = 0; i < 8; i++) {
            int p = tid + 256*i;
            int r = p >> 5, c2 = (p & 31) * 2;
            __half2 hi, lo;
            cvt2(rK[i].x, rK[i].y, hi, lo);
            *(__half2*)&smh[KHIW*2 + r*AHST + c2] = hi;
            *(__half2*)&smh[KLOW*2 + r*AHST + c2] = lo;
            __half vh0 = __float2half_rn(rV[i].x);
            __half vh1 = __float2half_rn(rV[i].y);
            smh[VHIW*2 + c2*AHST + r]     = vh0;
            smh[VHIW*2 + (c2+1)*AHST + r] = vh1;
            smh[VLOW*2 + c2*AHST + r]     = __float2half_rn(rV[i].x - __half2float(vh0));
            smh[VLOW*2 + (c2+1)*AHST + r] = __float2half_rn(rV[i].y - __half2float(vh1));
        }
        if (tid < 64) smf[CFW + tid] = exp2f(-(float)(t0 + tid) * lg);
        // prefetch next tile while mma runs
        if (t0 + 64 <= s0) LOADKV(t0 + 64);
        __syncthreads();

        // S = Q @ K^T (m64 n64 k64)
        float sacc[4][4] = {};
#pragma unroll
        for (int ks = 0; ks < 4; ks++) {
            uint32_t ahi[4], alo[4], bhi[4][2], blo[4][2];
            int m = wm*16 + (lane >> 2);
            int ab = m*AWST + ks*8 + (lane & 3);
            ahi[0] = smw[QHIW + ab];       ahi[1] = smw[QHIW + ab + 8*AWST];
            ahi[2] = smw[QHIW + ab + 4];   ahi[3] = smw[QHIW + ab + 8*AWST + 4];
            alo[0] = smw[QLOW + ab];       alo[1] = smw[QLOW + ab + 8*AWST];
            alo[2] = smw[QLOW + ab + 4];   alo[3] = smw[QLOW + ab + 8*AWST + 4];
#pragma unroll
            for (int ni = 0; ni < 4; ni++) {
                int n = wn*32 + ni*8 + (lane >> 2);
                int nb = n*AWST + ks*8 + (lane & 3);
                bhi[ni][0] = smw[KHIW + nb]; bhi[ni][1] = smw[KHIW + nb + 4];
                blo[ni][0] = smw[KLOW + nb]; blo[ni][1] = smw[KLOW + nb + 4];
            }
#pragma unroll
            for (int ni = 0; ni < 4; ni++) {
                mma16(sacc[ni], ahi, bhi[ni]);
                mma16(sacc[ni], ahi, blo[ni]);
                mma16(sacc[ni], alo, bhi[ni]);
            }
        }

        bool diag = (t0 == s0);
        int r0 = wm*16 + (lane >> 2);
        float rf0 = smf[RFW + r0], rf1 = smf[RFW + r0 + 8];
#pragma unroll
        for (int ni = 0; ni < 4; ni++) {
            int c0 = wn*32 + ni*8 + 2*(lane & 3);
            float cf0 = smf[CFW + c0], cf1 = smf[CFW + c0 + 1];
            float w00 = rf0*cf0, w01 = rf0*cf1, w10 = rf1*cf0, w11 = rf1*cf1;
            if (diag) {
                if (r0   < c0  ) w00 = 0.f;
                if (r0   < c0+1) w01 = 0.f;
                if (r0+8 < c0  ) w10 = 0.f;
                if (r0+8 < c0+1) w11 = 0.f;
            }
            float v0 = sacc[ni][0]*w00, v1 = sacc[ni][1]*w01;
            float v2 = sacc[ni][2]*w10, v3 = sacc[ni][3]*w11;
            __half2 hi, lo;
            cvt2(v0, v1, hi, lo);
            *(__half2*)&smh[SHIW*2 + r0*AHST + c0] = hi;
            *(__half2*)&smh[SLOW*2 + r0*AHST + c0] = lo;
            cvt2(v2, v3, hi, lo);
            *(__half2*)&smh[SHIW*2 + (r0+8)*AHST + c0] = hi;
            *(__half2*)&smh[SLOW*2 + (r0+8)*AHST + c0] = lo;
        }
        __syncthreads();

        // O += S @ V (m64 n64 k64), V^T layout [d][t]
#pragma unroll
        for (int ks = 0; ks < 4; ks++) {
            uint32_t ahi[4], alo[4], bhi[4][2], blo[4][2];
            int m = wm*16 + (lane >> 2);
            int ab = m*AWST + ks*8 + (lane & 3);
            ahi[0] = smw[SHIW + ab];       ahi[1] = smw[SHIW + ab + 8*AWST];
            ahi[2] = smw[SHIW + ab + 4];   ahi[3] = smw[SHIW + ab + 8*AWST + 4];
            alo[0] = smw[SLOW + ab];       alo[1] = smw[SLOW + ab + 8*AWST];
            alo[2] = smw[SLOW + ab + 4];   alo[3] = smw[SLOW + ab + 8*AWST + 4];
#pragma unroll
            for (int ni = 0; ni < 4; ni++) {
                int n = wn*32 + ni*8 + (lane >> 2);
                int nb = n*AWST + ks*8 + (lane & 3);
                bhi[ni][0] = smw[VHIW + nb]; bhi[ni][1] = smw[VHIW + nb + 4];
                blo[ni][0] = smw[VLOW + nb]; blo[ni][1] = smw[VLOW + nb + 4];
            }
#pragma unroll
            for (int ni = 0; ni < 4; ni++) {
                mma16(oacc[ni], ahi, bhi[ni]);
                mma16(oacc[ni], ahi, blo[ni]);
                mma16(oacc[ni], alo, bhi[ni]);
            }
        }
    }
#undef LOADKV

    int r0 = wm*16 + (lane >> 2);
#pragma unroll
    for (int ni = 0; ni < 4; ni++) {
        int d0 = wn*32 + ni*8 + 2*(lane & 3);
        size_t i0 = ((size_t)(b*SEQ + s0 + r0)*NH + h)*HD + d0;
        size_t i1 = ((size_t)(b*SEQ + s0 + r0 + 8)*NH + h)*HD + d0;
        *(float2*)(og + i0) = make_float2(oacc[ni][0], oacc[ni][1]);
        *(float2*)(og + i1) = make_float2(oacc[ni][2], oacc[ni][3]);
    }
}

// ---------------- per-head groupnorm * silu(gate) -> hi/lo planes ----------------
__global__ void gn_gate_kernel(const float* __restrict__ at, const float* __restrict__ qkvg,
                               __half* __restrict__ ohi, __half* __restrict__ olo)
{
    int warp = threadIdx.x >> 5, lane = threadIdx.x & 31;
    int g = blockIdx.x * 8 + warp;
    int row = g >> 4, h = g & 15;
    size_t base = (size_t)g * 64;
    const float* gp = qkvg + (size_t)row*QKVG_N + 3*DM + h*64;
    float x0 = at[base + lane], x1 = at[base + 32 + lane];
    float s = x0 + x1, q = x0*x0 + x1*x1;
#pragma unroll
    for (int off = 16; off; off >>= 1) {
        s += __shfl_xor_sync(~0u, s, off);
        q += __shfl_xor_sync(~0u, q, off);
    }
    float mu = s * (1.f/64), var = q * (1.f/64) - mu*mu;
    float rs = rsqrtf(var + 1e-6f);
    float g0 = gp[lane], g1 = gp[32 + lane];
    g0 = g0 / (1.f + __expf(-g0));
    g1 = g1 / (1.f + __expf(-g1));
    float o0 = (x0 - mu) * rs * g0;
    float o1 = (x1 - mu) * rs * g1;
    __half h0 = __float2half_rn(o0), h1 = __float2half_rn(o1);
    ohi[base + lane]      = h0;
    olo[base + lane]      = __float2half_rn(o0 - __half2float(h0));
    ohi[base + 32 + lane] = h1;
    olo[base + 32 + lane] = __float2half_rn(o1 - __half2float(h1));
}

// ---------------- swiglu -> hi/lo planes (K-padded, zero fill) ----------------
__global__ void swiglu_kernel(const float* __restrict__ ab,
                              __half* __restrict__ ohi, __half* __restrict__ olo)
{
    size_t i = (size_t)blockIdx.x * 256 + threadIdx.x;
    int row = (int)(i / HIDP), col = (int)(i % HIDP);
    float r = 0.f;
    if (col < HID) {
        float a = ab[(size_t)row * NINP + col];
        float bb = ab[(size_t)row * NINP + HID + col];
        r = a * bb / (1.f + __expf(-bb));
    }
    __half h = __float2half_rn(r);
    ohi[i] = h;
    olo[i] = __float2half_rn(r - __half2float(h));
}

// ---------------- launch ----------------
extern "C" void kernel_launch(void* const* d_in, const int* in_sizes, int n_in,
                              void* d_out, int out_size)
{
    const float* x     = (const float*)d_in[0];
    const float* ln1w  = (const float*)d_in[1];
    const float* ln1b  = (const float*)d_in[2];
    const float* wq    = (const float*)d_in[3];
    const float* wk    = (const float*)d_in[4];
    const float* wv    = (const float*)d_in[5];
    const float* wg    = (const float*)d_in[6];
    const float* wo    = (const float*)d_in[7];
    const float* ln2w  = (const float*)d_in[8];
    const float* ln2b  = (const float*)d_in[9];
    const float* w_in  = (const float*)d_in[10];
    const float* b_in  = (const float*)d_in[11];
    const float* w_out = (const float*)d_in[12];
    const float* b_out = (const float*)d_in[13];
    float* out = (float*)d_out;

    float *qkvg, *atraw, *x1, *ab;
    __half *xn_h, *xn_l, *xn2_h, *xn2_l, *at_h, *at_l, *hb_h, *hb_l;
    __half *wqk_h, *wqk_l, *wo_h, *wo_l, *win_h, *win_l, *wout_h, *wout_l;
    cudaGetSymbolAddress((void**)&qkvg,  g_qkvg);
    cudaGetSymbolAddress((void**)&atraw, g_atraw);
    cudaGetSymbolAddress((void**)&x1,    g_x1);
    cudaGetSymbolAddress((void**)&ab,    g_ab);
    cudaGetSymbolAddress((void**)&xn_h,  g_xn_h);   cudaGetSymbolAddress((void**)&xn_l,  g_xn_l);
    cudaGetSymbolAddress((void**)&xn2_h, g_xn2_h);  cudaGetSymbolAddress((void**)&xn2_l, g_xn2_l);
    cudaGetSymbolAddress((void**)&at_h,  g_at_h);   cudaGetSymbolAddress((void**)&at_l,  g_at_l);
    cudaGetSymbolAddress((void**)&hb_h,  g_hb_h);   cudaGetSymbolAddress((void**)&hb_l,  g_hb_l);
    cudaGetSymbolAddress((void**)&wqk_h, g_wqkvg_h); cudaGetSymbolAddress((void**)&wqk_l, g_wqkvg_l);
    cudaGetSymbolAddress((void**)&wo_h,  g_wo_h);   cudaGetSymbolAddress((void**)&wo_l,  g_wo_l);
    cudaGetSymbolAddress((void**)&win_h, g_win_h);  cudaGetSymbolAddress((void**)&win_l, g_win_l);
    cudaGetSymbolAddress((void**)&wout_h, g_wout_h); cudaGetSymbolAddress((void**)&wout_l, g_wout_l);

    cudaFuncSetAttribute(gemm_p, cudaFuncAttributeMaxDynamicSharedMemorySize, GP_SMEM);
    cudaFuncSetAttribute(attn3, cudaFuncAttributeMaxDynamicSharedMemorySize, ATTN_SMEM);

    // 1. merged weight transpose+split (single launch)
    convw_all<<<13376, 256>>>(wq, wk, wv, wg, wo, w_in, w_out,
                              wqk_h, wqk_l, wo_h, wo_l, win_h, win_l, wout_h, wout_l);
    // 2. LN1 -> planes
    ln_kernel<<<ROWS, 256>>>(x, ln1w, ln1b, xn_h, xn_l);
    // 3. fused QKVG
    gemm_p<<<dim3(QKVG_N/128, ROWS/128), 256, GP_SMEM>>>(xn_h, xn_l, wqk_h, wqk_l,
        qkvg, QKVG_N, DM, QKVG_N, nullptr, nullptr);
    // 4. retention attention
    attn3<<<dim3(SEQ/64, BATCH*NH), 256, ATTN_SMEM>>>(qkvg, atraw);
    // 5. groupnorm + silu gate -> planes
    gn_gate_kernel<<<ROWS*NH/8, 256>>>(atraw, qkvg, at_h, at_l);
    // 6. output projection + residual  <-- profiled launch (index 5)
    gemm_p<<<dim3(DM/128, ROWS/128), 256, GP_SMEM>>>(at_h, at_l, wo_h, wo_l,
        x1, DM, DM, DM, nullptr, x);
    // 7. LN2 -> planes
    ln_kernel<<<ROWS, 256>>>(x1, ln2w, ln2b, xn2_h, xn2_l);
    // 8. FFN in (N real 5460, padded 5504)
    gemm_p<<<dim3(NINP/128, ROWS/128), 256, GP_SMEM>>>(xn2_h, xn2_l, win_h, win_l,
        ab, NIN, DM, NINP, b_in, nullptr);
    // 9. swiglu -> planes (K padded 2752)
    swiglu_kernel<<<(int)(((size_t)ROWS*HIDP)/256), 256>>>(ab, hb_h, hb_l);
    // 10. FFN out + bias + residual (K = 2752)
    gemm_p<<<dim3(DM/128, ROWS/128), 256, GP_SMEM>>>(hb_h, hb_l, wout_h, wout_l,
        out, DM, HIDP, DM, b_out, x1);
}

// round 7
// speedup vs baseline: 5.6631x; 1.1028x over previous
#include <cuda_runtime.h>
#include <cuda_fp16.h>
#include <cstdint>
#include <cstddef>

#define SEQ    2048
#define BATCH  2
#define NH     16
#define DM     1024
#define HD     64
#define HID    2730
#define HIDP   2752
#define NIN    5460
#define NINP   5504
#define ROWS   (BATCH*SEQ)
#define QKVG_N 4096

// ---------------- scratch (allocation-free device globals) ----------------
__device__ float  g_qkvg [(size_t)ROWS*QKVG_N];
__device__ float  g_atraw[ROWS*DM];
__device__ float  g_x1   [ROWS*DM];
__device__ float  g_ab   [(size_t)ROWS*NINP];
__device__ __half g_xn_h [ROWS*DM],  g_xn_l [ROWS*DM];
__device__ __half g_xn2_h[ROWS*DM],  g_xn2_l[ROWS*DM];
__device__ __half g_at_h [ROWS*DM],  g_at_l [ROWS*DM];
__device__ __half g_hb_h [(size_t)ROWS*HIDP], g_hb_l[(size_t)ROWS*HIDP];
__device__ __half g_wqkvg_h[(size_t)QKVG_N*DM], g_wqkvg_l[(size_t)QKVG_N*DM];
__device__ __half g_wo_h   [DM*DM],             g_wo_l   [DM*DM];
__device__ __half g_win_h  [(size_t)NINP*DM],   g_win_l  [(size_t)NINP*DM];
__device__ __half g_wout_h [(size_t)DM*HIDP],   g_wout_l [(size_t)DM*HIDP];

// ---------------- helpers ----------------
__device__ __forceinline__ void mma16(float* c, const uint32_t* a, const uint32_t* b) {
    asm volatile("mma.sync.aligned.m16n8k16.row.col.f32.f16.f16.f32 "
                 "{%0,%1,%2,%3},{%4,%5,%6,%7},{%8,%9},{%0,%1,%2,%3};\n"
                 : "+f"(c[0]), "+f"(c[1]), "+f"(c[2]), "+f"(c[3])
                 : "r"(a[0]), "r"(a[1]), "r"(a[2]), "r"(a[3]), "r"(b[0]), "r"(b[1]));
}
__device__ __forceinline__ void cvt2(float x, float y, __half2& hi, __half2& lo) {
    __half hx = __float2half_rn(x), hy = __float2half_rn(y);
    __half lx = __float2half_rn(x - __half2float(hx));
    __half ly = __float2half_rn(y - __half2float(hy));
    hi = __halves2half2(hx, hy);
    lo = __halves2half2(lx, ly);
}
__device__ __forceinline__ uint32_t smem_u32(const void* p) {
    return (uint32_t)__cvta_generic_to_shared(p);
}
__device__ __forceinline__ void ldsm4(uint32_t& r0, uint32_t& r1, uint32_t& r2, uint32_t& r3,
                                      uint32_t addr) {
    asm volatile("ldmatrix.sync.aligned.m8n8.x4.shared.b16 {%0,%1,%2,%3},[%4];\n"
                 : "=r"(r0), "=r"(r1), "=r"(r2), "=r"(r3) : "r"(addr));
}
__device__ __forceinline__ void ldsm4t(uint32_t& r0, uint32_t& r1, uint32_t& r2, uint32_t& r3,
                                       uint32_t addr) {
    asm volatile("ldmatrix.sync.aligned.m8n8.x4.trans.shared.b16 {%0,%1,%2,%3},[%4];\n"
                 : "=r"(r0), "=r"(r1), "=r"(r2), "=r"(r3) : "r"(addr));
}
__device__ __forceinline__ void cpa16(uint32_t dst, const void* src) {
    asm volatile("cp.async.cg.shared.global [%0],[%1],16;\n" :: "r"(dst), "l"(src));
}

// ---------------- merged weight transpose + hi/lo split (ONE launch) ----------------
__global__ void convw_all(const float* __restrict__ wq, const float* __restrict__ wk,
                          const float* __restrict__ wv, const float* __restrict__ wg,
                          const float* __restrict__ wo, const float* __restrict__ w_in,
                          const float* __restrict__ w_out,
                          __half* __restrict__ wqk_h, __half* __restrict__ wqk_l,
                          __half* __restrict__ wo_h,  __half* __restrict__ wo_l,
                          __half* __restrict__ win_h, __half* __restrict__ win_l,
                          __half* __restrict__ wout_h,__half* __restrict__ wout_l)
{
    __shared__ float t[32][33];
    int bt = blockIdx.x;
    const float* src; __half *hiT, *loT; int sK, sN, dK, n0, k0;
    if (bt < 4096) {
        int sub = bt >> 10, tt = bt & 1023;
        src = sub == 0 ? wq : sub == 1 ? wk : sub == 2 ? wv : wg;
        hiT = wqk_h + (size_t)sub*DM*DM; loT = wqk_l + (size_t)sub*DM*DM;
        sK = DM; sN = DM; dK = DM; n0 = (tt & 31)*32; k0 = (tt >> 5)*32;
    } else if (bt < 5120) {
        int tt = bt - 4096;
        src = wo; hiT = wo_h; loT = wo_l;
        sK = DM; sN = DM; dK = DM; n0 = (tt & 31)*32; k0 = (tt >> 5)*32;
    } else if (bt < 10624) {
        int tt = bt - 5120;
        src = w_in; hiT = win_h; loT = win_l;
        sK = DM; sN = NIN; dK = DM; n0 = (tt % 172)*32; k0 = (tt / 172)*32;
    } else {
        int tt = bt - 10624;
        src = w_out; hiT = wout_h; loT = wout_l;
        sK = HID; sN = DM; dK = HIDP; n0 = (tt & 31)*32; k0 = (tt >> 5)*32;
    }
    int tx = threadIdx.x & 31, ty = threadIdx.x >> 5;
#pragma unroll
    for (int i = 0; i < 4; i++) {
        int k = k0 + ty + 8*i;
        float v = (k < sK && (n0 + tx) < sN) ? src[(size_t)k * sN + n0 + tx] : 0.f;
        t[ty + 8*i][tx] = v;
    }
    __syncthreads();
#pragma unroll
    for (int i = 0; i < 4; i++) {
        int nl = ty + 8*i;
        float v = t[tx][nl];
        __half h = __float2half_rn(v);
        size_t o = (size_t)(n0 + nl) * dK + k0 + tx;
        hiT[o] = h;
        loT[o] = __float2half_rn(v - __half2float(h));
    }
}

// ---------------- LayerNorm -> hi/lo planes ----------------
__global__ void ln_kernel(const float* __restrict__ x, const float* __restrict__ w,
                          const float* __restrict__ b,
                          __half* __restrict__ ohi, __half* __restrict__ olo)
{
    __shared__ float red[2][8];
    int row = blockIdx.x, tid = threadIdx.x;
    const float* xr = x + (size_t)row * DM;
    float v[4], s = 0.f, q = 0.f;
#pragma unroll
    for (int i = 0; i < 4; i++) { v[i] = xr[tid + 256*i]; s += v[i]; q += v[i]*v[i]; }
#pragma unroll
    for (int off = 16; off; off >>= 1) {
        s += __shfl_xor_sync(~0u, s, off);
        q += __shfl_xor_sync(~0u, q, off);
    }
    if ((tid & 31) == 0) { red[0][tid>>5] = s; red[1][tid>>5] = q; }
    __syncthreads();
    if (tid < 32) {
        s = (tid < 8) ? red[0][tid] : 0.f;
        q = (tid < 8) ? red[1][tid] : 0.f;
#pragma unroll
        for (int off = 4; off; off >>= 1) {
            s += __shfl_xor_sync(~0u, s, off);
            q += __shfl_xor_sync(~0u, q, off);
        }
        if (tid == 0) { red[0][0] = s; red[1][0] = q; }
    }
    __syncthreads();
    s = red[0][0]; q = red[1][0];
    float mu = s * (1.f/DM);
    float rs = rsqrtf(q * (1.f/DM) - mu*mu + 1e-5f);
#pragma unroll
    for (int i = 0; i < 4; i++) {
        int c = tid + 256*i;
        float o = (v[i] - mu) * rs * w[c] + b[c];
        __half h = __float2half_rn(o);
        ohi[(size_t)row*DM + c] = h;
        olo[(size_t)row*DM + c] = __float2half_rn(o - __half2float(h));
    }
}

// ---------------- plane GEMM (unchanged, validated) ----------------
#define GP_SMEM 65536

__global__ __launch_bounds__(256, 2)
void gemm_p(const __half* __restrict__ Ahi, const __half* __restrict__ Alo,
            const __half* __restrict__ Bhi, const __half* __restrict__ Blo,
            float* __restrict__ C, int N, int K, int ldC,
            const float* __restrict__ bias, const float* __restrict__ add)
{
    extern __shared__ __half sh[];
    uint32_t sbase = smem_u32(sh);
    int tid = threadIdx.x, lane = tid & 31, wid = tid >> 5;
    int wm = wid >> 2, wn = wid & 3;
    int m0 = blockIdx.y * 128, n0 = blockIdx.x * 128;
    int KT = K >> 5;

    int cr = tid >> 2, cc = tid & 3;
    uint32_t dsto = (uint32_t)(cr*64 + ((cc ^ ((cr>>1)&3)) * 16));
    const __half* aS0 = Ahi + (size_t)(m0 + cr)*K + cc*8;
    const __half* aS1 = Alo + (size_t)(m0 + cr)*K + cc*8;
    const __half* bS0 = Bhi + (size_t)(n0 + cr)*K + cc*8;
    const __half* bS1 = Blo + (size_t)(n0 + cr)*K + cc*8;

#define ISSUE(st, kt) do {                                                   \
        uint32_t d_ = sbase + (st)*32768 + dsto;                             \
        int ko_ = (kt)*32;                                                   \
        cpa16(d_,               aS0 + ko_);                                  \
        cpa16(d_ + 4096,        aS0 + ko_ + (size_t)64*K);                   \
        cpa16(d_ + 8192,        aS1 + ko_);                                  \
        cpa16(d_ + 8192 + 4096, aS1 + ko_ + (size_t)64*K);                   \
        cpa16(d_ + 16384,        bS0 + ko_);                                 \
        cpa16(d_ + 16384 + 4096, bS0 + ko_ + (size_t)64*K);                  \
        cpa16(d_ + 24576,        bS1 + ko_);                                 \
        cpa16(d_ + 24576 + 4096, bS1 + ko_ + (size_t)64*K);                  \
        asm volatile("cp.async.commit_group;\n");                            \
    } while (0)

    int l8 = lane & 7, g = lane >> 3;
    int f_rl = (g & 1)*8 + l8;
    int f_cs = g >> 1;
    int f_swz = (f_rl >> 1) & 3;
    uint32_t ck[2] = { (uint32_t)(((0 + f_cs) ^ f_swz) * 16),
                       (uint32_t)(((2 + f_cs) ^ f_swz) * 16) };
    uint32_t aRow = (uint32_t)((wm*64 + f_rl) * 64);
    uint32_t bRow = (uint32_t)((wn*32 + f_rl) * 64);

    float acc[4][4][4] = {};

    ISSUE(0, 0);
    for (int kt = 0; kt < KT; kt++) {
        if (kt + 1 < KT) {
            ISSUE((kt + 1) & 1, kt + 1);
            asm volatile("cp.async.wait_group 1;\n");
        } else {
            asm volatile("cp.async.wait_group 0;\n");
        }
        __syncthreads();
        uint32_t sb = sbase + (kt & 1)*32768;
#pragma unroll
        for (int ks = 0; ks < 2; ks++) {
            uint32_t bh[4][2], bl[4][2], af[4][4];
#pragma unroll
            for (int nt = 0; nt < 2; nt++) {
                uint32_t r0, r1, r2, r3;
                ldsm4(r0, r1, r2, r3, sb + 16384 + bRow + nt*1024 + ck[ks]);
                bh[2*nt][0] = r0; bh[2*nt+1][0] = r1; bh[2*nt][1] = r2; bh[2*nt+1][1] = r3;
                ldsm4(r0, r1, r2, r3, sb + 24576 + bRow + nt*1024 + ck[ks]);
                bl[2*nt][0] = r0; bl[2*nt+1][0] = r1; bl[2*nt][1] = r2; bl[2*nt+1][1] = r3;
            }
#pragma unroll
            for (int mi = 0; mi < 4; mi++)
                ldsm4(af[mi][0], af[mi][1], af[mi][2], af[mi][3],
                      sb + aRow + mi*1024 + ck[ks]);
#pragma unroll
            for (int mi = 0; mi < 4; mi++)
#pragma unroll
                for (int ni = 0; ni < 4; ni++) {
                    mma16(acc[mi][ni], af[mi], bh[ni]);
                    mma16(acc[mi][ni], af[mi], bl[ni]);
                }
#pragma unroll
            for (int mi = 0; mi < 4; mi++)
                ldsm4(af[mi][0], af[mi][1], af[mi][2], af[mi][3],
                      sb + 8192 + aRow + mi*1024 + ck[ks]);
#pragma unroll
            for (int mi = 0; mi < 4; mi++)
#pragma unroll
                for (int ni = 0; ni < 4; ni++)
                    mma16(acc[mi][ni], af[mi], bh[ni]);
        }
        __syncthreads();
    }
#undef ISSUE

#pragma unroll
    for (int mi = 0; mi < 4; mi++) {
        int r = m0 + wm*64 + mi*16 + (lane >> 2);
#pragma unroll
        for (int ni = 0; ni < 4; ni++) {
            int cn = n0 + wn*32 + ni*8 + 2*(lane & 3);
            if (cn >= N) continue;
            float b0v = bias ? bias[cn]   : 0.f;
            float b1v = bias ? bias[cn+1] : 0.f;
            float v0 = acc[mi][ni][0] + b0v;
            float v1 = acc[mi][ni][1] + b1v;
            float v2 = acc[mi][ni][2] + b0v;
            float v3 = acc[mi][ni][3] + b1v;
            if (add) {
                v0 += add[(size_t)r*ldC + cn];     v1 += add[(size_t)r*ldC + cn + 1];
                v2 += add[(size_t)(r+8)*ldC + cn]; v3 += add[(size_t)(r+8)*ldC + cn + 1];
            }
            *(float2*)(C + (size_t)r*ldC + cn)     = make_float2(v0, v1);
            *(float2*)(C + (size_t)(r+8)*ldC + cn) = make_float2(v2, v3);
        }
    }
}

// ---------------- fused retention attention (ldmatrix + swizzled smem) ----------------
// tiles: 64 rows x 64 halves, 128B row stride, 16B-chunk XOR swizzle (chunk ^= row&7)
// byte offsets in dynamic smem:
#define AQH 0
#define AQL 8192
#define AKH 16384
#define AKL 24576
#define AVH 32768
#define AVL 40960
#define ASH 49152
#define ASL 57344
#define ARF 65536            // 64 floats
#define ACF (65536 + 256)    // 64 floats
#define ATT_SMEM (65536 + 512)

__device__ __forceinline__ uint32_t aswz(int row, int bytecol) {
    return (uint32_t)(row*128 + ((((bytecol >> 4) ^ (row & 7)) << 4) | (bytecol & 15)));
}

__global__ __launch_bounds__(256, 2)
void attn4(const float* __restrict__ qkvg, float* __restrict__ og)
{
    extern __shared__ char smc[];
    uint32_t sbase = smem_u32(smc);
    float* smf = (float*)smc;
    int tid = threadIdx.x, lane = tid & 31, wid = tid >> 5;
    int wm = wid >> 1, wn = wid & 1;
    int bh = blockIdx.y, b = bh >> 4, h = bh & 15;
    int s0 = ((blockIdx.x * 11) & 31) * 64;    // permuted for wave balance
    float lg = log2f(1.f - exp2f(-5.f - (float)h));
    const float* q = qkvg + h*HD;
    const float* k = qkvg + DM + h*HD;
    const float* v = qkvg + 2*DM + h*HD;

    int dist_max = (int)(40.0f / (-lg));
    int cc = s0 - 63 - dist_max;
    int t_start = (cc <= 0) ? 0 : ((cc + 63) & ~63);

    // store-phase indices: row fixed per warp, bytecol = lane*4 (conflict-free)
    int sr = 0, sc = 0; // computed per iteration from p

    // Q tile (scaled 1/8) -> AQH/AQL
#pragma unroll
    for (int i = 0; i < 8; i++) {
        int p = tid + 256*i;
        int r = p >> 5, bc = (p & 31) * 4;
        float2 t = *(const float2*)(q + (size_t)(b*SEQ + s0 + r)*QKVG_N + (bc >> 1));
        __half2 hi, lo;
        cvt2(t.x*0.125f, t.y*0.125f, hi, lo);
        uint32_t o = aswz(r, bc);
        *(__half2*)(smc + AQH + o) = hi;
        *(__half2*)(smc + AQL + o) = lo;
    }
    if (tid < 64) smf[(ARF>>2) + tid] = exp2f((float)(s0 + tid) * lg);

    float2 rK[8], rV[8];
#define LOADKV(t0_) do {                                                      \
        _Pragma("unroll")                                                     \
        for (int i_ = 0; i_ < 8; i_++) {                                      \
            int p_ = tid + 256*i_;                                            \
            int r_ = p_ >> 5, c2_ = (p_ & 31) * 2;                            \
            size_t base_ = (size_t)(b*SEQ + (t0_) + r_)*QKVG_N + c2_;         \
            rK[i_] = *(const float2*)(k + base_);                             \
            rV[i_] = *(const float2*)(v + base_);                             \
        }                                                                     \
    } while (0)

    LOADKV(t_start);

    // fragment address constants
    int l8 = lane & 7;
    int f_rl = ((lane >> 3) & 1)*8 + l8;
    int f_cs = lane >> 4;                    // 0/1
    uint32_t aRow = (uint32_t)((wm*16 + f_rl) * 128);

    float oacc[4][4] = {};
    for (int t0 = t_start; t0 <= s0; t0 += 64) {
        __syncthreads();
        // commit K/V registers -> smem (both row-major now)
#pragma unroll
        for (int i = 0; i < 8; i++) {
            int p = tid + 256*i;
            int r = p >> 5, bc = (p & 31) * 4;
            __half2 hi, lo;
            uint32_t o = aswz(r, bc);
            cvt2(rK[i].x, rK[i].y, hi, lo);
            *(__half2*)(smc + AKH + o) = hi;
            *(__half2*)(smc + AKL + o) = lo;
            cvt2(rV[i].x, rV[i].y, hi, lo);
            *(__half2*)(smc + AVH + o) = hi;
            *(__half2*)(smc + AVL + o) = lo;
        }
        if (tid < 64) smf[(ACF>>2) + tid] = exp2f(-(float)(t0 + tid) * lg);
        if (t0 + 64 <= s0) LOADKV(t0 + 64);
        __syncthreads();

        // S = Q @ K^T (m64 n64 k64) via ldmatrix
        float sacc[4][4] = {};
#pragma unroll
        for (int ks = 0; ks < 4; ks++) {
            uint32_t ca = (uint32_t)((((2*ks + f_cs) ^ l8) << 4));
            uint32_t ahi[4], alo[4], bhi[4][2], blo[4][2];
            ldsm4(ahi[0], ahi[1], ahi[2], ahi[3], sbase + AQH + aRow + ca);
            ldsm4(alo[0], alo[1], alo[2], alo[3], sbase + AQL + aRow + ca);
#pragma unroll
            for (int nt = 0; nt < 2; nt++) {
                uint32_t kRow = (uint32_t)((wn*32 + nt*16 + f_rl) * 128);
                uint32_t r0, r1, r2, r3;
                ldsm4(r0, r1, r2, r3, sbase + AKH + kRow + ca);
                bhi[2*nt][0] = r0; bhi[2*nt+1][0] = r1; bhi[2*nt][1] = r2; bhi[2*nt+1][1] = r3;
                ldsm4(r0, r1, r2, r3, sbase + AKL + kRow + ca);
                blo[2*nt][0] = r0; blo[2*nt+1][0] = r1; blo[2*nt][1] = r2; blo[2*nt+1][1] = r3;
            }
#pragma unroll
            for (int ni = 0; ni < 4; ni++) {
                mma16(sacc[ni], ahi, bhi[ni]);
                mma16(sacc[ni], ahi, blo[ni]);
                mma16(sacc[ni], alo, bhi[ni]);
            }
        }

        // decay * mask -> hi/lo into swizzled S tiles
        bool diag = (t0 == s0);
        int r0 = wm*16 + (lane >> 2);
        float rf0 = smf[(ARF>>2) + r0], rf1 = smf[(ARF>>2) + r0 + 8];
#pragma unroll
        for (int ni = 0; ni < 4; ni++) {
            int c0 = wn*32 + ni*8 + 2*(lane & 3);
            float cf0 = smf[(ACF>>2) + c0], cf1 = smf[(ACF>>2) + c0 + 1];
            float w00 = rf0*cf0, w01 = rf0*cf1, w10 = rf1*cf0, w11 = rf1*cf1;
            if (diag) {
                if (r0   < c0  ) w00 = 0.f;
                if (r0   < c0+1) w01 = 0.f;
                if (r0+8 < c0  ) w10 = 0.f;
                if (r0+8 < c0+1) w11 = 0.f;
            }
            __half2 hi, lo;
            uint32_t o0 = aswz(r0, c0*2), o1 = aswz(r0 + 8, c0*2);
            cvt2(sacc[ni][0]*w00, sacc[ni][1]*w01, hi, lo);
            *(__half2*)(smc + ASH + o0) = hi;
            *(__half2*)(smc + ASL + o0) = lo;
            cvt2(sacc[ni][2]*w10, sacc[ni][3]*w11, hi, lo);
            *(__half2*)(smc + ASH + o1) = hi;
            *(__half2*)(smc + ASL + o1) = lo;
        }
        __syncthreads();

        // O += S @ V (m64 n64 k64); V row-major, B frags via ldmatrix.trans
#pragma unroll
        for (int ks = 0; ks < 4; ks++) {
            uint32_t ca = (uint32_t)((((2*ks + f_cs) ^ l8) << 4));
            uint32_t ahi[4], alo[4], bhi[4][2], blo[4][2];
            ldsm4(ahi[0], ahi[1], ahi[2], ahi[3], sbase + ASH + aRow + ca);
            ldsm4(alo[0], alo[1], alo[2], alo[3], sbase + ASL + aRow + ca);
            uint32_t vRow = (uint32_t)((ks*16 + f_rl) * 128);
#pragma unroll
            for (int nt = 0; nt < 2; nt++) {
                uint32_t cv = (uint32_t)((((wn*4 + nt*2 + f_cs) ^ l8) << 4));
                uint32_t r0r, r1r, r2r, r3r;
                ldsm4t(r0r, r1r, r2r, r3r, sbase + AVH + vRow + cv);
                bhi[2*nt][0] = r0r; bhi[2*nt][1] = r1r; bhi[2*nt+1][0] = r2r; bhi[2*nt+1][1] = r3r;
                ldsm4t(r0r, r1r, r2r, r3r, sbase + AVL + vRow + cv);
                blo[2*nt][0] = r0r; blo[2*nt][1] = r1r; blo[2*nt+1][0] = r2r; blo[2*nt+1][1] = r3r;
            }
#pragma unroll
            for (int ni = 0; ni < 4; ni++) {
                mma16(oacc[ni], ahi, bhi[ni]);
                mma16(oacc[ni], ahi, blo[ni]);
                mma16(oacc[ni], alo, bhi[ni]);
            }
        }
    }
#undef LOADKV

    int r0 = wm*16 + (lane >> 2);
#pragma unroll
    for (int ni = 0; ni < 4; ni++) {
        int d0 = wn*32 + ni*8 + 2*(lane & 3);
        size_t i0 = ((size_t)(b*SEQ + s0 + r0)*NH + h)*HD + d0;
        size_t i1 = ((size_t)(b*SEQ + s0 + r0 + 8)*NH + h)*HD + d0;
        *(float2*)(og + i0) = make_float2(oacc[ni][0], oacc[ni][1]);
        *(float2*)(og + i1) = make_float2(oacc[ni][2], oacc[ni][3]);
    }
}

// ---------------- per-head groupnorm * silu(gate) -> hi/lo planes ----------------
__global__ void gn_gate_kernel(const float* __restrict__ at, const float* __restrict__ qkvg,
                               __half* __restrict__ ohi, __half* __restrict__ olo)
{
    int warp = threadIdx.x >> 5, lane = threadIdx.x & 31;
    int g = blockIdx.x * 8 + warp;
    int row = g >> 4, h = g & 15;
    size_t base = (size_t)g * 64;
    const float* gp = qkvg + (size_t)row*QKVG_N + 3*DM + h*64;
    float x0 = at[base + lane], x1 = at[base + 32 + lane];
    float s = x0 + x1, q = x0*x0 + x1*x1;
#pragma unroll
    for (int off = 16; off; off >>= 1) {
        s += __shfl_xor_sync(~0u, s, off);
        q += __shfl_xor_sync(~0u, q, off);
    }
    float mu = s * (1.f/64), var = q * (1.f/64) - mu*mu;
    float rs = rsqrtf(var + 1e-6f);
    float g0 = gp[lane], g1 = gp[32 + lane];
    g0 = g0 / (1.f + __expf(-g0));
    g1 = g1 / (1.f + __expf(-g1));
    float o0 = (x0 - mu) * rs * g0;
    float o1 = (x1 - mu) * rs * g1;
    __half h0 = __float2half_rn(o0), h1 = __float2half_rn(o1);
    ohi[base + lane]      = h0;
    olo[base + lane]      = __float2half_rn(o0 - __half2float(h0));
    ohi[base + 32 + lane] = h1;
    olo[base + 32 + lane] = __float2half_rn(o1 - __half2float(h1));
}

// ---------------- swiglu -> hi/lo planes (K-padded, zero fill) ----------------
__global__ void swiglu_kernel(const float* __restrict__ ab,
                              __half* __restrict__ ohi, __half* __restrict__ olo)
{
    size_t i = (size_t)blockIdx.x * 256 + threadIdx.x;
    int row = (int)(i / HIDP), col = (int)(i % HIDP);
    float r = 0.f;
    if (col < HID) {
        float a = ab[(size_t)row * NINP + col];
        float bb = ab[(size_t)row * NINP + HID + col];
        r = a * bb / (1.f + __expf(-bb));
    }
    __half h = __float2half_rn(r);
    ohi[i] = h;
    olo[i] = __float2half_rn(r - __half2float(h));
}

// ---------------- launch ----------------
extern "C" void kernel_launch(void* const* d_in, const int* in_sizes, int n_in,
                              void* d_out, int out_size)
{
    const float* x     = (const float*)d_in[0];
    const float* ln1w  = (const float*)d_in[1];
    const float* ln1b  = (const float*)d_in[2];
    const float* wq    = (const float*)d_in[3];
    const float* wk    = (const float*)d_in[4];
    const float* wv    = (const float*)d_in[5];
    const float* wg    = (const float*)d_in[6];
    const float* wo    = (const float*)d_in[7];
    const float* ln2w  = (const float*)d_in[8];
    const float* ln2b  = (const float*)d_in[9];
    const float* w_in  = (const float*)d_in[10];
    const float* b_in  = (const float*)d_in[11];
    const float* w_out = (const float*)d_in[12];
    const float* b_out = (const float*)d_in[13];
    float* out = (float*)d_out;

    float *qkvg, *atraw, *x1, *ab;
    __half *xn_h, *xn_l, *xn2_h, *xn2_l, *at_h, *at_l, *hb_h, *hb_l;
    __half *wqk_h, *wqk_l, *wo_h, *wo_l, *win_h, *win_l, *wout_h, *wout_l;
    cudaGetSymbolAddress((void**)&qkvg,  g_qkvg);
    cudaGetSymbolAddress((void**)&atraw, g_atraw);
    cudaGetSymbolAddress((void**)&x1,    g_x1);
    cudaGetSymbolAddress((void**)&ab,    g_ab);
    cudaGetSymbolAddress((void**)&xn_h,  g_xn_h);   cudaGetSymbolAddress((void**)&xn_l,  g_xn_l);
    cudaGetSymbolAddress((void**)&xn2_h, g_xn2_h);  cudaGetSymbolAddress((void**)&xn2_l, g_xn2_l);
    cudaGetSymbolAddress((void**)&at_h,  g_at_h);   cudaGetSymbolAddress((void**)&at_l,  g_at_l);
    cudaGetSymbolAddress((void**)&hb_h,  g_hb_h);   cudaGetSymbolAddress((void**)&hb_l,  g_hb_l);
    cudaGetSymbolAddress((void**)&wqk_h, g_wqkvg_h); cudaGetSymbolAddress((void**)&wqk_l, g_wqkvg_l);
    cudaGetSymbolAddress((void**)&wo_h,  g_wo_h);   cudaGetSymbolAddress((void**)&wo_l,  g_wo_l);
    cudaGetSymbolAddress((void**)&win_h, g_win_h);  cudaGetSymbolAddress((void**)&win_l, g_win_l);
    cudaGetSymbolAddress((void**)&wout_h, g_wout_h); cudaGetSymbolAddress((void**)&wout_l, g_wout_l);

    cudaFuncSetAttribute(gemm_p, cudaFuncAttributeMaxDynamicSharedMemorySize, GP_SMEM);
    cudaFuncSetAttribute(attn4, cudaFuncAttributeMaxDynamicSharedMemorySize, ATT_SMEM);

    // 1. merged weight transpose+split
    convw_all<<<13376, 256>>>(wq, wk, wv, wg, wo, w_in, w_out,
                              wqk_h, wqk_l, wo_h, wo_l, win_h, win_l, wout_h, wout_l);
    // 2. LN1 -> planes
    ln_kernel<<<ROWS, 256>>>(x, ln1w, ln1b, xn_h, xn_l);
    // 3. fused QKVG
    gemm_p<<<dim3(QKVG_N/128, ROWS/128), 256, GP_SMEM>>>(xn_h, xn_l, wqk_h, wqk_l,
        qkvg, QKVG_N, DM, QKVG_N, nullptr, nullptr);
    // 4. retention attention (ldmatrix version)
    attn4<<<dim3(SEQ/64, BATCH*NH), 256, ATT_SMEM>>>(qkvg, atraw);
    // 5. groupnorm + silu gate -> planes
    gn_gate_kernel<<<ROWS*NH/8, 256>>>(atraw, qkvg, at_h, at_l);
    // 6. output projection + residual
    gemm_p<<<dim3(DM/128, ROWS/128), 256, GP_SMEM>>>(at_h, at_l, wo_h, wo_l,
        x1, DM, DM, DM, nullptr, x);
    // 7. LN2 -> planes
    ln_kernel<<<ROWS, 256>>>(x1, ln2w, ln2b, xn2_h, xn2_l);
    // 8. FFN in
    gemm_p<<<dim3(NINP/128, ROWS/128), 256, GP_SMEM>>>(xn2_h, xn2_l, win_h, win_l,
        ab, NIN, DM, NINP, b_in, nullptr);
    // 9. swiglu -> planes
    swiglu_kernel<<<(int)(((size_t)ROWS*HIDP)/256), 256>>>(ab, hb_h, hb_l);
    // 10. FFN out + bias + residual
    gemm_p<<<dim3(DM/128, ROWS/128), 256, GP_SMEM>>>(hb_h, hb_l, wout_h, wout_l,
        out, DM, HIDP, DM, b_out, x1);
}

// round 8
// speedup vs baseline: 6.8728x; 1.2136x over previous
#include <cuda_runtime.h>
#include <cuda_fp16.h>
#include <cstdint>
#include <cstddef>

#define SEQ    2048
#define BATCH  2
#define NH     16
#define DM     1024
#define HD     64
#define HID    2730
#define HIDP   2752
#define NIN    5460
#define NINP   5504
#define ROWS   (BATCH*SEQ)
#define QKVG_N 4096

// ---------------- scratch (allocation-free device globals) ----------------
__device__ float  g_qkvg [(size_t)ROWS*QKVG_N];
__device__ float  g_atraw[ROWS*DM];
__device__ float  g_x1   [ROWS*DM];
__device__ float  g_ab   [(size_t)ROWS*NINP];
__device__ __half g_xn_h [ROWS*DM],  g_xn_l [ROWS*DM];
__device__ __half g_xn2_h[ROWS*DM],  g_xn2_l[ROWS*DM];
__device__ __half g_at_h [ROWS*DM],  g_at_l [ROWS*DM];
__device__ __half g_hb_h [(size_t)ROWS*HIDP], g_hb_l[(size_t)ROWS*HIDP];
__device__ __half g_wqkvg_h[(size_t)QKVG_N*DM], g_wqkvg_l[(size_t)QKVG_N*DM];
__device__ __half g_wo_h   [DM*DM],             g_wo_l   [DM*DM];
__device__ __half g_win_h  [(size_t)NINP*DM],   g_win_l  [(size_t)NINP*DM];
__device__ __half g_wout_h [(size_t)DM*HIDP],   g_wout_l [(size_t)DM*HIDP];

// ---------------- helpers ----------------
__device__ __forceinline__ void mma16(float* c, const uint32_t* a, const uint32_t* b) {
    asm volatile("mma.sync.aligned.m16n8k16.row.col.f32.f16.f16.f32 "
                 "{%0,%1,%2,%3},{%4,%5,%6,%7},{%8,%9},{%0,%1,%2,%3};\n"
                 : "+f"(c[0]), "+f"(c[1]), "+f"(c[2]), "+f"(c[3])
                 : "r"(a[0]), "r"(a[1]), "r"(a[2]), "r"(a[3]), "r"(b[0]), "r"(b[1]));
}
__device__ __forceinline__ void cvt2(float x, float y, __half2& hi, __half2& lo) {
    __half hx = __float2half_rn(x), hy = __float2half_rn(y);
    __half lx = __float2half_rn(x - __half2float(hx));
    __half ly = __float2half_rn(y - __half2float(hy));
    hi = __halves2half2(hx, hy);
    lo = __halves2half2(lx, ly);
}
__device__ __forceinline__ void cvt2u(float x, float y, uint32_t& hi, uint32_t& lo) {
    __half2 h, l;
    cvt2(x, y, h, l);
    hi = *(uint32_t*)&h;
    lo = *(uint32_t*)&l;
}
__device__ __forceinline__ uint32_t smem_u32(const void* p) {
    return (uint32_t)__cvta_generic_to_shared(p);
}
__device__ __forceinline__ void ldsm4(uint32_t& r0, uint32_t& r1, uint32_t& r2, uint32_t& r3,
                                      uint32_t addr) {
    asm volatile("ldmatrix.sync.aligned.m8n8.x4.shared.b16 {%0,%1,%2,%3},[%4];\n"
                 : "=r"(r0), "=r"(r1), "=r"(r2), "=r"(r3) : "r"(addr));
}
__device__ __forceinline__ void ldsm4t(uint32_t& r0, uint32_t& r1, uint32_t& r2, uint32_t& r3,
                                       uint32_t addr) {
    asm volatile("ldmatrix.sync.aligned.m8n8.x4.trans.shared.b16 {%0,%1,%2,%3},[%4];\n"
                 : "=r"(r0), "=r"(r1), "=r"(r2), "=r"(r3) : "r"(addr));
}
__device__ __forceinline__ void cpa16(uint32_t dst, const void* src) {
    asm volatile("cp.async.cg.shared.global [%0],[%1],16;\n" :: "r"(dst), "l"(src));
}

// ---------------- merged weight transpose + hi/lo split ----------------
__global__ void convw_all(const float* __restrict__ wq, const float* __restrict__ wk,
                          const float* __restrict__ wv, const float* __restrict__ wg,
                          const float* __restrict__ wo, const float* __restrict__ w_in,
                          const float* __restrict__ w_out,
                          __half* __restrict__ wqk_h, __half* __restrict__ wqk_l,
                          __half* __restrict__ wo_h,  __half* __restrict__ wo_l,
                          __half* __restrict__ win_h, __half* __restrict__ win_l,
                          __half* __restrict__ wout_h,__half* __restrict__ wout_l)
{
    __shared__ float t[32][33];
    int bt = blockIdx.x;
    const float* src; __half *hiT, *loT; int sK, sN, dK, n0, k0;
    if (bt < 4096) {
        int sub = bt >> 10, tt = bt & 1023;
        src = sub == 0 ? wq : sub == 1 ? wk : sub == 2 ? wv : wg;
        hiT = wqk_h + (size_t)sub*DM*DM; loT = wqk_l + (size_t)sub*DM*DM;
        sK = DM; sN = DM; dK = DM; n0 = (tt & 31)*32; k0 = (tt >> 5)*32;
    } else if (bt < 5120) {
        int tt = bt - 4096;
        src = wo; hiT = wo_h; loT = wo_l;
        sK = DM; sN = DM; dK = DM; n0 = (tt & 31)*32; k0 = (tt >> 5)*32;
    } else if (bt < 10624) {
        int tt = bt - 5120;
        src = w_in; hiT = win_h; loT = win_l;
        sK = DM; sN = NIN; dK = DM; n0 = (tt % 172)*32; k0 = (tt / 172)*32;
    } else {
        int tt = bt - 10624;
        src = w_out; hiT = wout_h; loT = wout_l;
        sK = HID; sN = DM; dK = HIDP; n0 = (tt & 31)*32; k0 = (tt >> 5)*32;
    }
    int tx = threadIdx.x & 31, ty = threadIdx.x >> 5;
#pragma unroll
    for (int i = 0; i < 4; i++) {
        int k = k0 + ty + 8*i;
        float v = (k < sK && (n0 + tx) < sN) ? src[(size_t)k * sN + n0 + tx] : 0.f;
        t[ty + 8*i][tx] = v;
    }
    __syncthreads();
#pragma unroll
    for (int i = 0; i < 4; i++) {
        int nl = ty + 8*i;
        float v = t[tx][nl];
        __half h = __float2half_rn(v);
        size_t o = (size_t)(n0 + nl) * dK + k0 + tx;
        hiT[o] = h;
        loT[o] = __float2half_rn(v - __half2float(h));
    }
}

// ---------------- LayerNorm -> hi/lo planes ----------------
__global__ void ln_kernel(const float* __restrict__ x, const float* __restrict__ w,
                          const float* __restrict__ b,
                          __half* __restrict__ ohi, __half* __restrict__ olo)
{
    __shared__ float red[2][8];
    int row = blockIdx.x, tid = threadIdx.x;
    const float* xr = x + (size_t)row * DM;
    float v[4], s = 0.f, q = 0.f;
#pragma unroll
    for (int i = 0; i < 4; i++) { v[i] = xr[tid + 256*i]; s += v[i]; q += v[i]*v[i]; }
#pragma unroll
    for (int off = 16; off; off >>= 1) {
        s += __shfl_xor_sync(~0u, s, off);
        q += __shfl_xor_sync(~0u, q, off);
    }
    if ((tid & 31) == 0) { red[0][tid>>5] = s; red[1][tid>>5] = q; }
    __syncthreads();
    if (tid < 32) {
        s = (tid < 8) ? red[0][tid] : 0.f;
        q = (tid < 8) ? red[1][tid] : 0.f;
#pragma unroll
        for (int off = 4; off; off >>= 1) {
            s += __shfl_xor_sync(~0u, s, off);
            q += __shfl_xor_sync(~0u, q, off);
        }
        if (tid == 0) { red[0][0] = s; red[1][0] = q; }
    }
    __syncthreads();
    s = red[0][0]; q = red[1][0];
    float mu = s * (1.f/DM);
    float rs = rsqrtf(q * (1.f/DM) - mu*mu + 1e-5f);
#pragma unroll
    for (int i = 0; i < 4; i++) {
        int c = tid + 256*i;
        float o = (v[i] - mu) * rs * w[c] + b[c];
        __half h = __float2half_rn(o);
        ohi[(size_t)row*DM + c] = h;
        olo[(size_t)row*DM + c] = __float2half_rn(o - __half2float(h));
    }
}

// ---------------- plane GEMM: C = A@B^T(+bias)(+add) ----------------
// comp=1: full 3-mma hi/lo compensation; comp=0: drop activation-lo (2-mma)
#define GP_SMEM 65536

__global__ __launch_bounds__(256, 2)
void gemm_p(const __half* __restrict__ Ahi, const __half* __restrict__ Alo,
            const __half* __restrict__ Bhi, const __half* __restrict__ Blo,
            float* __restrict__ C, int N, int K, int ldC, int comp,
            const float* __restrict__ bias, const float* __restrict__ add)
{
    extern __shared__ __half sh[];
    uint32_t sbase = smem_u32(sh);
    int tid = threadIdx.x, lane = tid & 31, wid = tid >> 5;
    int wm = wid >> 2, wn = wid & 3;
    int m0 = blockIdx.y * 128, n0 = blockIdx.x * 128;
    int KT = K >> 5;

    int cr = tid >> 2, cc = tid & 3;
    uint32_t dsto = (uint32_t)(cr*64 + ((cc ^ ((cr>>1)&3)) * 16));
    const __half* aS0 = Ahi + (size_t)(m0 + cr)*K + cc*8;
    const __half* aS1 = Alo + (size_t)(m0 + cr)*K + cc*8;
    const __half* bS0 = Bhi + (size_t)(n0 + cr)*K + cc*8;
    const __half* bS1 = Blo + (size_t)(n0 + cr)*K + cc*8;

#define ISSUE(st, kt) do {                                                   \
        uint32_t d_ = sbase + (st)*32768 + dsto;                             \
        int ko_ = (kt)*32;                                                   \
        cpa16(d_,               aS0 + ko_);                                  \
        cpa16(d_ + 4096,        aS0 + ko_ + (size_t)64*K);                   \
        if (comp) {                                                          \
            cpa16(d_ + 8192,        aS1 + ko_);                              \
            cpa16(d_ + 8192 + 4096, aS1 + ko_ + (size_t)64*K);               \
        }                                                                    \
        cpa16(d_ + 16384,        bS0 + ko_);                                 \
        cpa16(d_ + 16384 + 4096, bS0 + ko_ + (size_t)64*K);                  \
        cpa16(d_ + 24576,        bS1 + ko_);                                 \
        cpa16(d_ + 24576 + 4096, bS1 + ko_ + (size_t)64*K);                  \
        asm volatile("cp.async.commit_group;\n");                            \
    } while (0)

    int l8 = lane & 7, g = lane >> 3;
    int f_rl = (g & 1)*8 + l8;
    int f_cs = g >> 1;
    int f_swz = (f_rl >> 1) & 3;
    uint32_t ck[2] = { (uint32_t)(((0 + f_cs) ^ f_swz) * 16),
                       (uint32_t)(((2 + f_cs) ^ f_swz) * 16) };
    uint32_t aRow = (uint32_t)((wm*64 + f_rl) * 64);
    uint32_t bRow = (uint32_t)((wn*32 + f_rl) * 64);

    float acc[4][4][4] = {};

    ISSUE(0, 0);
    for (int kt = 0; kt < KT; kt++) {
        if (kt + 1 < KT) {
            ISSUE((kt + 1) & 1, kt + 1);
            asm volatile("cp.async.wait_group 1;\n");
        } else {
            asm volatile("cp.async.wait_group 0;\n");
        }
        __syncthreads();
        uint32_t sb = sbase + (kt & 1)*32768;
#pragma unroll
        for (int ks = 0; ks < 2; ks++) {
            uint32_t bh[4][2], bl[4][2], af[4][4];
#pragma unroll
            for (int nt = 0; nt < 2; nt++) {
                uint32_t r0, r1, r2, r3;
                ldsm4(r0, r1, r2, r3, sb + 16384 + bRow + nt*1024 + ck[ks]);
                bh[2*nt][0] = r0; bh[2*nt+1][0] = r1; bh[2*nt][1] = r2; bh[2*nt+1][1] = r3;
                ldsm4(r0, r1, r2, r3, sb + 24576 + bRow + nt*1024 + ck[ks]);
                bl[2*nt][0] = r0; bl[2*nt+1][0] = r1; bl[2*nt][1] = r2; bl[2*nt+1][1] = r3;
            }
#pragma unroll
            for (int mi = 0; mi < 4; mi++)
                ldsm4(af[mi][0], af[mi][1], af[mi][2], af[mi][3],
                      sb + aRow + mi*1024 + ck[ks]);
#pragma unroll
            for (int mi = 0; mi < 4; mi++)
#pragma unroll
                for (int ni = 0; ni < 4; ni++) {
                    mma16(acc[mi][ni], af[mi], bh[ni]);
                    mma16(acc[mi][ni], af[mi], bl[ni]);
                }
            if (comp) {
#pragma unroll
                for (int mi = 0; mi < 4; mi++)
                    ldsm4(af[mi][0], af[mi][1], af[mi][2], af[mi][3],
                          sb + 8192 + aRow + mi*1024 + ck[ks]);
#pragma unroll
                for (int mi = 0; mi < 4; mi++)
#pragma unroll
                    for (int ni = 0; ni < 4; ni++)
                        mma16(acc[mi][ni], af[mi], bh[ni]);
            }
        }
        __syncthreads();
    }
#undef ISSUE

#pragma unroll
    for (int mi = 0; mi < 4; mi++) {
        int r = m0 + wm*64 + mi*16 + (lane >> 2);
#pragma unroll
        for (int ni = 0; ni < 4; ni++) {
            int cn = n0 + wn*32 + ni*8 + 2*(lane & 3);
            if (cn >= N) continue;
            float b0v = bias ? bias[cn]   : 0.f;
            float b1v = bias ? bias[cn+1] : 0.f;
            float v0 = acc[mi][ni][0] + b0v;
            float v1 = acc[mi][ni][1] + b1v;
            float v2 = acc[mi][ni][2] + b0v;
            float v3 = acc[mi][ni][3] + b1v;
            if (add) {
                v0 += add[(size_t)r*ldC + cn];     v1 += add[(size_t)r*ldC + cn + 1];
                v2 += add[(size_t)(r+8)*ldC + cn]; v3 += add[(size_t)(r+8)*ldC + cn + 1];
            }
            *(float2*)(C + (size_t)r*ldC + cn)     = make_float2(v0, v1);
            *(float2*)(C + (size_t)(r+8)*ldC + cn) = make_float2(v2, v3);
        }
    }
}

// ---------------- retention attention v5: S stays in registers ----------------
// Q-block 128 rows; warp = m16 x n64; K/V single smem buffer (row-major, swizzled),
// register prefetch; S C-frags repacked directly as A-frags for S@V.
#define A5_KH 0
#define A5_KL 8192
#define A5_VH 16384
#define A5_VL 24576
#define A5_CF 32768
#define ATT5_SMEM (32768 + 256)

__device__ __forceinline__ uint32_t aswz(int row, int bytecol) {
    return (uint32_t)(row*128 + ((((bytecol >> 4) ^ (row & 7)) << 4) | (bytecol & 15)));
}

__global__ __launch_bounds__(256)
void attn5(const float* __restrict__ qkvg, float* __restrict__ og)
{
    extern __shared__ char smc[];
    uint32_t sbase = smem_u32(smc);
    float* cf = (float*)(smc + A5_CF);
    int tid = threadIdx.x, lane = tid & 31, w = tid >> 5;
    int bh = blockIdx.y, b = bh >> 4, h = bh & 15;
    int s0 = ((blockIdx.x * 7) & 15) * 128;
    float lg = log2f(1.f - exp2f(-5.f - (float)h));
    const float* q = qkvg + h*HD;
    const float* k = qkvg + DM + h*HD;
    const float* v = qkvg + 2*DM + h*HD;

    int dist_max = (int)(40.0f / (-lg));
    int cc0 = s0 - 63 - dist_max;
    int t_start = (cc0 <= 0) ? 0 : ((cc0 + 63) & ~63);
    int t_end = s0 + 64;

    int gq = lane >> 2, t4 = lane & 3;
    int r0 = w*16 + gq;                 // warp-local row within 128-block
    int r0g = s0 + r0, r1g = r0g + 8;
    float rowf0 = exp2f((float)r0g * lg);
    float rowf1 = exp2f((float)r1g * lg);

    // Q A-frags (hi/lo), scaled 1/8, loaded straight from gmem
    uint32_t qh[4][4], ql[4][4];
    {
        const float* qr0 = q + (size_t)(b*SEQ + r0g)*QKVG_N;
        const float* qr1 = qr0 + 8*(size_t)QKVG_N;
#pragma unroll
        for (int kc = 0; kc < 4; kc++) {
            int col = kc*16 + 2*t4;
            float2 x0 = *(const float2*)(qr0 + col);
            float2 x1 = *(const float2*)(qr1 + col);
            float2 x2 = *(const float2*)(qr0 + col + 8);
            float2 x3 = *(const float2*)(qr1 + col + 8);
            cvt2u(x0.x*0.125f, x0.y*0.125f, qh[kc][0], ql[kc][0]);
            cvt2u(x1.x*0.125f, x1.y*0.125f, qh[kc][1], ql[kc][1]);
            cvt2u(x2.x*0.125f, x2.y*0.125f, qh[kc][2], ql[kc][2]);
            cvt2u(x3.x*0.125f, x3.y*0.125f, qh[kc][3], ql[kc][3]);
        }
    }

    float2 rK[8], rV[8];
#define LOADKV(t0_) do {                                                      \
        _Pragma("unroll")                                                     \
        for (int i_ = 0; i_ < 8; i_++) {                                      \
            int p_ = tid + 256*i_;                                            \
            int r_ = p_ >> 5, c2_ = (p_ & 31) * 2;                            \
            size_t base_ = (size_t)(b*SEQ + (t0_) + r_)*QKVG_N + c2_;         \
            rK[i_] = *(const float2*)(k + base_);                             \
            rV[i_] = *(const float2*)(v + base_);                             \
        }                                                                     \
    } while (0)

    LOADKV(t_start);

    int l8 = lane & 7;
    int f_rl = ((lane >> 3) & 1)*8 + l8;
    int f_cs = lane >> 4;

    float oacc[8][4] = {};
    for (int t0 = t_start; t0 <= t_end; t0 += 64) {
        __syncthreads();   // prev compute done with smem
#pragma unroll
        for (int i = 0; i < 8; i++) {
            int p = tid + 256*i;
            int r = p >> 5, bc = (p & 31) * 4;
            uint32_t o = aswz(r, bc);
            __half2 hi, lo;
            cvt2(rK[i].x, rK[i].y, hi, lo);
            *(__half2*)(smc + A5_KH + o) = hi;
            *(__half2*)(smc + A5_KL + o) = lo;
            cvt2(rV[i].x, rV[i].y, hi, lo);
            *(__half2*)(smc + A5_VH + o) = hi;
            *(__half2*)(smc + A5_VL + o) = lo;
        }
        if (tid < 64) cf[tid] = exp2f(-(float)(t0 + tid) * lg);
        if (t0 + 64 <= t_end) LOADKV(t0 + 64);
        __syncthreads();

        if (t0 > s0 + w*16 + 15) continue;   // whole warp masked for this tile

        // ---- S = Q @ K^T  (m16 x n64 x k64 per warp) ----
        float sacc[8][4] = {};
#pragma unroll
        for (int ks = 0; ks < 4; ks++) {
            uint32_t ca = (uint32_t)(((2*ks + f_cs) ^ l8) << 4);
#pragma unroll
            for (int nb = 0; nb < 4; nb++) {
                uint32_t kRow = (uint32_t)((nb*16 + f_rl) * 128);
                uint32_t h0, h1, h2, h3, l0, l1, l2, l3;
                ldsm4(h0, h1, h2, h3, sbase + A5_KH + kRow + ca);
                ldsm4(l0, l1, l2, l3, sbase + A5_KL + kRow + ca);
                uint32_t bh0[2] = {h0, h2}, bh1[2] = {h1, h3};
                uint32_t bl0[2] = {l0, l2}, bl1[2] = {l1, l3};
                mma16(sacc[2*nb],   qh[ks], bh0);
                mma16(sacc[2*nb],   qh[ks], bl0);
                mma16(sacc[2*nb],   ql[ks], bh0);
                mma16(sacc[2*nb+1], qh[ks], bh1);
                mma16(sacc[2*nb+1], qh[ks], bl1);
                mma16(sacc[2*nb+1], ql[ks], bh1);
            }
        }

        // ---- decay * causal mask (in registers) ----
#pragma unroll
        for (int ni = 0; ni < 8; ni++) {
            int c0 = ni*8 + 2*t4;
            int c0g = t0 + c0, c1g = c0g + 1;
            float cf0 = cf[c0], cf1 = cf[c0 + 1];
            float w00 = (r0g >= c0g) ? rowf0*cf0 : 0.f;
            float w01 = (r0g >= c1g) ? rowf0*cf1 : 0.f;
            float w10 = (r1g >= c0g) ? rowf1*cf0 : 0.f;
            float w11 = (r1g >= c1g) ? rowf1*cf1 : 0.f;
            sacc[ni][0] *= w00; sacc[ni][1] *= w01;
            sacc[ni][2] *= w10; sacc[ni][3] *= w11;
        }

        // ---- repack S C-frags -> A-frags (hi/lo) for S@V ----
        uint32_t sh4[4][4], sl4[4][4];
#pragma unroll
        for (int t = 0; t < 4; t++) {
            cvt2u(sacc[2*t][0],   sacc[2*t][1],   sh4[t][0], sl4[t][0]);
            cvt2u(sacc[2*t][2],   sacc[2*t][3],   sh4[t][1], sl4[t][1]);
            cvt2u(sacc[2*t+1][0], sacc[2*t+1][1], sh4[t][2], sl4[t][2]);
            cvt2u(sacc[2*t+1][2], sacc[2*t+1][3], sh4[t][3], sl4[t][3]);
        }

        // ---- O += S @ V  (V row-major, trans-ldmatrix B frags) ----
#pragma unroll
        for (int ks = 0; ks < 4; ks++) {
            uint32_t vRow = (uint32_t)((ks*16 + f_rl) * 128);
#pragma unroll
            for (int nb = 0; nb < 4; nb++) {
                uint32_t cv = (uint32_t)(((nb*2 + f_cs) ^ l8) << 4);
                uint32_t h0, h1, h2, h3, l0, l1, l2, l3;
                ldsm4t(h0, h1, h2, h3, sbase + A5_VH + vRow + cv);
                ldsm4t(l0, l1, l2, l3, sbase + A5_VL + vRow + cv);
                uint32_t bh0[2] = {h0, h1}, bh1[2] = {h2, h3};
                uint32_t bl0[2] = {l0, l1}, bl1[2] = {l2, l3};
                mma16(oacc[2*nb],   sh4[ks], bh0);
                mma16(oacc[2*nb],   sh4[ks], bl0);
                mma16(oacc[2*nb],   sl4[ks], bh0);
                mma16(oacc[2*nb+1], sh4[ks], bh1);
                mma16(oacc[2*nb+1], sh4[ks], bl1);
                mma16(oacc[2*nb+1], sl4[ks], bh1);
            }
        }
    }
#undef LOADKV

#pragma unroll
    for (int ni = 0; ni < 8; ni++) {
        int d0 = ni*8 + 2*t4;
        size_t i0 = ((size_t)(b*SEQ + r0g)*NH + h)*HD + d0;
        size_t i1 = ((size_t)(b*SEQ + r1g)*NH + h)*HD + d0;
        *(float2*)(og + i0) = make_float2(oacc[ni][0], oacc[ni][1]);
        *(float2*)(og + i1) = make_float2(oacc[ni][2], oacc[ni][3]);
    }
}

// ---------------- per-head groupnorm * silu(gate) -> hi/lo planes ----------------
__global__ void gn_gate_kernel(const float* __restrict__ at, const float* __restrict__ qkvg,
                               __half* __restrict__ ohi, __half* __restrict__ olo)
{
    int warp = threadIdx.x >> 5, lane = threadIdx.x & 31;
    int g = blockIdx.x * 8 + warp;
    int row = g >> 4, h = g & 15;
    size_t base = (size_t)g * 64;
    const float* gp = qkvg + (size_t)row*QKVG_N + 3*DM + h*64;
    float x0 = at[base + lane], x1 = at[base + 32 + lane];
    float s = x0 + x1, q = x0*x0 + x1*x1;
#pragma unroll
    for (int off = 16; off; off >>= 1) {
        s += __shfl_xor_sync(~0u, s, off);
        q += __shfl_xor_sync(~0u, q, off);
    }
    float mu = s * (1.f/64), var = q * (1.f/64) - mu*mu;
    float rs = rsqrtf(var + 1e-6f);
    float g0 = gp[lane], g1 = gp[32 + lane];
    g0 = g0 / (1.f + __expf(-g0));
    g1 = g1 / (1.f + __expf(-g1));
    float o0 = (x0 - mu) * rs * g0;
    float o1 = (x1 - mu) * rs * g1;
    __half h0 = __float2half_rn(o0), h1 = __float2half_rn(o1);
    ohi[base + lane]      = h0;
    olo[base + lane]      = __float2half_rn(o0 - __half2float(h0));
    ohi[base + 32 + lane] = h1;
    olo[base + 32 + lane] = __float2half_rn(o1 - __half2float(h1));
}

// ---------------- swiglu -> hi/lo planes (K-padded, zero fill) ----------------
__global__ void swiglu_kernel(const float* __restrict__ ab,
                              __half* __restrict__ ohi, __half* __restrict__ olo)
{
    size_t i = (size_t)blockIdx.x * 256 + threadIdx.x;
    int row = (int)(i / HIDP), col = (int)(i % HIDP);
    float r = 0.f;
    if (col < HID) {
        float a = ab[(size_t)row * NINP + col];
        float bb = ab[(size_t)row * NINP + HID + col];
        r = a * bb / (1.f + __expf(-bb));
    }
    __half h = __float2half_rn(r);
    ohi[i] = h;
    olo[i] = __float2half_rn(r - __half2float(h));
}

// ---------------- launch ----------------
extern "C" void kernel_launch(void* const* d_in, const int* in_sizes, int n_in,
                              void* d_out, int out_size)
{
    const float* x     = (const float*)d_in[0];
    const float* ln1w  = (const float*)d_in[1];
    const float* ln1b  = (const float*)d_in[2];
    const float* wq    = (const float*)d_in[3];
    const float* wk    = (const float*)d_in[4];
    const float* wv    = (const float*)d_in[5];
    const float* wg    = (const float*)d_in[6];
    const float* wo    = (const float*)d_in[7];
    const float* ln2w  = (const float*)d_in[8];
    const float* ln2b  = (const float*)d_in[9];
    const float* w_in  = (const float*)d_in[10];
    const float* b_in  = (const float*)d_in[11];
    const float* w_out = (const float*)d_in[12];
    const float* b_out = (const float*)d_in[13];
    float* out = (float*)d_out;

    float *qkvg, *atraw, *x1, *ab;
    __half *xn_h, *xn_l, *xn2_h, *xn2_l, *at_h, *at_l, *hb_h, *hb_l;
    __half *wqk_h, *wqk_l, *wo_h, *wo_l, *win_h, *win_l, *wout_h, *wout_l;
    cudaGetSymbolAddress((void**)&qkvg,  g_qkvg);
    cudaGetSymbolAddress((void**)&atraw, g_atraw);
    cudaGetSymbolAddress((void**)&x1,    g_x1);
    cudaGetSymbolAddress((void**)&ab,    g_ab);
    cudaGetSymbolAddress((void**)&xn_h,  g_xn_h);   cudaGetSymbolAddress((void**)&xn_l,  g_xn_l);
    cudaGetSymbolAddress((void**)&xn2_h, g_xn2_h);  cudaGetSymbolAddress((void**)&xn2_l, g_xn2_l);
    cudaGetSymbolAddress((void**)&at_h,  g_at_h);   cudaGetSymbolAddress((void**)&at_l,  g_at_l);
    cudaGetSymbolAddress((void**)&hb_h,  g_hb_h);   cudaGetSymbolAddress((void**)&hb_l,  g_hb_l);
    cudaGetSymbolAddress((void**)&wqk_h, g_wqkvg_h); cudaGetSymbolAddress((void**)&wqk_l, g_wqkvg_l);
    cudaGetSymbolAddress((void**)&wo_h,  g_wo_h);   cudaGetSymbolAddress((void**)&wo_l,  g_wo_l);
    cudaGetSymbolAddress((void**)&win_h, g_win_h);  cudaGetSymbolAddress((void**)&win_l, g_win_l);
    cudaGetSymbolAddress((void**)&wout_h, g_wout_h); cudaGetSymbolAddress((void**)&wout_l, g_wout_l);

    cudaFuncSetAttribute(gemm_p, cudaFuncAttributeMaxDynamicSharedMemorySize, GP_SMEM);
    cudaFuncSetAttribute(attn5, cudaFuncAttributeMaxDynamicSharedMemorySize, ATT5_SMEM);

    // 1. merged weight transpose+split
    convw_all<<<13376, 256>>>(wq, wk, wv, wg, wo, w_in, w_out,
                              wqk_h, wqk_l, wo_h, wo_l, win_h, win_l, wout_h, wout_l);
    // 2. LN1 -> planes
    ln_kernel<<<ROWS, 256>>>(x, ln1w, ln1b, xn_h, xn_l);
    // 3. fused QKVG (full compensation)
    gemm_p<<<dim3(QKVG_N/128, ROWS/128), 256, GP_SMEM>>>(xn_h, xn_l, wqk_h, wqk_l,
        qkvg, QKVG_N, DM, QKVG_N, 1, nullptr, nullptr);
    // 4. retention attention (register-S)
    attn5<<<dim3(SEQ/128, BATCH*NH), 256, ATT5_SMEM>>>(qkvg, atraw);
    // 5. groupnorm + silu gate -> planes
    gn_gate_kernel<<<ROWS*NH/8, 256>>>(atraw, qkvg, at_h, at_l);
    // 6. output projection + residual (full compensation)
    gemm_p<<<dim3(DM/128, ROWS/128), 256, GP_SMEM>>>(at_h, at_l, wo_h, wo_l,
        x1, DM, DM, DM, 1, nullptr, x);
    // 7. LN2 -> planes
    ln_kernel<<<ROWS, 256>>>(x1, ln2w, ln2b, xn2_h, xn2_l);
    // 8. FFN in (2-mma: activation-lo dropped)
    gemm_p<<<dim3(NINP/128, ROWS/128), 256, GP_SMEM>>>(xn2_h, xn2_l, win_h, win_l,
        ab, NIN, DM, NINP, 0, b_in, nullptr);
    // 9. swiglu -> planes
    swiglu_kernel<<<(int)(((size_t)ROWS*HIDP)/256), 256>>>(ab, hb_h, hb_l);
    // 10. FFN out + bias + residual (2-mma)
    gemm_p<<<dim3(DM/128, ROWS/128), 256, GP_SMEM>>>(hb_h, hb_l, wout_h, wout_l,
        out, DM, HIDP, DM, 0, b_out, x1);
}

// round 9
// speedup vs baseline: 7.8676x; 1.1448x over previous
#include <cuda_runtime.h>
#include <cuda_fp16.h>
#include <cstdint>
#include <cstddef>

#define SEQ    2048
#define NH     16
#define DM     1024
#define HD     64
#define HID    2730
#define HIDP   2752
#define NIN    5460
#define NINP   5504
#define ROWS   4096
#define QKVG_N 4096

// ---------------- scratch (allocation-free device globals) ----------------
__device__ float  g_qkvg [(size_t)ROWS*QKVG_N];
__device__ float  g_atraw[ROWS*DM];
__device__ float  g_x1   [ROWS*DM];
__device__ float  g_ab   [(size_t)ROWS*NINP];
__device__ __half g_xn_h [ROWS*DM],  g_xn_l [ROWS*DM];
__device__ __half g_xn2_h[ROWS*DM],  g_xn2_l[ROWS*DM];
__device__ __half g_at_h [ROWS*DM],  g_at_l [ROWS*DM];
__device__ __half g_hb_h [(size_t)ROWS*HIDP], g_hb_l[(size_t)ROWS*HIDP];
__device__ __half g_wqkvg_h[(size_t)QKVG_N*DM], g_wqkvg_l[(size_t)QKVG_N*DM];
__device__ __half g_wo_h   [DM*DM],             g_wo_l   [DM*DM];
__device__ __half g_win_h  [(size_t)NINP*DM],   g_win_l  [(size_t)NINP*DM];
__device__ __half g_wout_h [(size_t)DM*HIDP],   g_wout_l [(size_t)DM*HIDP];

// ---------------- helpers ----------------
__device__ __forceinline__ void mma16(float* c, const uint32_t* a, const uint32_t* b) {
    asm volatile("mma.sync.aligned.m16n8k16.row.col.f32.f16.f16.f32 "
                 "{%0,%1,%2,%3},{%4,%5,%6,%7},{%8,%9},{%0,%1,%2,%3};\n"
                 : "+f"(c[0]), "+f"(c[1]), "+f"(c[2]), "+f"(c[3])
                 : "r"(a[0]), "r"(a[1]), "r"(a[2]), "r"(a[3]), "r"(b[0]), "r"(b[1]));
}
__device__ __forceinline__ void cvt2(float x, float y, __half2& hi, __half2& lo) {
    __half hx = __float2half_rn(x), hy = __float2half_rn(y);
    __half lx = __float2half_rn(x - __half2float(hx));
    __half ly = __float2half_rn(y - __half2float(hy));
    hi = __halves2half2(hx, hy);
    lo = __halves2half2(lx, ly);
}
__device__ __forceinline__ void cvt2u(float x, float y, uint32_t& hi, uint32_t& lo) {
    __half2 h, l;
    cvt2(x, y, h, l);
    hi = *(uint32_t*)&h;
    lo = *(uint32_t*)&l;
}
__device__ __forceinline__ uint32_t smem_u32(const void* p) {
    return (uint32_t)__cvta_generic_to_shared(p);
}
__device__ __forceinline__ void ldsm4(uint32_t& r0, uint32_t& r1, uint32_t& r2, uint32_t& r3,
                                      uint32_t addr) {
    asm volatile("ldmatrix.sync.aligned.m8n8.x4.shared.b16 {%0,%1,%2,%3},[%4];\n"
                 : "=r"(r0), "=r"(r1), "=r"(r2), "=r"(r3) : "r"(addr));
}
__device__ __forceinline__ void ldsm4t(uint32_t& r0, uint32_t& r1, uint32_t& r2, uint32_t& r3,
                                       uint32_t addr) {
    asm volatile("ldmatrix.sync.aligned.m8n8.x4.trans.shared.b16 {%0,%1,%2,%3},[%4];\n"
                 : "=r"(r0), "=r"(r1), "=r"(r2), "=r"(r3) : "r"(addr));
}
__device__ __forceinline__ void cpa16(uint32_t dst, const void* src) {
    asm volatile("cp.async.cg.shared.global [%0],[%1],16;\n" :: "r"(dst), "l"(src));
}

// ---------------- merged weight transpose + hi/lo split ----------------
__global__ void convw_all(const float* __restrict__ wq, const float* __restrict__ wk,
                          const float* __restrict__ wv, const float* __restrict__ wg,
                          const float* __restrict__ wo, const float* __restrict__ w_in,
                          const float* __restrict__ w_out,
                          __half* __restrict__ wqk_h, __half* __restrict__ wqk_l,
                          __half* __restrict__ wo_h,  __half* __restrict__ wo_l,
                          __half* __restrict__ win_h, __half* __restrict__ win_l,
                          __half* __restrict__ wout_h,__half* __restrict__ wout_l)
{
    __shared__ float t[32][33];
    int bt = blockIdx.x;
    const float* src; __half *hiT, *loT; int sK, sN, dK, n0, k0;
    bool do_lo = (bt < 5120);    // FFN weights used pure-fp16: no lo plane needed
    if (bt < 4096) {
        int sub = bt >> 10, tt = bt & 1023;
        src = sub == 0 ? wq : sub == 1 ? wk : sub == 2 ? wv : wg;
        hiT = wqk_h + (size_t)sub*DM*DM; loT = wqk_l + (size_t)sub*DM*DM;
        sK = DM; sN = DM; dK = DM; n0 = (tt & 31)*32; k0 = (tt >> 5)*32;
    } else if (bt < 5120) {
        int tt = bt - 4096;
        src = wo; hiT = wo_h; loT = wo_l;
        sK = DM; sN = DM; dK = DM; n0 = (tt & 31)*32; k0 = (tt >> 5)*32;
    } else if (bt < 10624) {
        int tt = bt - 5120;
        src = w_in; hiT = win_h; loT = win_l;
        sK = DM; sN = NIN; dK = DM; n0 = (tt % 172)*32; k0 = (tt / 172)*32;
    } else {
        int tt = bt - 10624;
        src = w_out; hiT = wout_h; loT = wout_l;
        sK = HID; sN = DM; dK = HIDP; n0 = (tt & 31)*32; k0 = (tt >> 5)*32;
    }
    int tx = threadIdx.x & 31, ty = threadIdx.x >> 5;
#pragma unroll
    for (int i = 0; i < 4; i++) {
        int k = k0 + ty + 8*i;
        float v = (k < sK && (n0 + tx) < sN) ? src[(size_t)k * sN + n0 + tx] : 0.f;
        t[ty + 8*i][tx] = v;
    }
    __syncthreads();
#pragma unroll
    for (int i = 0; i < 4; i++) {
        int nl = ty + 8*i;
        float v = t[tx][nl];
        __half h = __float2half_rn(v);
        size_t o = (size_t)(n0 + nl) * dK + k0 + tx;
        hiT[o] = h;
        if (do_lo) loT[o] = __float2half_rn(v - __half2float(h));
    }
}

// ---------------- LayerNorm -> hi/lo planes ----------------
__global__ void ln_kernel(const float* __restrict__ x, const float* __restrict__ w,
                          const float* __restrict__ b,
                          __half* __restrict__ ohi, __half* __restrict__ olo)
{
    __shared__ float red[2][8];
    int row = blockIdx.x, tid = threadIdx.x;
    const float* xr = x + (size_t)row * DM;
    float v[4], s = 0.f, q = 0.f;
#pragma unroll
    for (int i = 0; i < 4; i++) { v[i] = xr[tid + 256*i]; s += v[i]; q += v[i]*v[i]; }
#pragma unroll
    for (int off = 16; off; off >>= 1) {
        s += __shfl_xor_sync(~0u, s, off);
        q += __shfl_xor_sync(~0u, q, off);
    }
    if ((tid & 31) == 0) { red[0][tid>>5] = s; red[1][tid>>5] = q; }
    __syncthreads();
    if (tid < 32) {
        s = (tid < 8) ? red[0][tid] : 0.f;
        q = (tid < 8) ? red[1][tid] : 0.f;
#pragma unroll
        for (int off = 4; off; off >>= 1) {
            s += __shfl_xor_sync(~0u, s, off);
            q += __shfl_xor_sync(~0u, q, off);
        }
        if (tid == 0) { red[0][0] = s; red[1][0] = q; }
    }
    __syncthreads();
    s = red[0][0]; q = red[1][0];
    float mu = s * (1.f/DM);
    float rs = rsqrtf(q * (1.f/DM) - mu*mu + 1e-5f);
#pragma unroll
    for (int i = 0; i < 4; i++) {
        int c = tid + 256*i;
        float o = (v[i] - mu) * rs * w[c] + b[c];
        __half h = __float2half_rn(o);
        ohi[(size_t)row*DM + c] = h;
        olo[(size_t)row*DM + c] = __float2half_rn(o - __half2float(h));
    }
}

// ---------------- plane GEMM: C = A@B^T(+bias)(+add) ----------------
// comp=2: A-hi*(B-hi+B-lo) + A-lo*B-hi (3 mma)
// comp=1: A-hi*(B-hi+B-lo)             (2 mma, act-lo dropped)
// comp=0: A-hi*B-hi                    (1 mma, pure fp16)
#define GP_SMEM 65536

__global__ __launch_bounds__(256, 2)
void gemm_p(const __half* __restrict__ Ahi, const __half* __restrict__ Alo,
            const __half* __restrict__ Bhi, const __half* __restrict__ Blo,
            float* __restrict__ C, int N, int K, int ldC, int comp,
            const float* __restrict__ bias, const float* __restrict__ add)
{
    extern __shared__ __half sh[];
    uint32_t sbase = smem_u32(sh);
    int tid = threadIdx.x, lane = tid & 31, wid = tid >> 5;
    int wm = wid >> 2, wn = wid & 3;
    int m0 = blockIdx.y * 128, n0 = blockIdx.x * 128;
    int KT = K >> 5;

    int cr = tid >> 2, cc = tid & 3;
    uint32_t dsto = (uint32_t)(cr*64 + ((cc ^ ((cr>>1)&3)) * 16));
    const __half* aS0 = Ahi + (size_t)(m0 + cr)*K + cc*8;
    const __half* aS1 = Alo + (size_t)(m0 + cr)*K + cc*8;
    const __half* bS0 = Bhi + (size_t)(n0 + cr)*K + cc*8;
    const __half* bS1 = Blo + (size_t)(n0 + cr)*K + cc*8;

#define ISSUE(st, kt) do {                                                   \
        uint32_t d_ = sbase + (st)*32768 + dsto;                             \
        int ko_ = (kt)*32;                                                   \
        cpa16(d_,               aS0 + ko_);                                  \
        cpa16(d_ + 4096,        aS0 + ko_ + (size_t)64*K);                   \
        if (comp >= 2) {                                                     \
            cpa16(d_ + 8192,        aS1 + ko_);                              \
            cpa16(d_ + 8192 + 4096, aS1 + ko_ + (size_t)64*K);               \
        }                                                                    \
        cpa16(d_ + 16384,        bS0 + ko_);                                 \
        cpa16(d_ + 16384 + 4096, bS0 + ko_ + (size_t)64*K);                  \
        if (comp >= 1) {                                                     \
            cpa16(d_ + 24576,        bS1 + ko_);                             \
            cpa16(d_ + 24576 + 4096, bS1 + ko_ + (size_t)64*K);              \
        }                                                                    \
        asm volatile("cp.async.commit_group;\n");                            \
    } while (0)

    int l8 = lane & 7, g = lane >> 3;
    int f_rl = (g & 1)*8 + l8;
    int f_cs = g >> 1;
    int f_swz = (f_rl >> 1) & 3;
    uint32_t ck[2] = { (uint32_t)(((0 + f_cs) ^ f_swz) * 16),
                       (uint32_t)(((2 + f_cs) ^ f_swz) * 16) };
    uint32_t aRow = (uint32_t)((wm*64 + f_rl) * 64);
    uint32_t bRow = (uint32_t)((wn*32 + f_rl) * 64);

    float acc[4][4][4] = {};

    ISSUE(0, 0);
    for (int kt = 0; kt < KT; kt++) {
        if (kt + 1 < KT) {
            ISSUE((kt + 1) & 1, kt + 1);
            asm volatile("cp.async.wait_group 1;\n");
        } else {
            asm volatile("cp.async.wait_group 0;\n");
        }
        __syncthreads();
        uint32_t sb = sbase + (kt & 1)*32768;
#pragma unroll
        for (int ks = 0; ks < 2; ks++) {
            uint32_t bh[4][2], bl[4][2], af[4][4];
#pragma unroll
            for (int nt = 0; nt < 2; nt++) {
                uint32_t r0, r1, r2, r3;
                ldsm4(r0, r1, r2, r3, sb + 16384 + bRow + nt*1024 + ck[ks]);
                bh[2*nt][0] = r0; bh[2*nt+1][0] = r1; bh[2*nt][1] = r2; bh[2*nt+1][1] = r3;
                if (comp >= 1) {
                    ldsm4(r0, r1, r2, r3, sb + 24576 + bRow + nt*1024 + ck[ks]);
                    bl[2*nt][0] = r0; bl[2*nt+1][0] = r1; bl[2*nt][1] = r2; bl[2*nt+1][1] = r3;
                }
            }
#pragma unroll
            for (int mi = 0; mi < 4; mi++)
                ldsm4(af[mi][0], af[mi][1], af[mi][2], af[mi][3],
                      sb + aRow + mi*1024 + ck[ks]);
#pragma unroll
            for (int mi = 0; mi < 4; mi++)
#pragma unroll
                for (int ni = 0; ni < 4; ni++) {
                    mma16(acc[mi][ni], af[mi], bh[ni]);
                    if (comp >= 1) mma16(acc[mi][ni], af[mi], bl[ni]);
                }
            if (comp >= 2) {
#pragma unroll
                for (int mi = 0; mi < 4; mi++)
                    ldsm4(af[mi][0], af[mi][1], af[mi][2], af[mi][3],
                          sb + 8192 + aRow + mi*1024 + ck[ks]);
#pragma unroll
                for (int mi = 0; mi < 4; mi++)
#pragma unroll
                    for (int ni = 0; ni < 4; ni++)
                        mma16(acc[mi][ni], af[mi], bh[ni]);
            }
        }
        __syncthreads();
    }
#undef ISSUE

#pragma unroll
    for (int mi = 0; mi < 4; mi++) {
        int r = m0 + wm*64 + mi*16 + (lane >> 2);
#pragma unroll
        for (int ni = 0; ni < 4; ni++) {
            int cn = n0 + wn*32 + ni*8 + 2*(lane & 3);
            if (cn >= N) continue;
            float b0v = bias ? bias[cn]   : 0.f;
            float b1v = bias ? bias[cn+1] : 0.f;
            float v0 = acc[mi][ni][0] + b0v;
            float v1 = acc[mi][ni][1] + b1v;
            float v2 = acc[mi][ni][2] + b0v;
            float v3 = acc[mi][ni][3] + b1v;
            if (add) {
                v0 += add[(size_t)r*ldC + cn];     v1 += add[(size_t)r*ldC + cn + 1];
                v2 += add[(size_t)(r+8)*ldC + cn]; v3 += add[(size_t)(r+8)*ldC + cn + 1];
            }
            *(float2*)(C + (size_t)r*ldC + cn)     = make_float2(v0, v1);
            *(float2*)(C + (size_t)(r+8)*ldC + cn) = make_float2(v2, v3);
        }
    }
}

// ---------------- retention attention v5 (unchanged, validated) ----------------
#define A5_KH 0
#define A5_KL 8192
#define A5_VH 16384
#define A5_VL 24576
#define A5_CF 32768
#define ATT5_SMEM (32768 + 256)

__device__ __forceinline__ uint32_t aswz(int row, int bytecol) {
    return (uint32_t)(row*128 + ((((bytecol >> 4) ^ (row & 7)) << 4) | (bytecol & 15)));
}

__global__ __launch_bounds__(256)
void attn5(const float* __restrict__ qkvg, float* __restrict__ og)
{
    extern __shared__ char smc[];
    uint32_t sbase = smem_u32(smc);
    float* cf = (float*)(smc + A5_CF);
    int tid = threadIdx.x, lane = tid & 31, w = tid >> 5;
    int bh = blockIdx.y, b = bh >> 4, h = bh & 15;
    int s0 = ((blockIdx.x * 7) & 15) * 128;
    float lg = log2f(1.f - exp2f(-5.f - (float)h));
    const float* q = qkvg + h*HD;
    const float* k = qkvg + DM + h*HD;
    const float* v = qkvg + 2*DM + h*HD;

    int dist_max = (int)(40.0f / (-lg));
    int cc0 = s0 - 63 - dist_max;
    int t_start = (cc0 <= 0) ? 0 : ((cc0 + 63) & ~63);
    int t_end = s0 + 64;

    int gq = lane >> 2, t4 = lane & 3;
    int r0 = w*16 + gq;
    int r0g = s0 + r0, r1g = r0g + 8;
    float rowf0 = exp2f((float)r0g * lg);
    float rowf1 = exp2f((float)r1g * lg);

    uint32_t qh[4][4], ql[4][4];
    {
        const float* qr0 = q + (size_t)(b*SEQ + r0g)*QKVG_N;
        const float* qr1 = qr0 + 8*(size_t)QKVG_N;
#pragma unroll
        for (int kc = 0; kc < 4; kc++) {
            int col = kc*16 + 2*t4;
            float2 x0 = *(const float2*)(qr0 + col);
            float2 x1 = *(const float2*)(qr1 + col);
            float2 x2 = *(const float2*)(qr0 + col + 8);
            float2 x3 = *(const float2*)(qr1 + col + 8);
            cvt2u(x0.x*0.125f, x0.y*0.125f, qh[kc][0], ql[kc][0]);
            cvt2u(x1.x*0.125f, x1.y*0.125f, qh[kc][1], ql[kc][1]);
            cvt2u(x2.x*0.125f, x2.y*0.125f, qh[kc][2], ql[kc][2]);
            cvt2u(x3.x*0.125f, x3.y*0.125f, qh[kc][3], ql[kc][3]);
        }
    }

    float2 rK[8], rV[8];
#define LOADKV(t0_) do {                                                      \
        _Pragma("unroll")                                                     \
        for (int i_ = 0; i_ < 8; i_++) {                                      \
            int p_ = tid + 256*i_;                                            \
            int r_ = p_ >> 5, c2_ = (p_ & 31) * 2;                            \
            size_t base_ = (size_t)(b*SEQ + (t0_) + r_)*QKVG_N + c2_;         \
            rK[i_] = *(const float2*)(k + base_);                             \
            rV[i_] = *(const float2*)(v + base_);                             \
        }                                                                     \
    } while (0)

    LOADKV(t_start);

    int l8 = lane & 7;
    int f_rl = ((lane >> 3) & 1)*8 + l8;
    int f_cs = lane >> 4;

    float oacc[8][4] = {};
    for (int t0 = t_start; t0 <= t_end; t0 += 64) {
        __syncthreads();
#pragma unroll
        for (int i = 0; i < 8; i++) {
            int p = tid + 256*i;
            int r = p >> 5, bc = (p & 31) * 4;
            uint32_t o = aswz(r, bc);
            __half2 hi, lo;
            cvt2(rK[i].x, rK[i].y, hi, lo);
            *(__half2*)(smc + A5_KH + o) = hi;
            *(__half2*)(smc + A5_KL + o) = lo;
            cvt2(rV[i].x, rV[i].y, hi, lo);
            *(__half2*)(smc + A5_VH + o) = hi;
            *(__half2*)(smc + A5_VL + o) = lo;
        }
        if (tid < 64) cf[tid] = exp2f(-(float)(t0 + tid) * lg);
        if (t0 + 64 <= t_end) LOADKV(t0 + 64);
        __syncthreads();

        if (t0 > s0 + w*16 + 15) continue;

        float sacc[8][4] = {};
#pragma unroll
        for (int ks = 0; ks < 4; ks++) {
            uint32_t ca = (uint32_t)(((2*ks + f_cs) ^ l8) << 4);
#pragma unroll
            for (int nb = 0; nb < 4; nb++) {
                uint32_t kRow = (uint32_t)((nb*16 + f_rl) * 128);
                uint32_t h0, h1, h2, h3, l0, l1, l2, l3;
                ldsm4(h0, h1, h2, h3, sbase + A5_KH + kRow + ca);
                ldsm4(l0, l1, l2, l3, sbase + A5_KL + kRow + ca);
                uint32_t bh0[2] = {h0, h2}, bh1[2] = {h1, h3};
                uint32_t bl0[2] = {l0, l2}, bl1[2] = {l1, l3};
                mma16(sacc[2*nb],   qh[ks], bh0);
                mma16(sacc[2*nb],   qh[ks], bl0);
                mma16(sacc[2*nb],   ql[ks], bh0);
                mma16(sacc[2*nb+1], qh[ks], bh1);
                mma16(sacc[2*nb+1], qh[ks], bl1);
                mma16(sacc[2*nb+1], ql[ks], bh1);
            }
        }

#pragma unroll
        for (int ni = 0; ni < 8; ni++) {
            int c0 = ni*8 + 2*t4;
            int c0g = t0 + c0, c1g = c0g + 1;
            float cf0 = cf[c0], cf1 = cf[c0 + 1];
            float w00 = (r0g >= c0g) ? rowf0*cf0 : 0.f;
            float w01 = (r0g >= c1g) ? rowf0*cf1 : 0.f;
            float w10 = (r1g >= c0g) ? rowf1*cf0 : 0.f;
            float w11 = (r1g >= c1g) ? rowf1*cf1 : 0.f;
            sacc[ni][0] *= w00; sacc[ni][1] *= w01;
            sacc[ni][2] *= w10; sacc[ni][3] *= w11;
        }

        uint32_t sh4[4][4], sl4[4][4];
#pragma unroll
        for (int t = 0; t < 4; t++) {
            cvt2u(sacc[2*t][0],   sacc[2*t][1],   sh4[t][0], sl4[t][0]);
            cvt2u(sacc[2*t][2],   sacc[2*t][3],   sh4[t][1], sl4[t][1]);
            cvt2u(sacc[2*t+1][0], sacc[2*t+1][1], sh4[t][2], sl4[t][2]);
            cvt2u(sacc[2*t+1][2], sacc[2*t+1][3], sh4[t][3], sl4[t][3]);
        }

#pragma unroll
        for (int ks = 0; ks < 4; ks++) {
            uint32_t vRow = (uint32_t)((ks*16 + f_rl) * 128);
#pragma unroll
            for (int nb = 0; nb < 4; nb++) {
                uint32_t cv = (uint32_t)(((nb*2 + f_cs) ^ l8) << 4);
                uint32_t h0, h1, h2, h3, l0, l1, l2, l3;
                ldsm4t(h0, h1, h2, h3, sbase + A5_VH + vRow + cv);
                ldsm4t(l0, l1, l2, l3, sbase + A5_VL + vRow + cv);
                uint32_t bh0[2] = {h0, h1}, bh1[2] = {h2, h3};
                uint32_t bl0[2] = {l0, l1}, bl1[2] = {l2, l3};
                mma16(oacc[2*nb],   sh4[ks], bh0);
                mma16(oacc[2*nb],   sh4[ks], bl0);
                mma16(oacc[2*nb],   sl4[ks], bh0);
                mma16(oacc[2*nb+1], sh4[ks], bh1);
                mma16(oacc[2*nb+1], sh4[ks], bl1);
                mma16(oacc[2*nb+1], sl4[ks], bh1);
            }
        }
    }
#undef LOADKV

#pragma unroll
    for (int ni = 0; ni < 8; ni++) {
        int d0 = ni*8 + 2*t4;
        size_t i0 = ((size_t)(b*SEQ + r0g)*NH + h)*HD + d0;
        size_t i1 = ((size_t)(b*SEQ + r1g)*NH + h)*HD + d0;
        *(float2*)(og + i0) = make_float2(oacc[ni][0], oacc[ni][1]);
        *(float2*)(og + i1) = make_float2(oacc[ni][2], oacc[ni][3]);
    }
}

// ---------------- per-head groupnorm * silu(gate) -> hi/lo planes ----------------
__global__ void gn_gate_kernel(const float* __restrict__ at, const float* __restrict__ qkvg,
                               __half* __restrict__ ohi, __half* __restrict__ olo)
{
    int warp = threadIdx.x >> 5, lane = threadIdx.x & 31;
    int g = blockIdx.x * 8 + warp;
    int row = g >> 4, h = g & 15;
    size_t base = (size_t)g * 64;
    const float* gp = qkvg + (size_t)row*QKVG_N + 3*DM + h*64;
    float x0 = at[base + lane], x1 = at[base + 32 + lane];
    float s = x0 + x1, q = x0*x0 + x1*x1;
#pragma unroll
    for (int off = 16; off; off >>= 1) {
        s += __shfl_xor_sync(~0u, s, off);
        q += __shfl_xor_sync(~0u, q, off);
    }
    float mu = s * (1.f/64), var = q * (1.f/64) - mu*mu;
    float rs = rsqrtf(var + 1e-6f);
    float g0 = gp[lane], g1 = gp[32 + lane];
    g0 = g0 / (1.f + __expf(-g0));
    g1 = g1 / (1.f + __expf(-g1));
    float o0 = (x0 - mu) * rs * g0;
    float o1 = (x1 - mu) * rs * g1;
    __half h0 = __float2half_rn(o0), h1 = __float2half_rn(o1);
    ohi[base + lane]      = h0;
    olo[base + lane]      = __float2half_rn(o0 - __half2float(h0));
    ohi[base + 32 + lane] = h1;
    olo[base + 32 + lane] = __float2half_rn(o1 - __half2float(h1));
}

// ---------------- swiglu -> hi plane only (FFN-out is pure fp16) ----------------
__global__ void swiglu_kernel(const float* __restrict__ ab,
                              __half* __restrict__ ohi, __half* __restrict__ olo)
{
    size_t i = (size_t)blockIdx.x * 256 + threadIdx.x;
    int row = (int)(i / HIDP), col = (int)(i % HIDP);
    float r = 0.f;
    if (col < HID) {
        float a = ab[(size_t)row * NINP + col];
        float bb = ab[(size_t)row * NINP + HID + col];
        r = a * bb / (1.f + __expf(-bb));
    }
    ohi[i] = __float2half_rn(r);
}

// ---------------- launch ----------------
extern "C" void kernel_launch(void* const* d_in, const int* in_sizes, int n_in,
                              void* d_out, int out_size)
{
    const float* x     = (const float*)d_in[0];
    const float* ln1w  = (const float*)d_in[1];
    const float* ln1b  = (const float*)d_in[2];
    const float* wq    = (const float*)d_in[3];
    const float* wk    = (const float*)d_in[4];
    const float* wv    = (const float*)d_in[5];
    const float* wg    = (const float*)d_in[6];
    const float* wo    = (const float*)d_in[7];
    const float* ln2w  = (const float*)d_in[8];
    const float* ln2b  = (const float*)d_in[9];
    const float* w_in  = (const float*)d_in[10];
    const float* b_in  = (const float*)d_in[11];
    const float* w_out = (const float*)d_in[12];
    const float* b_out = (const float*)d_in[13];
    float* out = (float*)d_out;

    float *qkvg, *atraw, *x1, *ab;
    __half *xn_h, *xn_l, *xn2_h, *xn2_l, *at_h, *at_l, *hb_h, *hb_l;
    __half *wqk_h, *wqk_l, *wo_h, *wo_l, *win_h, *win_l, *wout_h, *wout_l;
    cudaGetSymbolAddress((void**)&qkvg,  g_qkvg);
    cudaGetSymbolAddress((void**)&atraw, g_atraw);
    cudaGetSymbolAddress((void**)&x1,    g_x1);
    cudaGetSymbolAddress((void**)&ab,    g_ab);
    cudaGetSymbolAddress((void**)&xn_h,  g_xn_h);   cudaGetSymbolAddress((void**)&xn_l,  g_xn_l);
    cudaGetSymbolAddress((void**)&xn2_h, g_xn2_h);  cudaGetSymbolAddress((void**)&xn2_l, g_xn2_l);
    cudaGetSymbolAddress((void**)&at_h,  g_at_h);   cudaGetSymbolAddress((void**)&at_l,  g_at_l);
    cudaGetSymbolAddress((void**)&hb_h,  g_hb_h);   cudaGetSymbolAddress((void**)&hb_l,  g_hb_l);
    cudaGetSymbolAddress((void**)&wqk_h, g_wqkvg_h); cudaGetSymbolAddress((void**)&wqk_l, g_wqkvg_l);
    cudaGetSymbolAddress((void**)&wo_h,  g_wo_h);   cudaGetSymbolAddress((void**)&wo_l,  g_wo_l);
    cudaGetSymbolAddress((void**)&win_h, g_win_h);  cudaGetSymbolAddress((void**)&win_l, g_win_l);
    cudaGetSymbolAddress((void**)&wout_h, g_wout_h); cudaGetSymbolAddress((void**)&wout_l, g_wout_l);

    cudaFuncSetAttribute(gemm_p, cudaFuncAttributeMaxDynamicSharedMemorySize, GP_SMEM);
    cudaFuncSetAttribute(attn5, cudaFuncAttributeMaxDynamicSharedMemorySize, ATT5_SMEM);

    // 1. merged weight transpose+split
    convw_all<<<13376, 256>>>(wq, wk, wv, wg, wo, w_in, w_out,
                              wqk_h, wqk_l, wo_h, wo_l, win_h, win_l, wout_h, wout_l);
    // 2. LN1 -> planes
    ln_kernel<<<ROWS, 256>>>(x, ln1w, ln1b, xn_h, xn_l);
    // 3. fused QKVG (2-mma: weight-lo kept, act-lo dropped)
    gemm_p<<<dim3(QKVG_N/128, ROWS/128), 256, GP_SMEM>>>(xn_h, xn_l, wqk_h, wqk_l,
        qkvg, QKVG_N, DM, QKVG_N, 1, nullptr, nullptr);
    // 4. retention attention (full 3-mma, register-S)
    attn5<<<dim3(SEQ/128, 2*NH), 256, ATT5_SMEM>>>(qkvg, atraw);
    // 5. groupnorm + silu gate -> planes
    gn_gate_kernel<<<ROWS*NH/8, 256>>>(atraw, qkvg, at_h, at_l);
    // 6. output projection + residual (2-mma)
    gemm_p<<<dim3(DM/128, ROWS/128), 256, GP_SMEM>>>(at_h, at_l, wo_h, wo_l,
        x1, DM, DM, DM, 1, nullptr, x);
    // 7. LN2 -> planes
    ln_kernel<<<ROWS, 256>>>(x1, ln2w, ln2b, xn2_h, xn2_l);
    // 8. FFN in (pure fp16 1-mma)
    gemm_p<<<dim3(NINP/128, ROWS/128), 256, GP_SMEM>>>(xn2_h, xn2_l, win_h, win_l,
        ab, NIN, DM, NINP, 0, b_in, nullptr);
    // 9. swiglu -> hi plane
    swiglu_kernel<<<(int)(((size_t)ROWS*HIDP)/256), 256>>>(ab, hb_h, hb_l);
    // 10. FFN out + bias + residual (pure fp16 1-mma)
    gemm_p<<<dim3(DM/128, ROWS/128), 256, GP_SMEM>>>(hb_h, hb_l, wout_h, wout_l,
        out, DM, HIDP, DM, 0, b_out, x1);
}

// round 10
// speedup vs baseline: 11.5357x; 1.4662x over previous
#include <cuda_runtime.h>
#include <cuda_fp16.h>
#include <cstdint>
#include <cstddef>

#define SEQ    2048
#define NH     16
#define DM     1024
#define HD     64
#define HID    2730
#define HIDP   2752
#define NIN    5460
#define NINP   5504
#define ROWS   4096
#define QKVG_N 4096

// ---------------- scratch (allocation-free device globals) ----------------
__device__ float  g_qkvg [(size_t)ROWS*QKVG_N];
__device__ float  g_atraw[ROWS*DM];
__device__ float  g_x1   [ROWS*DM];
__device__ float  g_ab   [(size_t)ROWS*NINP];
__device__ __half g_xn_h [ROWS*DM];
__device__ __half g_xn2_h[ROWS*DM];
__device__ __half g_at_h [ROWS*DM];
__device__ __half g_hb_h [(size_t)ROWS*HIDP];
__device__ __half g_wqkvg_h[(size_t)QKVG_N*DM];
__device__ __half g_wo_h   [DM*DM];
__device__ __half g_win_h  [(size_t)NINP*DM];
__device__ __half g_wout_h [(size_t)DM*HIDP];

// ---------------- helpers ----------------
__device__ __forceinline__ void mma16(float* c, const uint32_t* a, const uint32_t* b) {
    asm volatile("mma.sync.aligned.m16n8k16.row.col.f32.f16.f16.f32 "
                 "{%0,%1,%2,%3},{%4,%5,%6,%7},{%8,%9},{%0,%1,%2,%3};\n"
                 : "+f"(c[0]), "+f"(c[1]), "+f"(c[2]), "+f"(c[3])
                 : "r"(a[0]), "r"(a[1]), "r"(a[2]), "r"(a[3]), "r"(b[0]), "r"(b[1]));
}
__device__ __forceinline__ void cvt2(float x, float y, __half2& hi, __half2& lo) {
    __half hx = __float2half_rn(x), hy = __float2half_rn(y);
    __half lx = __float2half_rn(x - __half2float(hx));
    __half ly = __float2half_rn(y - __half2float(hy));
    hi = __halves2half2(hx, hy);
    lo = __halves2half2(lx, ly);
}
__device__ __forceinline__ uint32_t pack2(float x, float y) {
    __half2 h = __halves2half2(__float2half_rn(x), __float2half_rn(y));
    return *(uint32_t*)&h;
}
__device__ __forceinline__ uint32_t smem_u32(const void* p) {
    return (uint32_t)__cvta_generic_to_shared(p);
}
__device__ __forceinline__ void ldsm4(uint32_t& r0, uint32_t& r1, uint32_t& r2, uint32_t& r3,
                                      uint32_t addr) {
    asm volatile("ldmatrix.sync.aligned.m8n8.x4.shared.b16 {%0,%1,%2,%3},[%4];\n"
                 : "=r"(r0), "=r"(r1), "=r"(r2), "=r"(r3) : "r"(addr));
}
__device__ __forceinline__ void ldsm4t(uint32_t& r0, uint32_t& r1, uint32_t& r2, uint32_t& r3,
                                       uint32_t addr) {
    asm volatile("ldmatrix.sync.aligned.m8n8.x4.trans.shared.b16 {%0,%1,%2,%3},[%4];\n"
                 : "=r"(r0), "=r"(r1), "=r"(r2), "=r"(r3) : "r"(addr));
}
__device__ __forceinline__ void cpa16(uint32_t dst, const void* src) {
    asm volatile("cp.async.cg.shared.global [%0],[%1],16;\n" :: "r"(dst), "l"(src));
}

// ---------------- merged weight transpose + fp16 convert (hi only) ----------------
__global__ void convw_all(const float* __restrict__ wq, const float* __restrict__ wk,
                          const float* __restrict__ wv, const float* __restrict__ wg,
                          const float* __restrict__ wo, const float* __restrict__ w_in,
                          const float* __restrict__ w_out,
                          __half* __restrict__ wqk_h, __half* __restrict__ wo_h,
                          __half* __restrict__ win_h, __half* __restrict__ wout_h)
{
    __shared__ float t[32][33];
    int bt = blockIdx.x;
    const float* src; __half *hiT; int sK, sN, dK, n0, k0;
    if (bt < 4096) {
        int sub = bt >> 10, tt = bt & 1023;
        src = sub == 0 ? wq : sub == 1 ? wk : sub == 2 ? wv : wg;
        hiT = wqk_h + (size_t)sub*DM*DM;
        sK = DM; sN = DM; dK = DM; n0 = (tt & 31)*32; k0 = (tt >> 5)*32;
    } else if (bt < 5120) {
        int tt = bt - 4096;
        src = wo; hiT = wo_h;
        sK = DM; sN = DM; dK = DM; n0 = (tt & 31)*32; k0 = (tt >> 5)*32;
    } else if (bt < 10624) {
        int tt = bt - 5120;
        src = w_in; hiT = win_h;
        sK = DM; sN = NIN; dK = DM; n0 = (tt % 172)*32; k0 = (tt / 172)*32;
    } else {
        int tt = bt - 10624;
        src = w_out; hiT = wout_h;
        sK = HID; sN = DM; dK = HIDP; n0 = (tt & 31)*32; k0 = (tt >> 5)*32;
    }
    int tx = threadIdx.x & 31, ty = threadIdx.x >> 5;
#pragma unroll
    for (int i = 0; i < 4; i++) {
        int k = k0 + ty + 8*i;
        float v = (k < sK && (n0 + tx) < sN) ? src[(size_t)k * sN + n0 + tx] : 0.f;
        t[ty + 8*i][tx] = v;
    }
    __syncthreads();
#pragma unroll
    for (int i = 0; i < 4; i++) {
        int nl = ty + 8*i;
        hiT[(size_t)(n0 + nl) * dK + k0 + tx] = __float2half_rn(t[tx][nl]);
    }
}

// ---------------- LayerNorm -> fp16 (hi only) ----------------
__global__ void ln_kernel(const float* __restrict__ x, const float* __restrict__ w,
                          const float* __restrict__ b, __half* __restrict__ ohi)
{
    __shared__ float red[2][8];
    int row = blockIdx.x, tid = threadIdx.x;
    const float* xr = x + (size_t)row * DM;
    float v[4], s = 0.f, q = 0.f;
#pragma unroll
    for (int i = 0; i < 4; i++) { v[i] = xr[tid + 256*i]; s += v[i]; q += v[i]*v[i]; }
#pragma unroll
    for (int off = 16; off; off >>= 1) {
        s += __shfl_xor_sync(~0u, s, off);
        q += __shfl_xor_sync(~0u, q, off);
    }
    if ((tid & 31) == 0) { red[0][tid>>5] = s; red[1][tid>>5] = q; }
    __syncthreads();
    if (tid < 32) {
        s = (tid < 8) ? red[0][tid] : 0.f;
        q = (tid < 8) ? red[1][tid] : 0.f;
#pragma unroll
        for (int off = 4; off; off >>= 1) {
            s += __shfl_xor_sync(~0u, s, off);
            q += __shfl_xor_sync(~0u, q, off);
        }
        if (tid == 0) { red[0][0] = s; red[1][0] = q; }
    }
    __syncthreads();
    s = red[0][0]; q = red[1][0];
    float mu = s * (1.f/DM);
    float rs = rsqrtf(q * (1.f/DM) - mu*mu + 1e-5f);
#pragma unroll
    for (int i = 0; i < 4; i++) {
        int c = tid + 256*i;
        ohi[(size_t)row*DM + c] = __float2half_rn((v[i] - mu) * rs * w[c] + b[c]);
    }
}

// ---------------- pure-fp16 plane GEMM: C = A@B^T(+bias)(+add) ----------------
#define GP_SMEM 65536

__global__ __launch_bounds__(256, 2)
void gemm_p(const __half* __restrict__ Ahi, const __half* __restrict__ Bhi,
            float* __restrict__ C, int N, int K, int ldC,
            const float* __restrict__ bias, const float* __restrict__ add)
{
    extern __shared__ __half sh[];
    uint32_t sbase = smem_u32(sh);
    int tid = threadIdx.x, lane = tid & 31, wid = tid >> 5;
    int wm = wid >> 2, wn = wid & 3;
    int m0 = blockIdx.y * 128, n0 = blockIdx.x * 128;
    int KT = K >> 5;

    int cr = tid >> 2, cc = tid & 3;
    uint32_t dsto = (uint32_t)(cr*64 + ((cc ^ ((cr>>1)&3)) * 16));
    const __half* aS0 = Ahi + (size_t)(m0 + cr)*K + cc*8;
    const __half* bS0 = Bhi + (size_t)(n0 + cr)*K + cc*8;

#define ISSUE(st, kt) do {                                                   \
        uint32_t d_ = sbase + (st)*32768 + dsto;                             \
        int ko_ = (kt)*32;                                                   \
        cpa16(d_,               aS0 + ko_);                                  \
        cpa16(d_ + 4096,        aS0 + ko_ + (size_t)64*K);                   \
        cpa16(d_ + 16384,        bS0 + ko_);                                 \
        cpa16(d_ + 16384 + 4096, bS0 + ko_ + (size_t)64*K);                  \
        asm volatile("cp.async.commit_group;\n");                            \
    } while (0)

    int l8 = lane & 7, g = lane >> 3;
    int f_rl = (g & 1)*8 + l8;
    int f_cs = g >> 1;
    int f_swz = (f_rl >> 1) & 3;
    uint32_t ck[2] = { (uint32_t)(((0 + f_cs) ^ f_swz) * 16),
                       (uint32_t)(((2 + f_cs) ^ f_swz) * 16) };
    uint32_t aRow = (uint32_t)((wm*64 + f_rl) * 64);
    uint32_t bRow = (uint32_t)((wn*32 + f_rl) * 64);

    float acc[4][4][4] = {};

    ISSUE(0, 0);
    for (int kt = 0; kt < KT; kt++) {
        if (kt + 1 < KT) {
            ISSUE((kt + 1) & 1, kt + 1);
            asm volatile("cp.async.wait_group 1;\n");
        } else {
            asm volatile("cp.async.wait_group 0;\n");
        }
        __syncthreads();
        uint32_t sb = sbase + (kt & 1)*32768;
#pragma unroll
        for (int ks = 0; ks < 2; ks++) {
            uint32_t bh[4][2], af[4][4];
#pragma unroll
            for (int nt = 0; nt < 2; nt++) {
                uint32_t r0, r1, r2, r3;
                ldsm4(r0, r1, r2, r3, sb + 16384 + bRow + nt*1024 + ck[ks]);
                bh[2*nt][0] = r0; bh[2*nt+1][0] = r1; bh[2*nt][1] = r2; bh[2*nt+1][1] = r3;
            }
#pragma unroll
            for (int mi = 0; mi < 4; mi++)
                ldsm4(af[mi][0], af[mi][1], af[mi][2], af[mi][3],
                      sb + aRow + mi*1024 + ck[ks]);
#pragma unroll
            for (int mi = 0; mi < 4; mi++)
#pragma unroll
                for (int ni = 0; ni < 4; ni++)
                    mma16(acc[mi][ni], af[mi], bh[ni]);
        }
        __syncthreads();
    }
#undef ISSUE

#pragma unroll
    for (int mi = 0; mi < 4; mi++) {
        int r = m0 + wm*64 + mi*16 + (lane >> 2);
#pragma unroll
        for (int ni = 0; ni < 4; ni++) {
            int cn = n0 + wn*32 + ni*8 + 2*(lane & 3);
            if (cn >= N) continue;
            float b0v = bias ? bias[cn]   : 0.f;
            float b1v = bias ? bias[cn+1] : 0.f;
            float v0 = acc[mi][ni][0] + b0v;
            float v1 = acc[mi][ni][1] + b1v;
            float v2 = acc[mi][ni][2] + b0v;
            float v3 = acc[mi][ni][3] + b1v;
            if (add) {
                v0 += add[(size_t)r*ldC + cn];     v1 += add[(size_t)r*ldC + cn + 1];
                v2 += add[(size_t)(r+8)*ldC + cn]; v3 += add[(size_t)(r+8)*ldC + cn + 1];
            }
            *(float2*)(C + (size_t)r*ldC + cn)     = make_float2(v0, v1);
            *(float2*)(C + (size_t)(r+8)*ldC + cn) = make_float2(v2, v3);
        }
    }
}

// ---------------- retention attention v6: K/V-compensated, Q/S pure fp16 ----------------
#define A5_KH 0
#define A5_KL 8192
#define A5_VH 16384
#define A5_VL 24576
#define A5_CF 32768
#define ATT5_SMEM (32768 + 256)

__device__ __forceinline__ uint32_t aswz(int row, int bytecol) {
    return (uint32_t)(row*128 + ((((bytecol >> 4) ^ (row & 7)) << 4) | (bytecol & 15)));
}

__global__ __launch_bounds__(256)
void attn6(const float* __restrict__ qkvg, float* __restrict__ og)
{
    extern __shared__ char smc[];
    uint32_t sbase = smem_u32(smc);
    float* cf = (float*)(smc + A5_CF);
    int tid = threadIdx.x, lane = tid & 31, w = tid >> 5;
    int bh = blockIdx.y, b = bh >> 4, h = bh & 15;
    int s0 = ((blockIdx.x * 7) & 15) * 128;
    float lg = log2f(1.f - exp2f(-5.f - (float)h));
    const float* q = qkvg + h*HD;
    const float* k = qkvg + DM + h*HD;
    const float* v = qkvg + 2*DM + h*HD;

    int dist_max = (int)(40.0f / (-lg));
    int cc0 = s0 - 63 - dist_max;
    int t_start = (cc0 <= 0) ? 0 : ((cc0 + 63) & ~63);
    int t_end = s0 + 64;

    int gq = lane >> 2, t4 = lane & 3;
    int r0 = w*16 + gq;
    int r0g = s0 + r0, r1g = r0g + 8;
    float rowf0 = exp2f((float)r0g * lg);
    float rowf1 = exp2f((float)r1g * lg);

    // Q A-frags (hi only), scaled 1/8
    uint32_t qh[4][4];
    {
        const float* qr0 = q + (size_t)(b*SEQ + r0g)*QKVG_N;
        const float* qr1 = qr0 + 8*(size_t)QKVG_N;
#pragma unroll
        for (int kc = 0; kc < 4; kc++) {
            int col = kc*16 + 2*t4;
            float2 x0 = *(const float2*)(qr0 + col);
            float2 x1 = *(const float2*)(qr1 + col);
            float2 x2 = *(const float2*)(qr0 + col + 8);
            float2 x3 = *(const float2*)(qr1 + col + 8);
            qh[kc][0] = pack2(x0.x*0.125f, x0.y*0.125f);
            qh[kc][1] = pack2(x1.x*0.125f, x1.y*0.125f);
            qh[kc][2] = pack2(x2.x*0.125f, x2.y*0.125f);
            qh[kc][3] = pack2(x3.x*0.125f, x3.y*0.125f);
        }
    }

    float2 rK[8], rV[8];
#define LOADKV(t0_) do {                                                      \
        _Pragma("unroll")                                                     \
        for (int i_ = 0; i_ < 8; i_++) {                                      \
            int p_ = tid + 256*i_;                                            \
            int r_ = p_ >> 5, c2_ = (p_ & 31) * 2;                            \
            size_t base_ = (size_t)(b*SEQ + (t0_) + r_)*QKVG_N + c2_;         \
            rK[i_] = *(const float2*)(k + base_);                             \
            rV[i_] = *(const float2*)(v + base_);                             \
        }                                                                     \
    } while (0)

    LOADKV(t_start);

    int l8 = lane & 7;
    int f_rl = ((lane >> 3) & 1)*8 + l8;
    int f_cs = lane >> 4;

    float oacc[8][4] = {};
    for (int t0 = t_start; t0 <= t_end; t0 += 64) {
        __syncthreads();
#pragma unroll
        for (int i = 0; i < 8; i++) {
            int p = tid + 256*i;
            int r = p >> 5, bc = (p & 31) * 4;
            uint32_t o = aswz(r, bc);
            __half2 hi, lo;
            cvt2(rK[i].x, rK[i].y, hi, lo);
            *(__half2*)(smc + A5_KH + o) = hi;
            *(__half2*)(smc + A5_KL + o) = lo;
            cvt2(rV[i].x, rV[i].y, hi, lo);
            *(__half2*)(smc + A5_VH + o) = hi;
            *(__half2*)(smc + A5_VL + o) = lo;
        }
        if (tid < 64) cf[tid] = exp2f(-(float)(t0 + tid) * lg);
        if (t0 + 64 <= t_end) LOADKV(t0 + 64);
        __syncthreads();

        if (t0 > s0 + w*16 + 15) continue;

        // S = Q @ K^T : Q-hi * (K-hi + K-lo)
        float sacc[8][4] = {};
#pragma unroll
        for (int ks = 0; ks < 4; ks++) {
            uint32_t ca = (uint32_t)(((2*ks + f_cs) ^ l8) << 4);
#pragma unroll
            for (int nb = 0; nb < 4; nb++) {
                uint32_t kRow = (uint32_t)((nb*16 + f_rl) * 128);
                uint32_t h0, h1, h2, h3, l0, l1, l2, l3;
                ldsm4(h0, h1, h2, h3, sbase + A5_KH + kRow + ca);
                ldsm4(l0, l1, l2, l3, sbase + A5_KL + kRow + ca);
                uint32_t bh0[2] = {h0, h2}, bh1[2] = {h1, h3};
                uint32_t bl0[2] = {l0, l2}, bl1[2] = {l1, l3};
                mma16(sacc[2*nb],   qh[ks], bh0);
                mma16(sacc[2*nb],   qh[ks], bl0);
                mma16(sacc[2*nb+1], qh[ks], bh1);
                mma16(sacc[2*nb+1], qh[ks], bl1);
            }
        }

#pragma unroll
        for (int ni = 0; ni < 8; ni++) {
            int c0 = ni*8 + 2*t4;
            int c0g = t0 + c0, c1g = c0g + 1;
            float cf0 = cf[c0], cf1 = cf[c0 + 1];
            float w00 = (r0g >= c0g) ? rowf0*cf0 : 0.f;
            float w01 = (r0g >= c1g) ? rowf0*cf1 : 0.f;
            float w10 = (r1g >= c0g) ? rowf1*cf0 : 0.f;
            float w11 = (r1g >= c1g) ? rowf1*cf1 : 0.f;
            sacc[ni][0] *= w00; sacc[ni][1] *= w01;
            sacc[ni][2] *= w10; sacc[ni][3] *= w11;
        }

        // repack S (hi only) as A-frags
        uint32_t sh4[4][4];
#pragma unroll
        for (int t = 0; t < 4; t++) {
            sh4[t][0] = pack2(sacc[2*t][0],   sacc[2*t][1]);
            sh4[t][1] = pack2(sacc[2*t][2],   sacc[2*t][3]);
            sh4[t][2] = pack2(sacc[2*t+1][0], sacc[2*t+1][1]);
            sh4[t][3] = pack2(sacc[2*t+1][2], sacc[2*t+1][3]);
        }

        // O += S @ V : S-hi * (V-hi + V-lo)
#pragma unroll
        for (int ks = 0; ks < 4; ks++) {
            uint32_t vRow = (uint32_t)((ks*16 + f_rl) * 128);
#pragma unroll
            for (int nb = 0; nb < 4; nb++) {
                uint32_t cv = (uint32_t)(((nb*2 + f_cs) ^ l8) << 4);
                uint32_t h0, h1, h2, h3, l0, l1, l2, l3;
                ldsm4t(h0, h1, h2, h3, sbase + A5_VH + vRow + cv);
                ldsm4t(l0, l1, l2, l3, sbase + A5_VL + vRow + cv);
                uint32_t bh0[2] = {h0, h1}, bh1[2] = {h2, h3};
                uint32_t bl0[2] = {l0, l1}, bl1[2] = {l2, l3};
                mma16(oacc[2*nb],   sh4[ks], bh0);
                mma16(oacc[2*nb],   sh4[ks], bl0);
                mma16(oacc[2*nb+1], sh4[ks], bh1);
                mma16(oacc[2*nb+1], sh4[ks], bl1);
            }
        }
    }
#undef LOADKV

#pragma unroll
    for (int ni = 0; ni < 8; ni++) {
        int d0 = ni*8 + 2*t4;
        size_t i0 = ((size_t)(b*SEQ + r0g)*NH + h)*HD + d0;
        size_t i1 = ((size_t)(b*SEQ + r1g)*NH + h)*HD + d0;
        *(float2*)(og + i0) = make_float2(oacc[ni][0], oacc[ni][1]);
        *(float2*)(og + i1) = make_float2(oacc[ni][2], oacc[ni][3]);
    }
}

// ---------------- per-head groupnorm * silu(gate) -> fp16 (hi only) ----------------
__global__ void gn_gate_kernel(const float* __restrict__ at, const float* __restrict__ qkvg,
                               __half* __restrict__ ohi)
{
    int warp = threadIdx.x >> 5, lane = threadIdx.x & 31;
    int g = blockIdx.x * 8 + warp;
    int row = g >> 4, h = g & 15;
    size_t base = (size_t)g * 64;
    const float* gp = qkvg + (size_t)row*QKVG_N + 3*DM + h*64;
    float x0 = at[base + lane], x1 = at[base + 32 + lane];
    float s = x0 + x1, q = x0*x0 + x1*x1;
#pragma unroll
    for (int off = 16; off; off >>= 1) {
        s += __shfl_xor_sync(~0u, s, off);
        q += __shfl_xor_sync(~0u, q, off);
    }
    float mu = s * (1.f/64), var = q * (1.f/64) - mu*mu;
    float rs = rsqrtf(var + 1e-6f);
    float g0 = gp[lane], g1 = gp[32 + lane];
    g0 = g0 / (1.f + __expf(-g0));
    g1 = g1 / (1.f + __expf(-g1));
    ohi[base + lane]      = __float2half_rn((x0 - mu) * rs * g0);
    ohi[base + 32 + lane] = __float2half_rn((x1 - mu) * rs * g1);
}

// ---------------- swiglu -> fp16 (hi only, K-padded) ----------------
__global__ void swiglu_kernel(const float* __restrict__ ab, __half* __restrict__ ohi)
{
    size_t i = (size_t)blockIdx.x * 256 + threadIdx.x;
    int row = (int)(i / HIDP), col = (int)(i % HIDP);
    float r = 0.f;
    if (col < HID) {
        float a = ab[(size_t)row * NINP + col];
        float bb = ab[(size_t)row * NINP + HID + col];
        r = a * bb / (1.f + __expf(-bb));
    }
    ohi[i] = __float2half_rn(r);
}

// ---------------- launch ----------------
extern "C" void kernel_launch(void* const* d_in, const int* in_sizes, int n_in,
                              void* d_out, int out_size)
{
    const float* x     = (const float*)d_in[0];
    const float* ln1w  = (const float*)d_in[1];
    const float* ln1b  = (const float*)d_in[2];
    const float* wq    = (const float*)d_in[3];
    const float* wk    = (const float*)d_in[4];
    const float* wv    = (const float*)d_in[5];
    const float* wg    = (const float*)d_in[6];
    const float* wo    = (const float*)d_in[7];
    const float* ln2w  = (const float*)d_in[8];
    const float* ln2b  = (const float*)d_in[9];
    const float* w_in  = (const float*)d_in[10];
    const float* b_in  = (const float*)d_in[11];
    const float* w_out = (const float*)d_in[12];
    const float* b_out = (const float*)d_in[13];
    float* out = (float*)d_out;

    float *qkvg, *atraw, *x1, *ab;
    __half *xn_h, *xn2_h, *at_h, *hb_h, *wqk_h, *wo_h, *win_h, *wout_h;
    cudaGetSymbolAddress((void**)&qkvg,  g_qkvg);
    cudaGetSymbolAddress((void**)&atraw, g_atraw);
    cudaGetSymbolAddress((void**)&x1,    g_x1);
    cudaGetSymbolAddress((void**)&ab,    g_ab);
    cudaGetSymbolAddress((void**)&xn_h,  g_xn_h);
    cudaGetSymbolAddress((void**)&xn2_h, g_xn2_h);
    cudaGetSymbolAddress((void**)&at_h,  g_at_h);
    cudaGetSymbolAddress((void**)&hb_h,  g_hb_h);
    cudaGetSymbolAddress((void**)&wqk_h, g_wqkvg_h);
    cudaGetSymbolAddress((void**)&wo_h,  g_wo_h);
    cudaGetSymbolAddress((void**)&win_h, g_win_h);
    cudaGetSymbolAddress((void**)&wout_h, g_wout_h);

    cudaFuncSetAttribute(gemm_p, cudaFuncAttributeMaxDynamicSharedMemorySize, GP_SMEM);
    cudaFuncSetAttribute(attn6, cudaFuncAttributeMaxDynamicSharedMemorySize, ATT5_SMEM);

    // 1. merged weight transpose+convert (hi only)
    convw_all<<<13376, 256>>>(wq, wk, wv, wg, wo, w_in, w_out,
                              wqk_h, wo_h, win_h, wout_h);
    // 2. LN1 -> fp16
    ln_kernel<<<ROWS, 256>>>(x, ln1w, ln1b, xn_h);
    // 3. fused QKVG (pure fp16)
    gemm_p<<<dim3(QKVG_N/128, ROWS/128), 256, GP_SMEM>>>(xn_h, wqk_h,
        qkvg, QKVG_N, DM, QKVG_N, nullptr, nullptr);
    // 4. retention attention (K/V-compensated)
    attn6<<<dim3(SEQ/128, 2*NH), 256, ATT5_SMEM>>>(qkvg, atraw);
    // 5. groupnorm + silu gate -> fp16
    gn_gate_kernel<<<ROWS*NH/8, 256>>>(atraw, qkvg, at_h);
    // 6. output projection + residual (pure fp16)
    gemm_p<<<dim3(DM/128, ROWS/128), 256, GP_SMEM>>>(at_h, wo_h,
        x1, DM, DM, DM, nullptr, x);
    // 7. LN2 -> fp16
    ln_kernel<<<ROWS, 256>>>(x1, ln2w, ln2b, xn2_h);
    // 8. FFN in (pure fp16)
    gemm_p<<<dim3(NINP/128, ROWS/128), 256, GP_SMEM>>>(xn2_h, win_h,
        ab, NIN, DM, NINP, b_in, nullptr);
    // 9. swiglu -> fp16
    swiglu_kernel<<<(int)(((size_t)ROWS*HIDP)/256), 256>>>(ab, hb_h);
    // 10. FFN out + bias + residual (pure fp16)
    gemm_p<<<dim3(DM/128, ROWS/128), 256, GP_SMEM>>>(hb_h, wout_h,
        out, DM, HIDP, DM, b_out, x1);
}

// round 11
// speedup vs baseline: 11.7681x; 1.0201x over previous
#include <cuda_runtime.h>
#include <cuda_fp16.h>
#include <cstdint>
#include <cstddef>

#define SEQ    2048
#define NH     16
#define DM     1024
#define HD     64
#define HID    2730
#define HIDP   2752
#define NIN    5460
#define NINP   5504
#define ROWS   4096
#define QKVG_N 4096

// ---------------- scratch (allocation-free device globals) ----------------
__device__ float  g_atraw[ROWS*DM];
__device__ float  g_x1   [ROWS*DM];
__device__ float  g_ab   [(size_t)ROWS*NINP];
__device__ __half g_qkvg_h[(size_t)ROWS*QKVG_N];
__device__ __half g_qkvg_l[(size_t)ROWS*QKVG_N];
__device__ __half g_xn_h [ROWS*DM];
__device__ __half g_xn2_h[ROWS*DM];
__device__ __half g_at_h [ROWS*DM];
__device__ __half g_hb_h [(size_t)ROWS*HIDP];
__device__ __half g_wqkvg_h[(size_t)QKVG_N*DM];
__device__ __half g_wo_h   [DM*DM];
__device__ __half g_win_h  [(size_t)NINP*DM];
__device__ __half g_wout_h [(size_t)DM*HIDP];

// ---------------- helpers ----------------
__device__ __forceinline__ void mma16(float* c, const uint32_t* a, const uint32_t* b) {
    asm volatile("mma.sync.aligned.m16n8k16.row.col.f32.f16.f16.f32 "
                 "{%0,%1,%2,%3},{%4,%5,%6,%7},{%8,%9},{%0,%1,%2,%3};\n"
                 : "+f"(c[0]), "+f"(c[1]), "+f"(c[2]), "+f"(c[3])
                 : "r"(a[0]), "r"(a[1]), "r"(a[2]), "r"(a[3]), "r"(b[0]), "r"(b[1]));
}
__device__ __forceinline__ uint32_t pack2(float x, float y) {
    __half2 h = __halves2half2(__float2half_rn(x), __float2half_rn(y));
    return *(uint32_t*)&h;
}
__device__ __forceinline__ uint32_t smem_u32(const void* p) {
    return (uint32_t)__cvta_generic_to_shared(p);
}
__device__ __forceinline__ void ldsm4(uint32_t& r0, uint32_t& r1, uint32_t& r2, uint32_t& r3,
                                      uint32_t addr) {
    asm volatile("ldmatrix.sync.aligned.m8n8.x4.shared.b16 {%0,%1,%2,%3},[%4];\n"
                 : "=r"(r0), "=r"(r1), "=r"(r2), "=r"(r3) : "r"(addr));
}
__device__ __forceinline__ void ldsm4t(uint32_t& r0, uint32_t& r1, uint32_t& r2, uint32_t& r3,
                                       uint32_t addr) {
    asm volatile("ldmatrix.sync.aligned.m8n8.x4.trans.shared.b16 {%0,%1,%2,%3},[%4];\n"
                 : "=r"(r0), "=r"(r1), "=r"(r2), "=r"(r3) : "r"(addr));
}
__device__ __forceinline__ void cpa16(uint32_t dst, const void* src) {
    asm volatile("cp.async.cg.shared.global [%0],[%1],16;\n" :: "r"(dst), "l"(src));
}

// ---------------- merged weight transpose + fp16 convert (hi only) ----------------
__global__ void convw_all(const float* __restrict__ wq, const float* __restrict__ wk,
                          const float* __restrict__ wv, const float* __restrict__ wg,
                          const float* __restrict__ wo, const float* __restrict__ w_in,
                          const float* __restrict__ w_out,
                          __half* __restrict__ wqk_h, __half* __restrict__ wo_h,
                          __half* __restrict__ win_h, __half* __restrict__ wout_h)
{
    __shared__ float t[32][33];
    int bt = blockIdx.x;
    const float* src; __half *hiT; int sK, sN, dK, n0, k0;
    if (bt < 4096) {
        int sub = bt >> 10, tt = bt & 1023;
        src = sub == 0 ? wq : sub == 1 ? wk : sub == 2 ? wv : wg;
        hiT = wqk_h + (size_t)sub*DM*DM;
        sK = DM; sN = DM; dK = DM; n0 = (tt & 31)*32; k0 = (tt >> 5)*32;
    } else if (bt < 5120) {
        int tt = bt - 4096;
        src = wo; hiT = wo_h;
        sK = DM; sN = DM; dK = DM; n0 = (tt & 31)*32; k0 = (tt >> 5)*32;
    } else if (bt < 10624) {
        int tt = bt - 5120;
        src = w_in; hiT = win_h;
        sK = DM; sN = NIN; dK = DM; n0 = (tt % 172)*32; k0 = (tt / 172)*32;
    } else {
        int tt = bt - 10624;
        src = w_out; hiT = wout_h;
        sK = HID; sN = DM; dK = HIDP; n0 = (tt & 31)*32; k0 = (tt >> 5)*32;
    }
    int tx = threadIdx.x & 31, ty = threadIdx.x >> 5;
#pragma unroll
    for (int i = 0; i < 4; i++) {
        int k = k0 + ty + 8*i;
        float v = (k < sK && (n0 + tx) < sN) ? src[(size_t)k * sN + n0 + tx] : 0.f;
        t[ty + 8*i][tx] = v;
    }
    __syncthreads();
#pragma unroll
    for (int i = 0; i < 4; i++) {
        int nl = ty + 8*i;
        hiT[(size_t)(n0 + nl) * dK + k0 + tx] = __float2half_rn(t[tx][nl]);
    }
}

// ---------------- LayerNorm -> fp16 ----------------
__global__ void ln_kernel(const float* __restrict__ x, const float* __restrict__ w,
                          const float* __restrict__ b, __half* __restrict__ ohi)
{
    __shared__ float red[2][8];
    int row = blockIdx.x, tid = threadIdx.x;
    const float* xr = x + (size_t)row * DM;
    float v[4], s = 0.f, q = 0.f;
#pragma unroll
    for (int i = 0; i < 4; i++) { v[i] = xr[tid + 256*i]; s += v[i]; q += v[i]*v[i]; }
#pragma unroll
    for (int off = 16; off; off >>= 1) {
        s += __shfl_xor_sync(~0u, s, off);
        q += __shfl_xor_sync(~0u, q, off);
    }
    if ((tid & 31) == 0) { red[0][tid>>5] = s; red[1][tid>>5] = q; }
    __syncthreads();
    if (tid < 32) {
        s = (tid < 8) ? red[0][tid] : 0.f;
        q = (tid < 8) ? red[1][tid] : 0.f;
#pragma unroll
        for (int off = 4; off; off >>= 1) {
            s += __shfl_xor_sync(~0u, s, off);
            q += __shfl_xor_sync(~0u, q, off);
        }
        if (tid == 0) { red[0][0] = s; red[1][0] = q; }
    }
    __syncthreads();
    s = red[0][0]; q = red[1][0];
    float mu = s * (1.f/DM);
    float rs = rsqrtf(q * (1.f/DM) - mu*mu + 1e-5f);
#pragma unroll
    for (int i = 0; i < 4; i++) {
        int c = tid + 256*i;
        ohi[(size_t)row*DM + c] = __float2half_rn((v[i] - mu) * rs * w[c] + b[c]);
    }
}

// ---------------- shared GEMM mainloop (pure fp16) ----------------
#define GP_SMEM 65536

#define GEMM_MAIN(acc_)                                                          \
    int tid = threadIdx.x, lane = tid & 31, wid = tid >> 5;                      \
    int wm = wid >> 2, wn = wid & 3;                                             \
    int m0 = blockIdx.y * 128, n0 = blockIdx.x * 128;                            \
    int KT = K >> 5;                                                             \
    int cr = tid >> 2, cc = tid & 3;                                             \
    uint32_t dsto = (uint32_t)(cr*64 + ((cc ^ ((cr>>1)&3)) * 16));               \
    const __half* aS0 = Ahi + (size_t)(m0 + cr)*K + cc*8;                        \
    const __half* bS0 = Bhi + (size_t)(n0 + cr)*K + cc*8;                        \
    int l8 = lane & 7, g = lane >> 3;                                            \
    int f_rl = (g & 1)*8 + l8;                                                   \
    int f_cs = g >> 1;                                                           \
    int f_swz = (f_rl >> 1) & 3;                                                 \
    uint32_t ck[2] = { (uint32_t)(((0 + f_cs) ^ f_swz) * 16),                    \
                       (uint32_t)(((2 + f_cs) ^ f_swz) * 16) };                  \
    uint32_t aRow = (uint32_t)((wm*64 + f_rl) * 64);                             \
    uint32_t bRow = (uint32_t)((wn*32 + f_rl) * 64);                             \
    ISSUE(0, 0);                                                                 \
    for (int kt = 0; kt < KT; kt++) {                                            \
        if (kt + 1 < KT) {                                                       \
            ISSUE((kt + 1) & 1, kt + 1);                                         \
            asm volatile("cp.async.wait_group 1;\n");                            \
        } else {                                                                 \
            asm volatile("cp.async.wait_group 0;\n");                            \
        }                                                                        \
        __syncthreads();                                                         \
        uint32_t sb = sbase + (kt & 1)*32768;                                    \
        _Pragma("unroll")                                                        \
        for (int ks = 0; ks < 2; ks++) {                                         \
            uint32_t bh[4][2], af[4][4];                                         \
            _Pragma("unroll")                                                    \
            for (int nt = 0; nt < 2; nt++) {                                     \
                uint32_t r0, r1, r2, r3;                                         \
                ldsm4(r0, r1, r2, r3, sb + 16384 + bRow + nt*1024 + ck[ks]);     \
                bh[2*nt][0] = r0; bh[2*nt+1][0] = r1;                            \
                bh[2*nt][1] = r2; bh[2*nt+1][1] = r3;                            \
            }                                                                    \
            _Pragma("unroll")                                                    \
            for (int mi = 0; mi < 4; mi++)                                       \
                ldsm4(af[mi][0], af[mi][1], af[mi][2], af[mi][3],                \
                      sb + aRow + mi*1024 + ck[ks]);                             \
            _Pragma("unroll")                                                    \
            for (int mi = 0; mi < 4; mi++)                                       \
                _Pragma("unroll")                                                \
                for (int ni = 0; ni < 4; ni++)                                   \
                    mma16(acc_[mi][ni], af[mi], bh[ni]);                         \
        }                                                                        \
        __syncthreads();                                                         \
    }

#define ISSUE(st, kt) do {                                                   \
        uint32_t d_ = sbase + (st)*32768 + dsto;                             \
        int ko_ = (kt)*32;                                                   \
        cpa16(d_,               aS0 + ko_);                                  \
        cpa16(d_ + 4096,        aS0 + ko_ + (size_t)64*K);                   \
        cpa16(d_ + 16384,        bS0 + ko_);                                 \
        cpa16(d_ + 16384 + 4096, bS0 + ko_ + (size_t)64*K);                  \
        asm volatile("cp.async.commit_group;\n");                            \
    } while (0)

// generic fp32-out GEMM (+bias)(+add)
__global__ __launch_bounds__(256, 2)
void gemm_p(const __half* __restrict__ Ahi, const __half* __restrict__ Bhi,
            float* __restrict__ C, int N, int K, int ldC,
            const float* __restrict__ bias, const float* __restrict__ add)
{
    extern __shared__ __half sh[];
    uint32_t sbase = smem_u32(sh);
    float acc[4][4][4] = {};
    GEMM_MAIN(acc)
#pragma unroll
    for (int mi = 0; mi < 4; mi++) {
        int r = m0 + wm*64 + mi*16 + (lane >> 2);
#pragma unroll
        for (int ni = 0; ni < 4; ni++) {
            int cn = n0 + wn*32 + ni*8 + 2*(lane & 3);
            if (cn >= N) continue;
            float b0v = bias ? bias[cn]   : 0.f;
            float b1v = bias ? bias[cn+1] : 0.f;
            float v0 = acc[mi][ni][0] + b0v;
            float v1 = acc[mi][ni][1] + b1v;
            float v2 = acc[mi][ni][2] + b0v;
            float v3 = acc[mi][ni][3] + b1v;
            if (add) {
                v0 += add[(size_t)r*ldC + cn];     v1 += add[(size_t)r*ldC + cn + 1];
                v2 += add[(size_t)(r+8)*ldC + cn]; v3 += add[(size_t)(r+8)*ldC + cn + 1];
            }
            *(float2*)(C + (size_t)r*ldC + cn)     = make_float2(v0, v1);
            *(float2*)(C + (size_t)(r+8)*ldC + cn) = make_float2(v2, v3);
        }
    }
}

// QKVG GEMM: writes fp16 hi plane (all cols) + lo plane (K/V cols only)
__global__ __launch_bounds__(256, 2)
void gemm_q(const __half* __restrict__ Ahi, const __half* __restrict__ Bhi,
            __half* __restrict__ Chi, __half* __restrict__ Clo, int K)
{
    extern __shared__ __half sh[];
    uint32_t sbase = smem_u32(sh);
    float acc[4][4][4] = {};
    GEMM_MAIN(acc)
#pragma unroll
    for (int mi = 0; mi < 4; mi++) {
        int r = m0 + wm*64 + mi*16 + (lane >> 2);
#pragma unroll
        for (int ni = 0; ni < 4; ni++) {
            int cn = n0 + wn*32 + ni*8 + 2*(lane & 3);
            bool kv = (cn >= DM && cn < 3*DM);
#pragma unroll
            for (int hh = 0; hh < 2; hh++) {
                int rr = r + 8*hh;
                float x0 = acc[mi][ni][2*hh], x1 = acc[mi][ni][2*hh + 1];
                __half h0 = __float2half_rn(x0), h1 = __float2half_rn(x1);
                *(__half2*)(Chi + (size_t)rr*QKVG_N + cn) = __halves2half2(h0, h1);
                if (kv) {
                    __half l0 = __float2half_rn(x0 - __half2float(h0));
                    __half l1 = __float2half_rn(x1 - __half2float(h1));
                    *(__half2*)(Clo + (size_t)rr*QKVG_N + cn) = __halves2half2(l0, l1);
                }
            }
        }
    }
}
#undef ISSUE

// ---------------- retention attention v7: cp.async K/V planes, 2 CTAs/SM ----------------
// stage s at s*32768: KH 0 / KL 8192 / VH 16384 / VL 24576; cf[s] at 65536+s*256
#define ATT7_SMEM (65536 + 512)

__global__ __launch_bounds__(256, 2)
void attn7(const __half* __restrict__ ph, const __half* __restrict__ pl,
           float* __restrict__ og)
{
    extern __shared__ char smc[];
    uint32_t sbase = smem_u32(smc);
    float* cfp = (float*)(smc + 65536);
    int tid = threadIdx.x, lane = tid & 31, w = tid >> 5;
    int bh = blockIdx.y, b = bh >> 4, h = bh & 15;
    int s0 = ((blockIdx.x * 7) & 15) * 128;
    float lg = log2f(1.f - exp2f(-5.f - (float)h));

    int dist_max = (int)(40.0f / (-lg));
    int cc0 = s0 - 63 - dist_max;
    int t_start = (cc0 <= 0) ? 0 : ((cc0 + 63) & ~63);
    int t_end = s0 + 64;
    int nt = (t_end - t_start)/64 + 1;

    int gq = lane >> 2, t4 = lane & 3;
    int r0 = w*16 + gq;
    int r0g = s0 + r0, r1g = r0g + 8;
    float rowf0 = exp2f((float)r0g * lg);
    float rowf1 = exp2f((float)r1g * lg);

    // Q A-frags from hi plane, exact x0.125 scale
    uint32_t qh[4][4];
    {
        const __half* qr0 = ph + (size_t)(b*SEQ + r0g)*QKVG_N + h*HD;
        const __half* qr1 = qr0 + 8*(size_t)QKVG_N;
        __half2 sc = __half2half2(__float2half_rn(0.125f));
#pragma unroll
        for (int kc = 0; kc < 4; kc++) {
            int col = kc*16 + 2*t4;
            __half2 a0 = __hmul2(*(const __half2*)(qr0 + col), sc);
            __half2 a1 = __hmul2(*(const __half2*)(qr1 + col), sc);
            __half2 a2 = __hmul2(*(const __half2*)(qr0 + col + 8), sc);
            __half2 a3 = __hmul2(*(const __half2*)(qr1 + col + 8), sc);
            qh[kc][0] = *(uint32_t*)&a0;
            qh[kc][1] = *(uint32_t*)&a1;
            qh[kc][2] = *(uint32_t*)&a2;
            qh[kc][3] = *(uint32_t*)&a3;
        }
    }

    const __half* kh = ph + DM + h*HD;
    const __half* kl = pl + DM + h*HD;
    const __half* vh = ph + 2*DM + h*HD;
    const __half* vl = pl + 2*DM + h*HD;

#define FILL(st, t0_) do {                                                        \
        _Pragma("unroll")                                                         \
        for (int pp = 0; pp < 2; pp++) {                                          \
            int p_ = tid + 256*pp;                                                \
            int r_ = p_ >> 3, c_ = p_ & 7;                                        \
            uint32_t do_ = (uint32_t)((st)*32768 + r_*128 + ((c_ ^ (r_ & 7))<<4));\
            size_t src_ = (size_t)(b*SEQ + (t0_) + r_)*QKVG_N + c_*8;             \
            cpa16(sbase + do_,          kh + src_);                               \
            cpa16(sbase + 8192 + do_,   kl + src_);                               \
            cpa16(sbase + 16384 + do_,  vh + src_);                               \
            cpa16(sbase + 24576 + do_,  vl + src_);                               \
        }                                                                         \
        if (tid < 64) cfp[(st)*64 + tid] = exp2f(-(float)((t0_) + tid) * lg);     \
        asm volatile("cp.async.commit_group;\n");                                 \
    } while (0)

    FILL(0, t_start);
    if (nt > 1) FILL(1, t_start + 64);

    int l8 = lane & 7;
    int f_rl = ((lane >> 3) & 1)*8 + l8;
    int f_cs = lane >> 4;

    float oacc[8][4] = {};
    for (int it = 0; it < nt; it++) {
        int s = it & 1;
        int t0 = t_start + it*64;
        if (it + 1 < nt) asm volatile("cp.async.wait_group 1;\n");
        else             asm volatile("cp.async.wait_group 0;\n");
        __syncthreads();

        if (t0 <= s0 + w*16 + 15) {
            uint32_t stb = sbase + s*32768;
            const float* cf = cfp + s*64;

            // S = Q @ K^T : Q-hi * (K-hi + K-lo)
            float sacc[8][4] = {};
#pragma unroll
            for (int ks = 0; ks < 4; ks++) {
                uint32_t ca = (uint32_t)(((2*ks + f_cs) ^ l8) << 4);
#pragma unroll
                for (int nb = 0; nb < 4; nb++) {
                    uint32_t kRow = (uint32_t)((nb*16 + f_rl) * 128);
                    uint32_t h0, h1, h2, h3, l0, l1, l2, l3;
                    ldsm4(h0, h1, h2, h3, stb + kRow + ca);
                    ldsm4(l0, l1, l2, l3, stb + 8192 + kRow + ca);
                    uint32_t bh0[2] = {h0, h2}, bh1[2] = {h1, h3};
                    uint32_t bl0[2] = {l0, l2}, bl1[2] = {l1, l3};
                    mma16(sacc[2*nb],   qh[ks], bh0);
                    mma16(sacc[2*nb],   qh[ks], bl0);
                    mma16(sacc[2*nb+1], qh[ks], bh1);
                    mma16(sacc[2*nb+1], qh[ks], bl1);
                }
            }

            // decay * causal mask
#pragma unroll
            for (int ni = 0; ni < 8; ni++) {
                int c0 = ni*8 + 2*t4;
                int c0g = t0 + c0, c1g = c0g + 1;
                float cf0 = cf[c0], cf1 = cf[c0 + 1];
                float w00 = (r0g >= c0g) ? rowf0*cf0 : 0.f;
                float w01 = (r0g >= c1g) ? rowf0*cf1 : 0.f;
                float w10 = (r1g >= c0g) ? rowf1*cf0 : 0.f;
                float w11 = (r1g >= c1g) ? rowf1*cf1 : 0.f;
                sacc[ni][0] *= w00; sacc[ni][1] *= w01;
                sacc[ni][2] *= w10; sacc[ni][3] *= w11;
            }

            // repack S as A-frags (hi only)
            uint32_t sh4[4][4];
#pragma unroll
            for (int t = 0; t < 4; t++) {
                sh4[t][0] = pack2(sacc[2*t][0],   sacc[2*t][1]);
                sh4[t][1] = pack2(sacc[2*t][2],   sacc[2*t][3]);
                sh4[t][2] = pack2(sacc[2*t+1][0], sacc[2*t+1][1]);
                sh4[t][3] = pack2(sacc[2*t+1][2], sacc[2*t+1][3]);
            }

            // O += S @ V : S-hi * (V-hi + V-lo)
#pragma unroll
            for (int ks = 0; ks < 4; ks++) {
                uint32_t vRow = (uint32_t)((ks*16 + f_rl) * 128);
#pragma unroll
                for (int nb = 0; nb < 4; nb++) {
                    uint32_t cv = (uint32_t)(((nb*2 + f_cs) ^ l8) << 4);
                    uint32_t h0, h1, h2, h3, l0, l1, l2, l3;
                    ldsm4t(h0, h1, h2, h3, stb + 16384 + vRow + cv);
                    ldsm4t(l0, l1, l2, l3, stb + 24576 + vRow + cv);
                    uint32_t bh0[2] = {h0, h1}, bh1[2] = {h2, h3};
                    uint32_t bl0[2] = {l0, l1}, bl1[2] = {l2, l3};
                    mma16(oacc[2*nb],   sh4[ks], bh0);
                    mma16(oacc[2*nb],   sh4[ks], bl0);
                    mma16(oacc[2*nb+1], sh4[ks], bh1);
                    mma16(oacc[2*nb+1], sh4[ks], bl1);
                }
            }
        }
        __syncthreads();
        if (it + 2 < nt) FILL(s, t_start + (it + 2)*64);
    }
#undef FILL

#pragma unroll
    for (int ni = 0; ni < 8; ni++) {
        int d0 = ni*8 + 2*t4;
        size_t i0 = ((size_t)(b*SEQ + r0g)*NH + h)*HD + d0;
        size_t i1 = ((size_t)(b*SEQ + r1g)*NH + h)*HD + d0;
        *(float2*)(og + i0) = make_float2(oacc[ni][0], oacc[ni][1]);
        *(float2*)(og + i1) = make_float2(oacc[ni][2], oacc[ni][3]);
    }
}

// ---------------- groupnorm * silu(gate from hi plane) -> fp16 ----------------
__global__ void gn_gate_kernel(const float* __restrict__ at, const __half* __restrict__ ph,
                               __half* __restrict__ ohi)
{
    int warp = threadIdx.x >> 5, lane = threadIdx.x & 31;
    int g = blockIdx.x * 8 + warp;
    int row = g >> 4, h = g & 15;
    size_t base = (size_t)g * 64;
    const __half* gp = ph + (size_t)row*QKVG_N + 3*DM + h*64;
    float x0 = at[base + lane], x1 = at[base + 32 + lane];
    float s = x0 + x1, q = x0*x0 + x1*x1;
#pragma unroll
    for (int off = 16; off; off >>= 1) {
        s += __shfl_xor_sync(~0u, s, off);
        q += __shfl_xor_sync(~0u, q, off);
    }
    float mu = s * (1.f/64), var = q * (1.f/64) - mu*mu;
    float rs = rsqrtf(var + 1e-6f);
    float g0 = __half2float(gp[lane]), g1 = __half2float(gp[32 + lane]);
    g0 = g0 / (1.f + __expf(-g0));
    g1 = g1 / (1.f + __expf(-g1));
    ohi[base + lane]      = __float2half_rn((x0 - mu) * rs * g0);
    ohi[base + 32 + lane] = __float2half_rn((x1 - mu) * rs * g1);
}

// ---------------- swiglu -> fp16 (hi only, K-padded) ----------------
__global__ void swiglu_kernel(const float* __restrict__ ab, __half* __restrict__ ohi)
{
    size_t i = (size_t)blockIdx.x * 256 + threadIdx.x;
    int row = (int)(i / HIDP), col = (int)(i % HIDP);
    float r = 0.f;
    if (col < HID) {
        float a = ab[(size_t)row * NINP + col];
        float bb = ab[(size_t)row * NINP + HID + col];
        r = a * bb / (1.f + __expf(-bb));
    }
    ohi[i] = __float2half_rn(r);
}

// ---------------- launch ----------------
extern "C" void kernel_launch(void* const* d_in, const int* in_sizes, int n_in,
                              void* d_out, int out_size)
{
    const float* x     = (const float*)d_in[0];
    const float* ln1w  = (const float*)d_in[1];
    const float* ln1b  = (const float*)d_in[2];
    const float* wq    = (const float*)d_in[3];
    const float* wk    = (const float*)d_in[4];
    const float* wv    = (const float*)d_in[5];
    const float* wg    = (const float*)d_in[6];
    const float* wo    = (const float*)d_in[7];
    const float* ln2w  = (const float*)d_in[8];
    const float* ln2b  = (const float*)d_in[9];
    const float* w_in  = (const float*)d_in[10];
    const float* b_in  = (const float*)d_in[11];
    const float* w_out = (const float*)d_in[12];
    const float* b_out = (const float*)d_in[13];
    float* out = (float*)d_out;

    float *atraw, *x1, *ab;
    __half *qk_h, *qk_l, *xn_h, *xn2_h, *at_h, *hb_h, *wqk_h, *wo_h, *win_h, *wout_h;
    cudaGetSymbolAddress((void**)&atraw, g_atraw);
    cudaGetSymbolAddress((void**)&x1,    g_x1);
    cudaGetSymbolAddress((void**)&ab,    g_ab);
    cudaGetSymbolAddress((void**)&qk_h,  g_qkvg_h);
    cudaGetSymbolAddress((void**)&qk_l,  g_qkvg_l);
    cudaGetSymbolAddress((void**)&xn_h,  g_xn_h);
    cudaGetSymbolAddress((void**)&xn2_h, g_xn2_h);
    cudaGetSymbolAddress((void**)&at_h,  g_at_h);
    cudaGetSymbolAddress((void**)&hb_h,  g_hb_h);
    cudaGetSymbolAddress((void**)&wqk_h, g_wqkvg_h);
    cudaGetSymbolAddress((void**)&wo_h,  g_wo_h);
    cudaGetSymbolAddress((void**)&win_h, g_win_h);
    cudaGetSymbolAddress((void**)&wout_h, g_wout_h);

    cudaFuncSetAttribute(gemm_p, cudaFuncAttributeMaxDynamicSharedMemorySize, GP_SMEM);
    cudaFuncSetAttribute(gemm_q, cudaFuncAttributeMaxDynamicSharedMemorySize, GP_SMEM);
    cudaFuncSetAttribute(attn7, cudaFuncAttributeMaxDynamicSharedMemorySize, ATT7_SMEM);

    // 1. merged weight transpose+convert
    convw_all<<<13376, 256>>>(wq, wk, wv, wg, wo, w_in, w_out,
                              wqk_h, wo_h, win_h, wout_h);
    // 2. LN1 -> fp16
    ln_kernel<<<ROWS, 256>>>(x, ln1w, ln1b, xn_h);
    // 3. fused QKVG -> fp16 hi/lo planes
    gemm_q<<<dim3(QKVG_N/128, ROWS/128), 256, GP_SMEM>>>(xn_h, wqk_h, qk_h, qk_l, DM);
    // 4. retention attention (cp.async planes, 2 CTAs/SM)
    attn7<<<dim3(SEQ/128, 2*NH), 256, ATT7_SMEM>>>(qk_h, qk_l, atraw);
    // 5. groupnorm + silu gate -> fp16
    gn_gate_kernel<<<ROWS*NH/8, 256>>>(atraw, qk_h, at_h);
    // 6. output projection + residual
    gemm_p<<<dim3(DM/128, ROWS/128), 256, GP_SMEM>>>(at_h, wo_h,
        x1, DM, DM, DM, nullptr, x);
    // 7. LN2 -> fp16
    ln_kernel<<<ROWS, 256>>>(x1, ln2w, ln2b, xn2_h);
    // 8. FFN in
    gemm_p<<<dim3(NINP/128, ROWS/128), 256, GP_SMEM>>>(xn2_h, win_h,
        ab, NIN, DM, NINP, b_in, nullptr);
    // 9. swiglu -> fp16
    swiglu_kernel<<<(int)(((size_t)ROWS*HIDP)/256), 256>>>(ab, hb_h);
    // 10. FFN out + bias + residual
    gemm_p<<<dim3(DM/128, ROWS/128), 256, GP_SMEM>>>(hb_h, wout_h,
        out, DM, HIDP, DM, b_out, x1);
}

// round 12
// speedup vs baseline: 12.4827x; 1.0607x over previous
#include <cuda_runtime.h>
#include <cuda_fp16.h>
#include <cstdint>
#include <cstddef>

#define SEQ    2048
#define NH     16
#define DM     1024
#define HD     64
#define HID    2730
#define HIDP   2752
#define NIN    5460
#define NINP   5504
#define ROWS   4096
#define QKVG_N 4096

// ---------------- scratch (allocation-free device globals) ----------------
__device__ float  g_x1   [ROWS*DM];
__device__ __half g_qkvg_h[(size_t)ROWS*QKVG_N];
__device__ __half g_qkvg_l[(size_t)ROWS*QKVG_N];
__device__ __half g_xn_h [ROWS*DM];
__device__ __half g_xn2_h[ROWS*DM];
__device__ __half g_at_h [ROWS*DM];
__device__ __half g_hb_h [(size_t)ROWS*HIDP];
__device__ __half g_wqkvg_h[(size_t)QKVG_N*DM];
__device__ __half g_wo_h   [DM*DM];
__device__ __half g_win_h  [(size_t)NINP*DM];
__device__ __half g_wout_h [(size_t)DM*HIDP];

// ---------------- helpers ----------------
__device__ __forceinline__ void mma16(float* c, const uint32_t* a, const uint32_t* b) {
    asm volatile("mma.sync.aligned.m16n8k16.row.col.f32.f16.f16.f32 "
                 "{%0,%1,%2,%3},{%4,%5,%6,%7},{%8,%9},{%0,%1,%2,%3};\n"
                 : "+f"(c[0]), "+f"(c[1]), "+f"(c[2]), "+f"(c[3])
                 : "r"(a[0]), "r"(a[1]), "r"(a[2]), "r"(a[3]), "r"(b[0]), "r"(b[1]));
}
__device__ __forceinline__ uint32_t pack2(float x, float y) {
    __half2 h = __halves2half2(__float2half_rn(x), __float2half_rn(y));
    return *(uint32_t*)&h;
}
__device__ __forceinline__ uint32_t smem_u32(const void* p) {
    return (uint32_t)__cvta_generic_to_shared(p);
}
__device__ __forceinline__ void ldsm4(uint32_t& r0, uint32_t& r1, uint32_t& r2, uint32_t& r3,
                                      uint32_t addr) {
    asm volatile("ldmatrix.sync.aligned.m8n8.x4.shared.b16 {%0,%1,%2,%3},[%4];\n"
                 : "=r"(r0), "=r"(r1), "=r"(r2), "=r"(r3) : "r"(addr));
}
__device__ __forceinline__ void ldsm4t(uint32_t& r0, uint32_t& r1, uint32_t& r2, uint32_t& r3,
                                       uint32_t addr) {
    asm volatile("ldmatrix.sync.aligned.m8n8.x4.trans.shared.b16 {%0,%1,%2,%3},[%4];\n"
                 : "=r"(r0), "=r"(r1), "=r"(r2), "=r"(r3) : "r"(addr));
}
__device__ __forceinline__ void cpa16(uint32_t dst, const void* src) {
    asm volatile("cp.async.cg.shared.global [%0],[%1],16;\n" :: "r"(dst), "l"(src));
}

// ---------------- merged weight transpose + fp16 convert ----------------
// w_in: packed interleave — dest col 2j = src col j (a), 2j+1 = src col HID+j (b)
__global__ void convw_all(const float* __restrict__ wq, const float* __restrict__ wk,
                          const float* __restrict__ wv, const float* __restrict__ wg,
                          const float* __restrict__ wo, const float* __restrict__ w_in,
                          const float* __restrict__ w_out,
                          __half* __restrict__ wqk_h, __half* __restrict__ wo_h,
                          __half* __restrict__ win_h, __half* __restrict__ wout_h)
{
    __shared__ float t[32][33];
    int bt = blockIdx.x;
    const float* src; __half *hiT; int sK, sN, dK, n0, k0;
    bool packed = false;
    if (bt < 4096) {
        int sub = bt >> 10, tt = bt & 1023;
        src = sub == 0 ? wq : sub == 1 ? wk : sub == 2 ? wv : wg;
        hiT = wqk_h + (size_t)sub*DM*DM;
        sK = DM; sN = DM; dK = DM; n0 = (tt & 31)*32; k0 = (tt >> 5)*32;
    } else if (bt < 5120) {
        int tt = bt - 4096;
        src = wo; hiT = wo_h;
        sK = DM; sN = DM; dK = DM; n0 = (tt & 31)*32; k0 = (tt >> 5)*32;
    } else if (bt < 10624) {
        int tt = bt - 5120;
        src = w_in; hiT = win_h; packed = true;
        sK = DM; sN = NIN; dK = DM; n0 = (tt % 172)*32; k0 = (tt / 172)*32;
    } else {
        int tt = bt - 10624;
        src = w_out; hiT = wout_h;
        sK = HID; sN = DM; dK = HIDP; n0 = (tt & 31)*32; k0 = (tt >> 5)*32;
    }
    int tx = threadIdx.x & 31, ty = threadIdx.x >> 5;
    int p = n0 + tx;
    int scol = packed ? ((p & 1) ? HID + (p >> 1) : (p >> 1)) : p;
    bool cok = packed ? ((p >> 1) < HID) : (scol < sN);
#pragma unroll
    for (int i = 0; i < 4; i++) {
        int k = k0 + ty + 8*i;
        float v = (k < sK && cok) ? src[(size_t)k * sN + scol] : 0.f;
        t[ty + 8*i][tx] = v;
    }
    __syncthreads();
#pragma unroll
    for (int i = 0; i < 4; i++) {
        int nl = ty + 8*i;
        hiT[(size_t)(n0 + nl) * dK + k0 + tx] = __float2half_rn(t[tx][nl]);
    }
}

// ---------------- LayerNorm -> fp16 ----------------
__global__ void ln_kernel(const float* __restrict__ x, const float* __restrict__ w,
                          const float* __restrict__ b, __half* __restrict__ ohi)
{
    __shared__ float red[2][8];
    int row = blockIdx.x, tid = threadIdx.x;
    const float* xr = x + (size_t)row * DM;
    float v[4], s = 0.f, q = 0.f;
#pragma unroll
    for (int i = 0; i < 4; i++) { v[i] = xr[tid + 256*i]; s += v[i]; q += v[i]*v[i]; }
#pragma unroll
    for (int off = 16; off; off >>= 1) {
        s += __shfl_xor_sync(~0u, s, off);
        q += __shfl_xor_sync(~0u, q, off);
    }
    if ((tid & 31) == 0) { red[0][tid>>5] = s; red[1][tid>>5] = q; }
    __syncthreads();
    if (tid < 32) {
        s = (tid < 8) ? red[0][tid] : 0.f;
        q = (tid < 8) ? red[1][tid] : 0.f;
#pragma unroll
        for (int off = 4; off; off >>= 1) {
            s += __shfl_xor_sync(~0u, s, off);
            q += __shfl_xor_sync(~0u, q, off);
        }
        if (tid == 0) { red[0][0] = s; red[1][0] = q; }
    }
    __syncthreads();
    s = red[0][0]; q = red[1][0];
    float mu = s * (1.f/DM);
    float rs = rsqrtf(q * (1.f/DM) - mu*mu + 1e-5f);
#pragma unroll
    for (int i = 0; i < 4; i++) {
        int c = tid + 256*i;
        ohi[(size_t)row*DM + c] = __float2half_rn((v[i] - mu) * rs * w[c] + b[c]);
    }
}

// ---------------- shared GEMM mainloop (pure fp16) ----------------
#define GP_SMEM 65536

#define GEMM_MAIN(acc_)                                                          \
    int tid = threadIdx.x, lane = tid & 31, wid = tid >> 5;                      \
    int wm = wid >> 2, wn = wid & 3;                                             \
    int m0 = blockIdx.y * 128, n0 = blockIdx.x * 128;                            \
    int KT = K >> 5;                                                             \
    int cr = tid >> 2, cc = tid & 3;                                             \
    uint32_t dsto = (uint32_t)(cr*64 + ((cc ^ ((cr>>1)&3)) * 16));               \
    const __half* aS0 = Ahi + (size_t)(m0 + cr)*K + cc*8;                        \
    const __half* bS0 = Bhi + (size_t)(n0 + cr)*K + cc*8;                        \
    int l8 = lane & 7, g = lane >> 3;                                            \
    int f_rl = (g & 1)*8 + l8;                                                   \
    int f_cs = g >> 1;                                                           \
    int f_swz = (f_rl >> 1) & 3;                                                 \
    uint32_t ck[2] = { (uint32_t)(((0 + f_cs) ^ f_swz) * 16),                    \
                       (uint32_t)(((2 + f_cs) ^ f_swz) * 16) };                  \
    uint32_t aRow = (uint32_t)((wm*64 + f_rl) * 64);                             \
    uint32_t bRow = (uint32_t)((wn*32 + f_rl) * 64);                             \
    ISSUE(0, 0);                                                                 \
    for (int kt = 0; kt < KT; kt++) {                                            \
        if (kt + 1 < KT) {                                                       \
            ISSUE((kt + 1) & 1, kt + 1);                                         \
            asm volatile("cp.async.wait_group 1;\n");                            \
        } else {                                                                 \
            asm volatile("cp.async.wait_group 0;\n");                            \
        }                                                                        \
        __syncthreads();                                                         \
        uint32_t sb = sbase + (kt & 1)*32768;                                    \
        _Pragma("unroll")                                                        \
        for (int ks = 0; ks < 2; ks++) {                                         \
            uint32_t bh[4][2], af[4][4];                                         \
            _Pragma("unroll")                                                    \
            for (int nt = 0; nt < 2; nt++) {                                     \
                uint32_t r0, r1, r2, r3;                                         \
                ldsm4(r0, r1, r2, r3, sb + 16384 + bRow + nt*1024 + ck[ks]);     \
                bh[2*nt][0] = r0; bh[2*nt+1][0] = r1;                            \
                bh[2*nt][1] = r2; bh[2*nt+1][1] = r3;                            \
            }                                                                    \
            _Pragma("unroll")                                                    \
            for (int mi = 0; mi < 4; mi++)                                       \
                ldsm4(af[mi][0], af[mi][1], af[mi][2], af[mi][3],                \
                      sb + aRow + mi*1024 + ck[ks]);                             \
            _Pragma("unroll")                                                    \
            for (int mi = 0; mi < 4; mi++)                                       \
                _Pragma("unroll")                                                \
                for (int ni = 0; ni < 4; ni++)                                   \
                    mma16(acc_[mi][ni], af[mi], bh[ni]);                         \
        }                                                                        \
        __syncthreads();                                                         \
    }

#define ISSUE(st, kt) do {                                                   \
        uint32_t d_ = sbase + (st)*32768 + dsto;                             \
        int ko_ = (kt)*32;                                                   \
        cpa16(d_,               aS0 + ko_);                                  \
        cpa16(d_ + 4096,        aS0 + ko_ + (size_t)64*K);                   \
        cpa16(d_ + 16384,        bS0 + ko_);                                 \
        cpa16(d_ + 16384 + 4096, bS0 + ko_ + (size_t)64*K);                  \
        asm volatile("cp.async.commit_group;\n");                            \
    } while (0)

// generic fp32-out GEMM (+bias)(+add)
__global__ __launch_bounds__(256, 2)
void gemm_p(const __half* __restrict__ Ahi, const __half* __restrict__ Bhi,
            float* __restrict__ C, int N, int K, int ldC,
            const float* __restrict__ bias, const float* __restrict__ add)
{
    extern __shared__ __half sh[];
    uint32_t sbase = smem_u32(sh);
    float acc[4][4][4] = {};
    GEMM_MAIN(acc)
#pragma unroll
    for (int mi = 0; mi < 4; mi++) {
        int r = m0 + wm*64 + mi*16 + (lane >> 2);
#pragma unroll
        for (int ni = 0; ni < 4; ni++) {
            int cn = n0 + wn*32 + ni*8 + 2*(lane & 3);
            if (cn >= N) continue;
            float b0v = bias ? bias[cn]   : 0.f;
            float b1v = bias ? bias[cn+1] : 0.f;
            float v0 = acc[mi][ni][0] + b0v;
            float v1 = acc[mi][ni][1] + b1v;
            float v2 = acc[mi][ni][2] + b0v;
            float v3 = acc[mi][ni][3] + b1v;
            if (add) {
                v0 += add[(size_t)r*ldC + cn];     v1 += add[(size_t)r*ldC + cn + 1];
                v2 += add[(size_t)(r+8)*ldC + cn]; v3 += add[(size_t)(r+8)*ldC + cn + 1];
            }
            *(float2*)(C + (size_t)r*ldC + cn)     = make_float2(v0, v1);
            *(float2*)(C + (size_t)(r+8)*ldC + cn) = make_float2(v2, v3);
        }
    }
}

// QKVG GEMM: writes fp16 hi plane (all cols) + lo plane (K/V cols only)
__global__ __launch_bounds__(256, 2)
void gemm_q(const __half* __restrict__ Ahi, const __half* __restrict__ Bhi,
            __half* __restrict__ Chi, __half* __restrict__ Clo, int K)
{
    extern __shared__ __half sh[];
    uint32_t sbase = smem_u32(sh);
    float acc[4][4][4] = {};
    GEMM_MAIN(acc)
#pragma unroll
    for (int mi = 0; mi < 4; mi++) {
        int r = m0 + wm*64 + mi*16 + (lane >> 2);
#pragma unroll
        for (int ni = 0; ni < 4; ni++) {
            int cn = n0 + wn*32 + ni*8 + 2*(lane & 3);
            bool kv = (cn >= DM && cn < 3*DM);
#pragma unroll
            for (int hh = 0; hh < 2; hh++) {
                int rr = r + 8*hh;
                float x0 = acc[mi][ni][2*hh], x1 = acc[mi][ni][2*hh + 1];
                __half h0 = __float2half_rn(x0), h1 = __float2half_rn(x1);
                *(__half2*)(Chi + (size_t)rr*QKVG_N + cn) = __halves2half2(h0, h1);
                if (kv) {
                    __half l0 = __float2half_rn(x0 - __half2float(h0));
                    __half l1 = __float2half_rn(x1 - __half2float(h1));
                    *(__half2*)(Clo + (size_t)rr*QKVG_N + cn) = __halves2half2(l0, l1);
                }
            }
        }
    }
}

// FFN-in GEMM with fused swiglu: packed (a,b) pairs -> hb = a*silu(b), fp16
__global__ __launch_bounds__(256, 2)
void gemm_f(const __half* __restrict__ Ahi, const __half* __restrict__ Bhi,
            __half* __restrict__ Hb, int K, const float* __restrict__ biasIn)
{
    extern __shared__ __half sh[];
    uint32_t sbase = smem_u32(sh);
    float acc[4][4][4] = {};
    GEMM_MAIN(acc)
#pragma unroll
    for (int mi = 0; mi < 4; mi++) {
        int r = m0 + wm*64 + mi*16 + (lane >> 2);
#pragma unroll
        for (int ni = 0; ni < 4; ni++) {
            int cn = n0 + wn*32 + ni*8 + 2*(lane & 3);   // even
            int j = cn >> 1;
            bool ok = j < HID;
            float ba = ok ? biasIn[j]       : 0.f;
            float bb = ok ? biasIn[HID + j] : 0.f;
#pragma unroll
            for (int hh = 0; hh < 2; hh++) {
                int rr = r + 8*hh;
                float a  = acc[mi][ni][2*hh]     + ba;
                float bv = acc[mi][ni][2*hh + 1] + bb;
                float hv = ok ? a * bv / (1.f + __expf(-bv)) : 0.f;
                Hb[(size_t)rr*HIDP + j] = __float2half_rn(hv);
            }
        }
    }
}
#undef ISSUE

// ---------------- retention attention v8: fused groupnorm+gate epilogue ----------------
// stage s at s*32768: KH 0 / KL 8192 / VH 16384 / VL 24576; cf[s] at 65536+s*256
#define ATT8_SMEM (65536 + 512)

__global__ __launch_bounds__(256, 2)
void attn8(const __half* __restrict__ ph, const __half* __restrict__ pl,
           __half* __restrict__ at_h)
{
    extern __shared__ char smc[];
    uint32_t sbase = smem_u32(smc);
    float* cfp = (float*)(smc + 65536);
    int tid = threadIdx.x, lane = tid & 31, w = tid >> 5;
    int bh = blockIdx.y, b = bh >> 4, h = bh & 15;
    int s0 = ((blockIdx.x * 7) & 15) * 128;
    float lg = log2f(1.f - exp2f(-5.f - (float)h));

    int dist_max = (int)(40.0f / (-lg));
    int cc0 = s0 - 63 - dist_max;
    int t_start = (cc0 <= 0) ? 0 : ((cc0 + 63) & ~63);
    int t_end = s0 + 64;
    int nt = (t_end - t_start)/64 + 1;

    int gq = lane >> 2, t4 = lane & 3;
    int r0 = w*16 + gq;
    int r0g = s0 + r0, r1g = r0g + 8;
    float rowf0 = exp2f((float)r0g * lg);
    float rowf1 = exp2f((float)r1g * lg);

    // Q A-frags from hi plane, exact x0.125 scale
    uint32_t qh[4][4];
    {
        const __half* qr0 = ph + (size_t)(b*SEQ + r0g)*QKVG_N + h*HD;
        const __half* qr1 = qr0 + 8*(size_t)QKVG_N;
        __half2 sc = __half2half2(__float2half_rn(0.125f));
#pragma unroll
        for (int kc = 0; kc < 4; kc++) {
            int col = kc*16 + 2*t4;
            __half2 a0 = __hmul2(*(const __half2*)(qr0 + col), sc);
            __half2 a1 = __hmul2(*(const __half2*)(qr1 + col), sc);
            __half2 a2 = __hmul2(*(const __half2*)(qr0 + col + 8), sc);
            __half2 a3 = __hmul2(*(const __half2*)(qr1 + col + 8), sc);
            qh[kc][0] = *(uint32_t*)&a0;
            qh[kc][1] = *(uint32_t*)&a1;
            qh[kc][2] = *(uint32_t*)&a2;
            qh[kc][3] = *(uint32_t*)&a3;
        }
    }

    const __half* kh = ph + DM + h*HD;
    const __half* kl = pl + DM + h*HD;
    const __half* vh = ph + 2*DM + h*HD;
    const __half* vl = pl + 2*DM + h*HD;

#define FILL(st, t0_) do {                                                        \
        _Pragma("unroll")                                                         \
        for (int pp = 0; pp < 2; pp++) {                                          \
            int p_ = tid + 256*pp;                                                \
            int r_ = p_ >> 3, c_ = p_ & 7;                                        \
            uint32_t do_ = (uint32_t)((st)*32768 + r_*128 + ((c_ ^ (r_ & 7))<<4));\
            size_t src_ = (size_t)(b*SEQ + (t0_) + r_)*QKVG_N + c_*8;             \
            cpa16(sbase + do_,          kh + src_);                               \
            cpa16(sbase + 8192 + do_,   kl + src_);                               \
            cpa16(sbase + 16384 + do_,  vh + src_);                               \
            cpa16(sbase + 24576 + do_,  vl + src_);                               \
        }                                                                         \
        if (tid < 64) cfp[(st)*64 + tid] = exp2f(-(float)((t0_) + tid) * lg);     \
        asm volatile("cp.async.commit_group;\n");                                 \
    } while (0)

    FILL(0, t_start);
    if (nt > 1) FILL(1, t_start + 64);

    int l8 = lane & 7;
    int f_rl = ((lane >> 3) & 1)*8 + l8;
    int f_cs = lane >> 4;

    float oacc[8][4] = {};
    for (int it = 0; it < nt; it++) {
        int s = it & 1;
        int t0 = t_start + it*64;
        if (it + 1 < nt) asm volatile("cp.async.wait_group 1;\n");
        else             asm volatile("cp.async.wait_group 0;\n");
        __syncthreads();

        if (t0 <= s0 + w*16 + 15) {
            uint32_t stb = sbase + s*32768;
            const float* cf = cfp + s*64;

            // S = Q @ K^T : Q-hi * (K-hi + K-lo)
            float sacc[8][4] = {};
#pragma unroll
            for (int ks = 0; ks < 4; ks++) {
                uint32_t ca = (uint32_t)(((2*ks + f_cs) ^ l8) << 4);
#pragma unroll
                for (int nb = 0; nb < 4; nb++) {
                    uint32_t kRow = (uint32_t)((nb*16 + f_rl) * 128);
                    uint32_t h0, h1, h2, h3, l0, l1, l2, l3;
                    ldsm4(h0, h1, h2, h3, stb + kRow + ca);
                    ldsm4(l0, l1, l2, l3, stb + 8192 + kRow + ca);
                    uint32_t bh0[2] = {h0, h2}, bh1[2] = {h1, h3};
                    uint32_t bl0[2] = {l0, l2}, bl1[2] = {l1, l3};
                    mma16(sacc[2*nb],   qh[ks], bh0);
                    mma16(sacc[2*nb],   qh[ks], bl0);
                    mma16(sacc[2*nb+1], qh[ks], bh1);
                    mma16(sacc[2*nb+1], qh[ks], bl1);
                }
            }

            // decay * causal mask
#pragma unroll
            for (int ni = 0; ni < 8; ni++) {
                int c0 = ni*8 + 2*t4;
                int c0g = t0 + c0, c1g = c0g + 1;
                float cf0 = cf[c0], cf1 = cf[c0 + 1];
                float w00 = (r0g >= c0g) ? rowf0*cf0 : 0.f;
                float w01 = (r0g >= c1g) ? rowf0*cf1 : 0.f;
                float w10 = (r1g >= c0g) ? rowf1*cf0 : 0.f;
                float w11 = (r1g >= c1g) ? rowf1*cf1 : 0.f;
                sacc[ni][0] *= w00; sacc[ni][1] *= w01;
                sacc[ni][2] *= w10; sacc[ni][3] *= w11;
            }

            // repack S as A-frags (hi only)
            uint32_t sh4[4][4];
#pragma unroll
            for (int t = 0; t < 4; t++) {
                sh4[t][0] = pack2(sacc[2*t][0],   sacc[2*t][1]);
                sh4[t][1] = pack2(sacc[2*t][2],   sacc[2*t][3]);
                sh4[t][2] = pack2(sacc[2*t+1][0], sacc[2*t+1][1]);
                sh4[t][3] = pack2(sacc[2*t+1][2], sacc[2*t+1][3]);
            }

            // O += S @ V : S-hi * (V-hi + V-lo)
#pragma unroll
            for (int ks = 0; ks < 4; ks++) {
                uint32_t vRow = (uint32_t)((ks*16 + f_rl) * 128);
#pragma unroll
                for (int nb = 0; nb < 4; nb++) {
                    uint32_t cv = (uint32_t)(((nb*2 + f_cs) ^ l8) << 4);
                    uint32_t h0, h1, h2, h3, l0, l1, l2, l3;
                    ldsm4t(h0, h1, h2, h3, stb + 16384 + vRow + cv);
                    ldsm4t(l0, l1, l2, l3, stb + 24576 + vRow + cv);
                    uint32_t bh0[2] = {h0, h1}, bh1[2] = {h2, h3};
                    uint32_t bl0[2] = {l0, l1}, bl1[2] = {l2, l3};
                    mma16(oacc[2*nb],   sh4[ks], bh0);
                    mma16(oacc[2*nb],   sh4[ks], bl0);
                    mma16(oacc[2*nb+1], sh4[ks], bh1);
                    mma16(oacc[2*nb+1], sh4[ks], bl1);
                }
            }
        }
        __syncthreads();
        if (it + 2 < nt) FILL(s, t_start + (it + 2)*64);
    }
#undef FILL

    // ---- fused groupnorm (eps 1e-6) * silu(gate) -> at_h fp16 ----
    float sum0 = 0.f, sq0 = 0.f, sum1 = 0.f, sq1 = 0.f;
#pragma unroll
    for (int ni = 0; ni < 8; ni++) {
        sum0 += oacc[ni][0] + oacc[ni][1];
        sq0  += oacc[ni][0]*oacc[ni][0] + oacc[ni][1]*oacc[ni][1];
        sum1 += oacc[ni][2] + oacc[ni][3];
        sq1  += oacc[ni][2]*oacc[ni][2] + oacc[ni][3]*oacc[ni][3];
    }
#pragma unroll
    for (int off = 1; off < 4; off <<= 1) {
        sum0 += __shfl_xor_sync(~0u, sum0, off);
        sq0  += __shfl_xor_sync(~0u, sq0,  off);
        sum1 += __shfl_xor_sync(~0u, sum1, off);
        sq1  += __shfl_xor_sync(~0u, sq1,  off);
    }
    float mu0 = sum0 * (1.f/64), rs0 = rsqrtf(sq0 * (1.f/64) - mu0*mu0 + 1e-6f);
    float mu1 = sum1 * (1.f/64), rs1 = rsqrtf(sq1 * (1.f/64) - mu1*mu1 + 1e-6f);

    const __half* gp0 = ph + (size_t)(b*SEQ + r0g)*QKVG_N + 3*DM + h*HD;
    const __half* gp1 = gp0 + 8*(size_t)QKVG_N;
    __half* o0 = at_h + (size_t)(b*SEQ + r0g)*DM + h*HD;
    __half* o1 = at_h + (size_t)(b*SEQ + r1g)*DM + h*HD;
#pragma unroll
    for (int ni = 0; ni < 8; ni++) {
        int d0 = ni*8 + 2*t4;
        __half2 gg0 = *(const __half2*)(gp0 + d0);
        __half2 gg1 = *(const __half2*)(gp1 + d0);
        float ga = __low2float(gg0), gb = __high2float(gg0);
        float gc = __low2float(gg1), gd = __high2float(gg1);
        ga = ga / (1.f + __expf(-ga));
        gb = gb / (1.f + __expf(-gb));
        gc = gc / (1.f + __expf(-gc));
        gd = gd / (1.f + __expf(-gd));
        float v0 = (oacc[ni][0] - mu0) * rs0 * ga;
        float v1 = (oacc[ni][1] - mu0) * rs0 * gb;
        float v2 = (oacc[ni][2] - mu1) * rs1 * gc;
        float v3 = (oacc[ni][3] - mu1) * rs1 * gd;
        *(__half2*)(o0 + d0) = __halves2half2(__float2half_rn(v0), __float2half_rn(v1));
        *(__half2*)(o1 + d0) = __halves2half2(__float2half_rn(v2), __float2half_rn(v3));
    }
}

// ---------------- launch ----------------
extern "C" void kernel_launch(void* const* d_in, const int* in_sizes, int n_in,
                              void* d_out, int out_size)
{
    const float* x     = (const float*)d_in[0];
    const float* ln1w  = (const float*)d_in[1];
    const float* ln1b  = (const float*)d_in[2];
    const float* wq    = (const float*)d_in[3];
    const float* wk    = (const float*)d_in[4];
    const float* wv    = (const float*)d_in[5];
    const float* wg    = (const float*)d_in[6];
    const float* wo    = (const float*)d_in[7];
    const float* ln2w  = (const float*)d_in[8];
    const float* ln2b  = (const float*)d_in[9];
    const float* w_in  = (const float*)d_in[10];
    const float* b_in  = (const float*)d_in[11];
    const float* w_out = (const float*)d_in[12];
    const float* b_out = (const float*)d_in[13];
    float* out = (float*)d_out;

    float *x1;
    __half *qk_h, *qk_l, *xn_h, *xn2_h, *at_h, *hb_h, *wqk_h, *wo_h, *win_h, *wout_h;
    cudaGetSymbolAddress((void**)&x1,    g_x1);
    cudaGetSymbolAddress((void**)&qk_h,  g_qkvg_h);
    cudaGetSymbolAddress((void**)&qk_l,  g_qkvg_l);
    cudaGetSymbolAddress((void**)&xn_h,  g_xn_h);
    cudaGetSymbolAddress((void**)&xn2_h, g_xn2_h);
    cudaGetSymbolAddress((void**)&at_h,  g_at_h);
    cudaGetSymbolAddress((void**)&hb_h,  g_hb_h);
    cudaGetSymbolAddress((void**)&wqk_h, g_wqkvg_h);
    cudaGetSymbolAddress((void**)&wo_h,  g_wo_h);
    cudaGetSymbolAddress((void**)&win_h, g_win_h);
    cudaGetSymbolAddress((void**)&wout_h, g_wout_h);

    cudaFuncSetAttribute(gemm_p, cudaFuncAttributeMaxDynamicSharedMemorySize, GP_SMEM);
    cudaFuncSetAttribute(gemm_q, cudaFuncAttributeMaxDynamicSharedMemorySize, GP_SMEM);
    cudaFuncSetAttribute(gemm_f, cudaFuncAttributeMaxDynamicSharedMemorySize, GP_SMEM);
    cudaFuncSetAttribute(attn8, cudaFuncAttributeMaxDynamicSharedMemorySize, ATT8_SMEM);

    // 1. merged weight transpose+convert (w_in interleaved for fused swiglu)
    convw_all<<<13376, 256>>>(wq, wk, wv, wg, wo, w_in, w_out,
                              wqk_h, wo_h, win_h, wout_h);
    // 2. LN1 -> fp16
    ln_kernel<<<ROWS, 256>>>(x, ln1w, ln1b, xn_h);
    // 3. fused QKVG -> fp16 hi/lo planes
    gemm_q<<<dim3(QKVG_N/128, ROWS/128), 256, GP_SMEM>>>(xn_h, wqk_h, qk_h, qk_l, DM);
    // 4. retention attention + fused groupnorm/gate -> at_h fp16
    attn8<<<dim3(SEQ/128, 2*NH), 256, ATT8_SMEM>>>(qk_h, qk_l, at_h);
    // 5. output projection + residual
    gemm_p<<<dim3(DM/128, ROWS/128), 256, GP_SMEM>>>(at_h, wo_h,
        x1, DM, DM, DM, nullptr, x);
    // 6. LN2 -> fp16
    ln_kernel<<<ROWS, 256>>>(x1, ln2w, ln2b, xn2_h);
    // 7. FFN in + fused swiglu -> hb fp16
    gemm_f<<<dim3(NINP/128, ROWS/128), 256, GP_SMEM>>>(xn2_h, win_h, hb_h, DM, b_in);
    // 8. FFN out + bias + residual
    gemm_p<<<dim3(DM/128, ROWS/128), 256, GP_SMEM>>>(hb_h, wout_h,
        out, DM, HIDP, DM, b_out, x1);
}

// round 13
// speedup vs baseline: 14.6192x; 1.1711x over previous
#include <cuda_runtime.h>
#include <cuda_fp16.h>
#include <cstdint>
#include <cstddef>

#define SEQ    2048
#define NH     16
#define DM     1024
#define HD     64
#define HID    2730
#define HIDP   2752
#define NIN    5460
#define NINP   5504
#define ROWS   4096
#define QKVG_N 4096

// ---------------- scratch (allocation-free device globals) ----------------
__device__ float  g_x1   [ROWS*DM];
__device__ __half g_qkvg_h[(size_t)ROWS*QKVG_N];
__device__ __half g_xn_h [ROWS*DM];
__device__ __half g_xn2_h[ROWS*DM];
__device__ __half g_at_h [ROWS*DM];
__device__ __half g_hb_h [(size_t)ROWS*HIDP];
__device__ __half g_wqkvg_h[(size_t)QKVG_N*DM];
__device__ __half g_wo_h   [DM*DM];
__device__ __half g_win_h  [(size_t)NINP*DM];
__device__ __half g_wout_h [(size_t)DM*HIDP];

// ---------------- helpers ----------------
__device__ __forceinline__ void mma16(float* c, const uint32_t* a, const uint32_t* b) {
    asm volatile("mma.sync.aligned.m16n8k16.row.col.f32.f16.f16.f32 "
                 "{%0,%1,%2,%3},{%4,%5,%6,%7},{%8,%9},{%0,%1,%2,%3};\n"
                 : "+f"(c[0]), "+f"(c[1]), "+f"(c[2]), "+f"(c[3])
                 : "r"(a[0]), "r"(a[1]), "r"(a[2]), "r"(a[3]), "r"(b[0]), "r"(b[1]));
}
__device__ __forceinline__ uint32_t pack2(float x, float y) {
    __half2 h = __halves2half2(__float2half_rn(x), __float2half_rn(y));
    return *(uint32_t*)&h;
}
__device__ __forceinline__ uint32_t smem_u32(const void* p) {
    return (uint32_t)__cvta_generic_to_shared(p);
}
__device__ __forceinline__ void ldsm4(uint32_t& r0, uint32_t& r1, uint32_t& r2, uint32_t& r3,
                                      uint32_t addr) {
    asm volatile("ldmatrix.sync.aligned.m8n8.x4.shared.b16 {%0,%1,%2,%3},[%4];\n"
                 : "=r"(r0), "=r"(r1), "=r"(r2), "=r"(r3) : "r"(addr));
}
__device__ __forceinline__ void ldsm4t(uint32_t& r0, uint32_t& r1, uint32_t& r2, uint32_t& r3,
                                       uint32_t addr) {
    asm volatile("ldmatrix.sync.aligned.m8n8.x4.trans.shared.b16 {%0,%1,%2,%3},[%4];\n"
                 : "=r"(r0), "=r"(r1), "=r"(r2), "=r"(r3) : "r"(addr));
}
__device__ __forceinline__ void cpa16(uint32_t dst, const void* src) {
    asm volatile("cp.async.cg.shared.global [%0],[%1],16;\n" :: "r"(dst), "l"(src));
}

// ---------------- merged weight transpose + fp16 convert ----------------
// w_in: packed interleave — dest col 2j = src col j (a), 2j+1 = src col HID+j (b)
__global__ void convw_all(const float* __restrict__ wq, const float* __restrict__ wk,
                          const float* __restrict__ wv, const float* __restrict__ wg,
                          const float* __restrict__ wo, const float* __restrict__ w_in,
                          const float* __restrict__ w_out,
                          __half* __restrict__ wqk_h, __half* __restrict__ wo_h,
                          __half* __restrict__ win_h, __half* __restrict__ wout_h)
{
    __shared__ float t[32][33];
    int bt = blockIdx.x;
    const float* src; __half *hiT; int sK, sN, dK, n0, k0;
    bool packed = false;
    if (bt < 4096) {
        int sub = bt >> 10, tt = bt & 1023;
        src = sub == 0 ? wq : sub == 1 ? wk : sub == 2 ? wv : wg;
        hiT = wqk_h + (size_t)sub*DM*DM;
        sK = DM; sN = DM; dK = DM; n0 = (tt & 31)*32; k0 = (tt >> 5)*32;
    } else if (bt < 5120) {
        int tt = bt - 4096;
        src = wo; hiT = wo_h;
        sK = DM; sN = DM; dK = DM; n0 = (tt & 31)*32; k0 = (tt >> 5)*32;
    } else if (bt < 10624) {
        int tt = bt - 5120;
        src = w_in; hiT = win_h; packed = true;
        sK = DM; sN = NIN; dK = DM; n0 = (tt % 172)*32; k0 = (tt / 172)*32;
    } else {
        int tt = bt - 10624;
        src = w_out; hiT = wout_h;
        sK = HID; sN = DM; dK = HIDP; n0 = (tt & 31)*32; k0 = (tt >> 5)*32;
    }
    int tx = threadIdx.x & 31, ty = threadIdx.x >> 5;
    int p = n0 + tx;
    int scol = packed ? ((p & 1) ? HID + (p >> 1) : (p >> 1)) : p;
    bool cok = packed ? ((p >> 1) < HID) : (scol < sN);
#pragma unroll
    for (int i = 0; i < 4; i++) {
        int k = k0 + ty + 8*i;
        float v = (k < sK && cok) ? src[(size_t)k * sN + scol] : 0.f;
        t[ty + 8*i][tx] = v;
    }
    __syncthreads();
#pragma unroll
    for (int i = 0; i < 4; i++) {
        int nl = ty + 8*i;
        hiT[(size_t)(n0 + nl) * dK + k0 + tx] = __float2half_rn(t[tx][nl]);
    }
}

// ---------------- LayerNorm -> fp16 ----------------
__global__ void ln_kernel(const float* __restrict__ x, const float* __restrict__ w,
                          const float* __restrict__ b, __half* __restrict__ ohi)
{
    __shared__ float red[2][8];
    int row = blockIdx.x, tid = threadIdx.x;
    const float* xr = x + (size_t)row * DM;
    float v[4], s = 0.f, q = 0.f;
#pragma unroll
    for (int i = 0; i < 4; i++) { v[i] = xr[tid + 256*i]; s += v[i]; q += v[i]*v[i]; }
#pragma unroll
    for (int off = 16; off; off >>= 1) {
        s += __shfl_xor_sync(~0u, s, off);
        q += __shfl_xor_sync(~0u, q, off);
    }
    if ((tid & 31) == 0) { red[0][tid>>5] = s; red[1][tid>>5] = q; }
    __syncthreads();
    if (tid < 32) {
        s = (tid < 8) ? red[0][tid] : 0.f;
        q = (tid < 8) ? red[1][tid] : 0.f;
#pragma unroll
        for (int off = 4; off; off >>= 1) {
            s += __shfl_xor_sync(~0u, s, off);
            q += __shfl_xor_sync(~0u, q, off);
        }
        if (tid == 0) { red[0][0] = s; red[1][0] = q; }
    }
    __syncthreads();
    s = red[0][0]; q = red[1][0];
    float mu = s * (1.f/DM);
    float rs = rsqrtf(q * (1.f/DM) - mu*mu + 1e-5f);
#pragma unroll
    for (int i = 0; i < 4; i++) {
        int c = tid + 256*i;
        ohi[(size_t)row*DM + c] = __float2half_rn((v[i] - mu) * rs * w[c] + b[c]);
    }
}

// ---------------- shared GEMM mainloop: 4-stage (16KB each), 1 sync/iter ----------------
// stage st at st*16384: A [0,8192), B [8192,16384)
#define GP_SMEM 65536

#define ISSUE(st, kt) do {                                                   \
        uint32_t d_ = sbase + (st)*16384 + dsto;                             \
        int ko_ = (kt)*32;                                                   \
        cpa16(d_,               aS0 + ko_);                                  \
        cpa16(d_ + 4096,        aS0 + ko_ + (size_t)64*K);                   \
        cpa16(d_ + 8192,        bS0 + ko_);                                  \
        cpa16(d_ + 8192 + 4096, bS0 + ko_ + (size_t)64*K);                   \
        asm volatile("cp.async.commit_group;\n");                            \
    } while (0)

#define GEMM_MAIN(acc_)                                                          \
    int tid = threadIdx.x, lane = tid & 31, wid = tid >> 5;                      \
    int wm = wid >> 2, wn = wid & 3;                                             \
    int m0 = blockIdx.y * 128, n0 = blockIdx.x * 128;                            \
    int KT = K >> 5;                                                             \
    int cr = tid >> 2, cc = tid & 3;                                             \
    uint32_t dsto = (uint32_t)(cr*64 + ((cc ^ ((cr>>1)&3)) * 16));               \
    const __half* aS0 = Ahi + (size_t)(m0 + cr)*K + cc*8;                        \
    const __half* bS0 = Bhi + (size_t)(n0 + cr)*K + cc*8;                        \
    int l8 = lane & 7, g = lane >> 3;                                            \
    int f_rl = (g & 1)*8 + l8;                                                   \
    int f_cs = g >> 1;                                                           \
    int f_swz = (f_rl >> 1) & 3;                                                 \
    uint32_t ck[2] = { (uint32_t)(((0 + f_cs) ^ f_swz) * 16),                    \
                       (uint32_t)(((2 + f_cs) ^ f_swz) * 16) };                  \
    uint32_t aRow = (uint32_t)((wm*64 + f_rl) * 64);                             \
    uint32_t bRow = (uint32_t)((wn*32 + f_rl) * 64);                             \
    ISSUE(0, 0);                                                                 \
    ISSUE(1, 1);                                                                 \
    for (int kt = 0; kt < KT; kt++) {                                            \
        if (kt + 2 < KT) {                                                       \
            ISSUE((kt + 2) & 3, kt + 2);                                         \
            asm volatile("cp.async.wait_group 2;\n");                            \
        } else if (kt + 1 < KT) {                                                \
            asm volatile("cp.async.wait_group 1;\n");                            \
        } else {                                                                 \
            asm volatile("cp.async.wait_group 0;\n");                            \
        }                                                                        \
        __syncthreads();                                                         \
        uint32_t sb = sbase + (uint32_t)((kt & 3) * 16384);                      \
        _Pragma("unroll")                                                        \
        for (int ks = 0; ks < 2; ks++) {                                         \
            uint32_t bh[4][2], af[4][4];                                         \
            _Pragma("unroll")                                                    \
            for (int nt = 0; nt < 2; nt++) {                                     \
                uint32_t r0, r1, r2, r3;                                         \
                ldsm4(r0, r1, r2, r3, sb + 8192 + bRow + nt*1024 + ck[ks]);      \
                bh[2*nt][0] = r0; bh[2*nt+1][0] = r1;                            \
                bh[2*nt][1] = r2; bh[2*nt+1][1] = r3;                            \
            }                                                                    \
            _Pragma("unroll")                                                    \
            for (int mi = 0; mi < 4; mi++)                                       \
                ldsm4(af[mi][0], af[mi][1], af[mi][2], af[mi][3],                \
                      sb + aRow + mi*1024 + ck[ks]);                             \
            _Pragma("unroll")                                                    \
            for (int mi = 0; mi < 4; mi++)                                       \
                _Pragma("unroll")                                                \
                for (int ni = 0; ni < 4; ni++)                                   \
                    mma16(acc_[mi][ni], af[mi], bh[ni]);                         \
        }                                                                        \
    }

// generic fp32-out GEMM (+bias)(+add)
__global__ __launch_bounds__(256, 2)
void gemm_p(const __half* __restrict__ Ahi, const __half* __restrict__ Bhi,
            float* __restrict__ C, int N, int K, int ldC,
            const float* __restrict__ bias, const float* __restrict__ add)
{
    extern __shared__ __half sh[];
    uint32_t sbase = smem_u32(sh);
    float acc[4][4][4] = {};
    GEMM_MAIN(acc)
#pragma unroll
    for (int mi = 0; mi < 4; mi++) {
        int r = m0 + wm*64 + mi*16 + (lane >> 2);
#pragma unroll
        for (int ni = 0; ni < 4; ni++) {
            int cn = n0 + wn*32 + ni*8 + 2*(lane & 3);
            if (cn >= N) continue;
            float b0v = bias ? bias[cn]   : 0.f;
            float b1v = bias ? bias[cn+1] : 0.f;
            float v0 = acc[mi][ni][0] + b0v;
            float v1 = acc[mi][ni][1] + b1v;
            float v2 = acc[mi][ni][2] + b0v;
            float v3 = acc[mi][ni][3] + b1v;
            if (add) {
                v0 += add[(size_t)r*ldC + cn];     v1 += add[(size_t)r*ldC + cn + 1];
                v2 += add[(size_t)(r+8)*ldC + cn]; v3 += add[(size_t)(r+8)*ldC + cn + 1];
            }
            *(float2*)(C + (size_t)r*ldC + cn)     = make_float2(v0, v1);
            *(float2*)(C + (size_t)(r+8)*ldC + cn) = make_float2(v2, v3);
        }
    }
}

// QKVG GEMM: fp16 hi plane out
__global__ __launch_bounds__(256, 2)
void gemm_q(const __half* __restrict__ Ahi, const __half* __restrict__ Bhi,
            __half* __restrict__ Chi, int K)
{
    extern __shared__ __half sh[];
    uint32_t sbase = smem_u32(sh);
    float acc[4][4][4] = {};
    GEMM_MAIN(acc)
#pragma unroll
    for (int mi = 0; mi < 4; mi++) {
        int r = m0 + wm*64 + mi*16 + (lane >> 2);
#pragma unroll
        for (int ni = 0; ni < 4; ni++) {
            int cn = n0 + wn*32 + ni*8 + 2*(lane & 3);
#pragma unroll
            for (int hh = 0; hh < 2; hh++) {
                int rr = r + 8*hh;
                *(__half2*)(Chi + (size_t)rr*QKVG_N + cn) =
                    __halves2half2(__float2half_rn(acc[mi][ni][2*hh]),
                                   __float2half_rn(acc[mi][ni][2*hh + 1]));
            }
        }
    }
}

// FFN-in GEMM with fused swiglu: packed (a,b) pairs -> hb = a*silu(b), fp16
__global__ __launch_bounds__(256, 2)
void gemm_f(const __half* __restrict__ Ahi, const __half* __restrict__ Bhi,
            __half* __restrict__ Hb, int K, const float* __restrict__ biasIn)
{
    extern __shared__ __half sh[];
    uint32_t sbase = smem_u32(sh);
    float acc[4][4][4] = {};
    GEMM_MAIN(acc)
#pragma unroll
    for (int mi = 0; mi < 4; mi++) {
        int r = m0 + wm*64 + mi*16 + (lane >> 2);
#pragma unroll
        for (int ni = 0; ni < 4; ni++) {
            int cn = n0 + wn*32 + ni*8 + 2*(lane & 3);   // even
            int j = cn >> 1;
            bool ok = j < HID;
            float ba = ok ? biasIn[j]       : 0.f;
            float bb = ok ? biasIn[HID + j] : 0.f;
#pragma unroll
            for (int hh = 0; hh < 2; hh++) {
                int rr = r + 8*hh;
                float a  = acc[mi][ni][2*hh]     + ba;
                float bv = acc[mi][ni][2*hh + 1] + bb;
                float hv = ok ? a * bv / (1.f + __expf(-bv)) : 0.f;
                Hb[(size_t)rr*HIDP + j] = __float2half_rn(hv);
            }
        }
    }
}
#undef ISSUE

// ---------------- retention attention v9: pure fp16, 4-stage, fused gn+gate ----------------
// stage st at st*16384: KH [0,8192), VH [8192,16384); cf[st] at 65536 + st*256
#define ATT9_SMEM (65536 + 1024)

__global__ __launch_bounds__(256, 2)
void attn9(const __half* __restrict__ ph, __half* __restrict__ at_h)
{
    extern __shared__ char smc[];
    uint32_t sbase = smem_u32(smc);
    float* cfp = (float*)(smc + 65536);
    int tid = threadIdx.x, lane = tid & 31, w = tid >> 5;
    int bh = blockIdx.y, b = bh >> 4, h = bh & 15;
    int s0 = ((blockIdx.x * 7) & 15) * 128;
    float lg = log2f(1.f - exp2f(-5.f - (float)h));

    int dist_max = (int)(40.0f / (-lg));
    int cc0 = s0 - 63 - dist_max;
    int t_start = (cc0 <= 0) ? 0 : ((cc0 + 63) & ~63);
    int nt = (s0 + 64 - t_start)/64 + 1;

    int gq = lane >> 2, t4 = lane & 3;
    int r0 = w*16 + gq;
    int r0g = s0 + r0, r1g = r0g + 8;
    float rowf0 = exp2f((float)r0g * lg);
    float rowf1 = exp2f((float)r1g * lg);

    // Q A-frags from hi plane, exact x0.125 scale
    uint32_t qh[4][4];
    {
        const __half* qr0 = ph + (size_t)(b*SEQ + r0g)*QKVG_N + h*HD;
        const __half* qr1 = qr0 + 8*(size_t)QKVG_N;
        __half2 sc = __half2half2(__float2half_rn(0.125f));
#pragma unroll
        for (int kc = 0; kc < 4; kc++) {
            int col = kc*16 + 2*t4;
            __half2 a0 = __hmul2(*(const __half2*)(qr0 + col), sc);
            __half2 a1 = __hmul2(*(const __half2*)(qr1 + col), sc);
            __half2 a2 = __hmul2(*(const __half2*)(qr0 + col + 8), sc);
            __half2 a3 = __hmul2(*(const __half2*)(qr1 + col + 8), sc);
            qh[kc][0] = *(uint32_t*)&a0;
            qh[kc][1] = *(uint32_t*)&a1;
            qh[kc][2] = *(uint32_t*)&a2;
            qh[kc][3] = *(uint32_t*)&a3;
        }
    }

    const __half* kh = ph + DM + h*HD;
    const __half* vh = ph + 2*DM + h*HD;

#define FILL(st, t0_) do {                                                        \
        _Pragma("unroll")                                                         \
        for (int pp = 0; pp < 2; pp++) {                                          \
            int p_ = tid + 256*pp;                                                \
            int r_ = p_ >> 3, c_ = p_ & 7;                                        \
            uint32_t do_ = (uint32_t)((st)*16384 + r_*128 + ((c_ ^ (r_ & 7))<<4));\
            size_t src_ = (size_t)(b*SEQ + (t0_) + r_)*QKVG_N + c_*8;             \
            cpa16(sbase + do_,         kh + src_);                                \
            cpa16(sbase + 8192 + do_,  vh + src_);                                \
        }                                                                         \
        if (tid < 64) cfp[(st)*64 + tid] = exp2f(-(float)((t0_) + tid) * lg);     \
        asm volatile("cp.async.commit_group;\n");                                 \
    } while (0)

    FILL(0, t_start);
    if (nt > 1) FILL(1, t_start + 64);

    int l8 = lane & 7;
    int f_rl = ((lane >> 3) & 1)*8 + l8;
    int f_cs = lane >> 4;

    float oacc[8][4] = {};
    for (int it = 0; it < nt; it++) {
        int t0 = t_start + it*64;
        if (it + 2 < nt) {
            FILL((it + 2) & 3, t_start + (it + 2)*64);
            asm volatile("cp.async.wait_group 2;\n");
        } else if (it + 1 < nt) {
            asm volatile("cp.async.wait_group 1;\n");
        } else {
            asm volatile("cp.async.wait_group 0;\n");
        }
        __syncthreads();

        if (t0 <= s0 + w*16 + 15) {
            uint32_t stb = sbase + (uint32_t)((it & 3) * 16384);
            const float* cf = cfp + (it & 3)*64;

            // S = Q @ K^T (pure fp16)
            float sacc[8][4] = {};
#pragma unroll
            for (int ks = 0; ks < 4; ks++) {
                uint32_t ca = (uint32_t)(((2*ks + f_cs) ^ l8) << 4);
#pragma unroll
                for (int nb = 0; nb < 4; nb++) {
                    uint32_t kRow = (uint32_t)((nb*16 + f_rl) * 128);
                    uint32_t h0, h1, h2, h3;
                    ldsm4(h0, h1, h2, h3, stb + kRow + ca);
                    uint32_t bh0[2] = {h0, h2}, bh1[2] = {h1, h3};
                    mma16(sacc[2*nb],   qh[ks], bh0);
                    mma16(sacc[2*nb+1], qh[ks], bh1);
                }
            }

            // decay * causal mask
#pragma unroll
            for (int ni = 0; ni < 8; ni++) {
                int c0 = ni*8 + 2*t4;
                int c0g = t0 + c0, c1g = c0g + 1;
                float cf0 = cf[c0], cf1 = cf[c0 + 1];
                float w00 = (r0g >= c0g) ? rowf0*cf0 : 0.f;
                float w01 = (r0g >= c1g) ? rowf0*cf1 : 0.f;
                float w10 = (r1g >= c0g) ? rowf1*cf0 : 0.f;
                float w11 = (r1g >= c1g) ? rowf1*cf1 : 0.f;
                sacc[ni][0] *= w00; sacc[ni][1] *= w01;
                sacc[ni][2] *= w10; sacc[ni][3] *= w11;
            }

            // repack S as A-frags
            uint32_t sh4[4][4];
#pragma unroll
            for (int t = 0; t < 4; t++) {
                sh4[t][0] = pack2(sacc[2*t][0],   sacc[2*t][1]);
                sh4[t][1] = pack2(sacc[2*t][2],   sacc[2*t][3]);
                sh4[t][2] = pack2(sacc[2*t+1][0], sacc[2*t+1][1]);
                sh4[t][3] = pack2(sacc[2*t+1][2], sacc[2*t+1][3]);
            }

            // O += S @ V (pure fp16, trans B)
#pragma unroll
            for (int ks = 0; ks < 4; ks++) {
                uint32_t vRow = (uint32_t)((ks*16 + f_rl) * 128);
#pragma unroll
                for (int nb = 0; nb < 4; nb++) {
                    uint32_t cv = (uint32_t)(((nb*2 + f_cs) ^ l8) << 4);
                    uint32_t h0, h1, h2, h3;
                    ldsm4t(h0, h1, h2, h3, stb + 8192 + vRow + cv);
                    uint32_t bh0[2] = {h0, h1}, bh1[2] = {h2, h3};
                    mma16(oacc[2*nb],   sh4[ks], bh0);
                    mma16(oacc[2*nb+1], sh4[ks], bh1);
                }
            }
        }
    }
#undef FILL

    // ---- fused groupnorm (eps 1e-6) * silu(gate) -> at_h fp16 ----
    float sum0 = 0.f, sq0 = 0.f, sum1 = 0.f, sq1 = 0.f;
#pragma unroll
    for (int ni = 0; ni < 8; ni++) {
        sum0 += oacc[ni][0] + oacc[ni][1];
        sq0  += oacc[ni][0]*oacc[ni][0] + oacc[ni][1]*oacc[ni][1];
        sum1 += oacc[ni][2] + oacc[ni][3];
        sq1  += oacc[ni][2]*oacc[ni][2] + oacc[ni][3]*oacc[ni][3];
    }
#pragma unroll
    for (int off = 1; off < 4; off <<= 1) {
        sum0 += __shfl_xor_sync(~0u, sum0, off);
        sq0  += __shfl_xor_sync(~0u, sq0,  off);
        sum1 += __shfl_xor_sync(~0u, sum1, off);
        sq1  += __shfl_xor_sync(~0u, sq1,  off);
    }
    float mu0 = sum0 * (1.f/64), rs0 = rsqrtf(sq0 * (1.f/64) - mu0*mu0 + 1e-6f);
    float mu1 = sum1 * (1.f/64), rs1 = rsqrtf(sq1 * (1.f/64) - mu1*mu1 + 1e-6f);

    const __half* gp0 = ph + (size_t)(b*SEQ + r0g)*QKVG_N + 3*DM + h*HD;
    const __half* gp1 = gp0 + 8*(size_t)QKVG_N;
    __half* o0 = at_h + (size_t)(b*SEQ + r0g)*DM + h*HD;
    __half* o1 = at_h + (size_t)(b*SEQ + r1g)*DM + h*HD;
#pragma unroll
    for (int ni = 0; ni < 8; ni++) {
        int d0 = ni*8 + 2*t4;
        __half2 gg0 = *(const __half2*)(gp0 + d0);
        __half2 gg1 = *(const __half2*)(gp1 + d0);
        float ga = __low2float(gg0), gb = __high2float(gg0);
        float gc = __low2float(gg1), gd = __high2float(gg1);
        ga = ga / (1.f + __expf(-ga));
        gb = gb / (1.f + __expf(-gb));
        gc = gc / (1.f + __expf(-gc));
        gd = gd / (1.f + __expf(-gd));
        float v0 = (oacc[ni][0] - mu0) * rs0 * ga;
        float v1 = (oacc[ni][1] - mu0) * rs0 * gb;
        float v2 = (oacc[ni][2] - mu1) * rs1 * gc;
        float v3 = (oacc[ni][3] - mu1) * rs1 * gd;
        *(__half2*)(o0 + d0) = __halves2half2(__float2half_rn(v0), __float2half_rn(v1));
        *(__half2*)(o1 + d0) = __halves2half2(__float2half_rn(v2), __float2half_rn(v3));
    }
}

// ---------------- launch ----------------
extern "C" void kernel_launch(void* const* d_in, const int* in_sizes, int n_in,
                              void* d_out, int out_size)
{
    const float* x     = (const float*)d_in[0];
    const float* ln1w  = (const float*)d_in[1];
    const float* ln1b  = (const float*)d_in[2];
    const float* wq    = (const float*)d_in[3];
    const float* wk    = (const float*)d_in[4];
    const float* wv    = (const float*)d_in[5];
    const float* wg    = (const float*)d_in[6];
    const float* wo    = (const float*)d_in[7];
    const float* ln2w  = (const float*)d_in[8];
    const float* ln2b  = (const float*)d_in[9];
    const float* w_in  = (const float*)d_in[10];
    const float* b_in  = (const float*)d_in[11];
    const float* w_out = (const float*)d_in[12];
    const float* b_out = (const float*)d_in[13];
    float* out = (float*)d_out;

    float *x1;
    __half *qk_h, *xn_h, *xn2_h, *at_h, *hb_h, *wqk_h, *wo_h, *win_h, *wout_h;
    cudaGetSymbolAddress((void**)&x1,    g_x1);
    cudaGetSymbolAddress((void**)&qk_h,  g_qkvg_h);
    cudaGetSymbolAddress((void**)&xn_h,  g_xn_h);
    cudaGetSymbolAddress((void**)&xn2_h, g_xn2_h);
    cudaGetSymbolAddress((void**)&at_h,  g_at_h);
    cudaGetSymbolAddress((void**)&hb_h,  g_hb_h);
    cudaGetSymbolAddress((void**)&wqk_h, g_wqkvg_h);
    cudaGetSymbolAddress((void**)&wo_h,  g_wo_h);
    cudaGetSymbolAddress((void**)&win_h, g_win_h);
    cudaGetSymbolAddress((void**)&wout_h, g_wout_h);

    cudaFuncSetAttribute(gemm_p, cudaFuncAttributeMaxDynamicSharedMemorySize, GP_SMEM);
    cudaFuncSetAttribute(gemm_q, cudaFuncAttributeMaxDynamicSharedMemorySize, GP_SMEM);
    cudaFuncSetAttribute(gemm_f, cudaFuncAttributeMaxDynamicSharedMemorySize, GP_SMEM);
    cudaFuncSetAttribute(attn9, cudaFuncAttributeMaxDynamicSharedMemorySize, ATT9_SMEM);

    // 1. merged weight transpose+convert (w_in interleaved for fused swiglu)
    convw_all<<<13376, 256>>>(wq, wk, wv, wg, wo, w_in, w_out,
                              wqk_h, wo_h, win_h, wout_h);
    // 2. LN1 -> fp16
    ln_kernel<<<ROWS, 256>>>(x, ln1w, ln1b, xn_h);
    // 3. fused QKVG -> fp16 plane
    gemm_q<<<dim3(QKVG_N/128, ROWS/128), 256, GP_SMEM>>>(xn_h, wqk_h, qk_h, DM);
    // 4. retention attention + fused groupnorm/gate -> at_h fp16
    attn9<<<dim3(SEQ/128, 2*NH), 256, ATT9_SMEM>>>(qk_h, at_h);
    // 5. output projection + residual
    gemm_p<<<dim3(DM/128, ROWS/128), 256, GP_SMEM>>>(at_h, wo_h,
        x1, DM, DM, DM, nullptr, x);
    // 6. LN2 -> fp16
    ln_kernel<<<ROWS, 256>>>(x1, ln2w, ln2b, xn2_h);
    // 7. FFN in + fused swiglu -> hb fp16
    gemm_f<<<dim3(NINP/128, ROWS/128), 256, GP_SMEM>>>(xn2_h, win_h, hb_h, DM, b_in);
    // 8. FFN out + bias + residual
    gemm_p<<<dim3(DM/128, ROWS/128), 256, GP_SMEM>>>(hb_h, wout_h,
        out, DM, HIDP, DM, b_out, x1);
}